// round 1
// baseline (speedup 1.0000x reference)
#include <cuda_runtime.h>

#define Bb 2
#define Ss 1024
#define Dd 768
#define DV 32
#define NV 64
#define D3 256
#define BS (Bb*Ss)
#define EPSV 1e-8f
#define LNEPS 1e-5f
#define NORMED_ELEMS ((size_t)Bb*Ss*Dd)

// ---------------- scratch (static __device__, no allocation) ----------------
__device__ float g_Q[BS*DV];
__device__ float g_K[BS*DV];
__device__ float g_V[BS*Dd];
__device__ float g_A[BS*D3];
__device__ float g_Bm[BS*D3];
__device__ float g_R[BS*D3];
__device__ float g_emb2[NV*DV];
__device__ float g_gm[NV];
__device__ float g_ws [(size_t)BS*Ss];
__device__ float g_wap[(size_t)BS*Ss];
__device__ float g_wbd[(size_t)BS*Ss];
__device__ float g_wrs[(size_t)BS*Ss];
__device__ float g_invden[4*BS];
__device__ float g_comb[BS*Dd];
__device__ float g_res[BS*Dd];

// ---------------- generic C = X(MxK) @ W(NxK)^T ----------------
__global__ __launch_bounds__(256)
void gemm_xwt(const float* __restrict__ X, const float* __restrict__ W,
              float* __restrict__ C, int M, int N, int K)
{
    __shared__ float Xs[16][68];
    __shared__ float Wsm[16][68];
    int tid = threadIdx.x;
    int tm = tid / 16, tn = tid % 16;
    int m0 = blockIdx.y * 64, n0 = blockIdx.x * 64;
    float acc[4][4];
    #pragma unroll
    for (int a = 0; a < 4; a++)
        #pragma unroll
        for (int b = 0; b < 4; b++) acc[a][b] = 0.f;

    for (int k0 = 0; k0 < K; k0 += 16) {
        for (int t = tid; t < 1024; t += 256) {
            int mm = t >> 4, kk = t & 15;
            int gm_ = m0 + mm, gk = k0 + kk;
            Xs[kk][mm]  = (gm_ < M) ? X[(size_t)gm_ * K + gk] : 0.f;
            int gn = n0 + mm;
            Wsm[kk][mm] = (gn < N) ? W[(size_t)gn * K + gk] : 0.f;
        }
        __syncthreads();
        #pragma unroll
        for (int kk = 0; kk < 16; kk++) {
            float xf[4], wf[4];
            #pragma unroll
            for (int a = 0; a < 4; a++) xf[a] = Xs[kk][tm*4+a];
            #pragma unroll
            for (int b = 0; b < 4; b++) wf[b] = Wsm[kk][tn*4+b];
            #pragma unroll
            for (int a = 0; a < 4; a++)
                #pragma unroll
                for (int b = 0; b < 4; b++)
                    acc[a][b] = fmaf(xf[a], wf[b], acc[a][b]);
        }
        __syncthreads();
    }
    #pragma unroll
    for (int a = 0; a < 4; a++) {
        int m = m0 + tm*4 + a;
        if (m >= M) continue;
        #pragma unroll
        for (int b = 0; b < 4; b++) {
            int n = n0 + tn*4 + b;
            if (n < N) C[(size_t)m * N + n] = acc[a][b];
        }
    }
}

// ---------------- emb2 = (I + 0.1*adj)^T @ (vemb + 0.1*spec@Wspec^T) ----------------
__global__ void prep_emb_kernel(const float* __restrict__ vemb, const float* __restrict__ spec,
                                const float* __restrict__ Wspec, const float* __restrict__ adj)
{
    __shared__ float eb[NV*DV];
    int tid = threadIdx.x;
    for (int t = tid; t < NV*DV; t += 256) {
        int u = t / DV, d = t % DV;
        float s = vemb[t];
        #pragma unroll
        for (int h = 0; h < 6; h++) s += 0.1f * spec[u*6+h] * Wspec[d*6+h];
        eb[t] = s;
    }
    __syncthreads();
    for (int t = tid; t < NV*DV; t += 256) {
        int v = t / DV, d = t % DV;
        float s = eb[t];
        for (int u = 0; u < NV; u++) s += 0.1f * adj[u*NV + v] * eb[u*DV + d];
        g_emb2[t] = s;
    }
}

__global__ void gate_mean_kernel(const float* __restrict__ vg)
{
    int v = blockIdx.x;
    float s = 0.f;
    for (int c = threadIdx.x; c < Dd; c += 256) {
        float x = vg[(size_t)v*Dd + c];
        s += 1.f / (1.f + __expf(-x));
    }
    __shared__ float red[256];
    red[threadIdx.x] = s; __syncthreads();
    for (int off = 128; off; off >>= 1) {
        if (threadIdx.x < off) red[threadIdx.x] += red[threadIdx.x + off];
        __syncthreads();
    }
    if (threadIdx.x == 0) g_gm[v] = red[0] * (1.f / Dd);
}

// ---------------- main attention: per (b,i,j) pair, 64-vertex softmax ----------------
__global__ __launch_bounds__(256)
void attn_kernel(float* __restrict__ pi_out)
{
    int i = blockIdx.x, b = blockIdx.y;
    __shared__ float4 emb4[DV][16];   // [d][v/4]
    __shared__ float  gm_s[NV];
    __shared__ float  q_s[DV];
    int tid = threadIdx.x;
    for (int t = tid; t < DV*16; t += 256) {
        int d = t / 16, g = t % 16;
        emb4[d][g] = make_float4(g_emb2[(g*4+0)*DV + d], g_emb2[(g*4+1)*DV + d],
                                 g_emb2[(g*4+2)*DV + d], g_emb2[(g*4+3)*DV + d]);
    }
    if (tid < NV) gm_s[tid] = g_gm[tid];
    if (tid < DV) q_s[tid]  = g_Q[((size_t)b*Ss + i)*DV + tid];
    __syncthreads();

    for (int j = tid; j < Ss; j += 256) {
        size_t pair = (size_t)(b*Ss + i)*Ss + j;
        float4* po = (float4*)(pi_out + pair * NV);
        if (j > i) {
            float4 z = make_float4(0.f, 0.f, 0.f, 0.f);
            #pragma unroll
            for (int g = 0; g < 16; g++) po[g] = z;
            g_ws[pair] = 0.f; g_wap[pair] = 0.f; g_wbd[pair] = 0.f; g_wrs[pair] = 0.f;
            continue;
        }
        const float4* kr = (const float4*)(g_K + ((size_t)b*Ss + j)*DV);
        float p[DV];
        #pragma unroll
        for (int q4 = 0; q4 < 8; q4++) {
            float4 kv = kr[q4];
            p[q4*4+0] = q_s[q4*4+0] * kv.x;
            p[q4*4+1] = q_s[q4*4+1] * kv.y;
            p[q4*4+2] = q_s[q4*4+2] * kv.z;
            p[q4*4+3] = q_s[q4*4+3] * kv.w;
        }
        float acc[NV];
        #pragma unroll
        for (int v = 0; v < NV; v++) acc[v] = 0.f;
        #pragma unroll
        for (int d = 0; d < DV; d++) {
            float pd = p[d];
            #pragma unroll
            for (int g = 0; g < 16; g++) {
                float4 e = emb4[d][g];
                acc[g*4+0] = fmaf(pd, e.x, acc[g*4+0]);
                acc[g*4+1] = fmaf(pd, e.y, acc[g*4+1]);
                acc[g*4+2] = fmaf(pd, e.z, acc[g*4+2]);
                acc[g*4+3] = fmaf(pd, e.w, acc[g*4+3]);
            }
        }
        float mx = acc[0];
        #pragma unroll
        for (int v = 1; v < NV; v++) mx = fmaxf(mx, acc[v]);
        float sum = 0.f, sg = 0.f, sap = 0.f, sbd = 0.f, srs = 0.f;
        #pragma unroll
        for (int v = 0; v < NV; v++) {
            float e = __expf(acc[v] - mx);
            acc[v] = e;
            sum += e;
            sg = fmaf(e, gm_s[v], sg);
            if (v & 1) sap += e;
            if (v & 2) sbd += e;
            if (v & 4) srs += e;
        }
        float inv = 1.f / sum;
        #pragma unroll
        for (int g = 0; g < 16; g++)
            po[g] = make_float4(acc[g*4+0]*inv, acc[g*4+1]*inv,
                                acc[g*4+2]*inv, acc[g*4+3]*inv);
        g_ws[pair]  = sg  * inv;
        g_wap[pair] = sap * inv;
        g_wbd[pair] = sbd * inv;
        g_wrs[pair] = srs * inv;
    }
}

// ---------------- per-row denominators ----------------
__global__ void reduce_rows_kernel()
{
    int row = blockIdx.x;               // b*S + i
    size_t base = (size_t)row * Ss;
    int tid = threadIdx.x;
    float s0 = 0.f, s1 = 0.f, s2 = 0.f, s3 = 0.f;
    for (int j = tid; j < Ss; j += 256) {
        s0 += g_ws[base+j]; s1 += g_wap[base+j];
        s2 += g_wbd[base+j]; s3 += g_wrs[base+j];
    }
    __shared__ float r0[256], r1[256], r2[256], r3[256];
    r0[tid]=s0; r1[tid]=s1; r2[tid]=s2; r3[tid]=s3;
    __syncthreads();
    for (int off = 128; off; off >>= 1) {
        if (tid < off) { r0[tid]+=r0[tid+off]; r1[tid]+=r1[tid+off];
                         r2[tid]+=r2[tid+off]; r3[tid]+=r3[tid+off]; }
        __syncthreads();
    }
    if (tid == 0) {
        g_invden[row] = 1.f / (r0[0] + EPSV);
        float S1, d1, S2;
        S1 = r1[0]; d1 = S1 + EPSV; S2 = S1 / d1; g_invden[1*BS + row] = 1.f / (d1 * (S2 + EPSV));
        S1 = r2[0]; d1 = S1 + EPSV; S2 = S1 / d1; g_invden[2*BS + row] = 1.f / (d1 * (S2 + EPSV));
        S1 = r3[0]; d1 = S1 + EPSV; S2 = S1 / d1; g_invden[3*BS + row] = 1.f / (d1 * (S2 + EPSV));
    }
}

// ---------------- combined = w_s@V + modal(w_t@T) (causal-skipped K-loop) ----------------
__global__ __launch_bounds__(256)
void combine_kernel()
{
    int bz = blockIdx.z;
    int b = bz / 3, t = bz % 3;
    const float* Wt = (t == 0) ? g_wap : (t == 1) ? g_wbd : g_wrs;
    const float* Tm = (t == 0) ? g_A   : (t == 1) ? g_Bm  : g_R;
    int m0 = blockIdx.y * 64, n0 = blockIdx.x * 64;
    __shared__ float Ssm[16][68], Stm[16][68], Svm[16][68], Smm[16][68];
    int tid = threadIdx.x, tm = tid / 16, tn = tid % 16;
    float accs[4][4], acct[4][4];
    #pragma unroll
    for (int a = 0; a < 4; a++)
        #pragma unroll
        for (int c = 0; c < 4; c++) { accs[a][c] = 0.f; acct[a][c] = 0.f; }

    int kmax = m0 + 64;
    if (kmax > Ss) kmax = Ss;
    for (int k0 = 0; k0 < kmax; k0 += 16) {
        for (int tt = tid; tt < 1024; tt += 256) {
            int mm = tt >> 4, kk = tt & 15;
            size_t widx = (size_t)(b*Ss + m0 + mm)*Ss + k0 + kk;
            Ssm[kk][mm] = g_ws[widx];
            Stm[kk][mm] = Wt[widx];
        }
        for (int tt = tid; tt < 1024; tt += 256) {
            int kk = tt >> 6, nn = tt & 63;
            Svm[kk][nn] = g_V[(size_t)(b*Ss + k0 + kk)*Dd + t*D3 + n0 + nn];
            Smm[kk][nn] = Tm[(size_t)(b*Ss + k0 + kk)*D3 + n0 + nn];
        }
        __syncthreads();
        #pragma unroll
        for (int kk = 0; kk < 16; kk++) {
            float xs[4], xt[4], bv[4], bt[4];
            #pragma unroll
            for (int a = 0; a < 4; a++) { xs[a] = Ssm[kk][tm*4+a]; xt[a] = Stm[kk][tm*4+a]; }
            #pragma unroll
            for (int c = 0; c < 4; c++) { bv[c] = Svm[kk][tn*4+c]; bt[c] = Smm[kk][tn*4+c]; }
            #pragma unroll
            for (int a = 0; a < 4; a++)
                #pragma unroll
                for (int c = 0; c < 4; c++) {
                    accs[a][c] = fmaf(xs[a], bv[c], accs[a][c]);
                    acct[a][c] = fmaf(xt[a], bt[c], acct[a][c]);
                }
        }
        __syncthreads();
    }
    #pragma unroll
    for (int a = 0; a < 4; a++) {
        int m = m0 + tm*4 + a;
        float is = g_invden[b*Ss + m];
        float it = g_invden[(t+1)*BS + b*Ss + m];
        #pragma unroll
        for (int c = 0; c < 4; c++) {
            g_comb[(size_t)(b*Ss + m)*Dd + t*D3 + n0 + tn*4 + c]
                = is * accs[a][c] + it * acct[a][c];
        }
    }
}

// ---------------- result = comb@Wo^T + bo -> layernorm -> out ----------------
__global__ void ln_kernel(const float* __restrict__ bo, const float* __restrict__ gamma,
                          const float* __restrict__ beta, float* __restrict__ out)
{
    int row = blockIdx.x, tid = threadIdx.x;
    const float* r = g_res + (size_t)row * Dd;
    float v[3];
    float s = 0.f;
    #pragma unroll
    for (int q = 0; q < 3; q++) { int c = tid + q*256; v[q] = r[c] + bo[c]; s += v[q]; }
    __shared__ float red[256];
    __shared__ float mu_s, inv_s;
    red[tid] = s; __syncthreads();
    for (int off = 128; off; off >>= 1) {
        if (tid < off) red[tid] += red[tid + off];
        __syncthreads();
    }
    if (tid == 0) mu_s = red[0] * (1.f / Dd);
    __syncthreads();
    float mu = mu_s;
    float s2 = 0.f;
    #pragma unroll
    for (int q = 0; q < 3; q++) { float d = v[q] - mu; s2 += d*d; }
    __syncthreads();               // all done reading red[0] path (only tid0 read it)
    red[tid] = s2; __syncthreads();
    for (int off = 128; off; off >>= 1) {
        if (tid < off) red[tid] += red[tid + off];
        __syncthreads();
    }
    if (tid == 0) inv_s = rsqrtf(red[0] * (1.f / Dd) + LNEPS);
    __syncthreads();
    float inv = inv_s;
    #pragma unroll
    for (int q = 0; q < 3; q++) {
        int c = tid + q*256;
        out[(size_t)row*Dd + c] = (v[q] - mu) * inv * gamma[c] + beta[c];
    }
}

// ---------------- launch ----------------
extern "C" void kernel_launch(void* const* d_in, const int* in_sizes, int n_in,
                              void* d_out, int out_size)
{
    const float* x      = (const float*)d_in[0];
    const float* Wq     = (const float*)d_in[2];
    const float* Wk     = (const float*)d_in[3];
    const float* vemb   = (const float*)d_in[4];
    const float* vgates = (const float*)d_in[5];
    const float* Wv     = (const float*)d_in[6];
    const float* Wspec  = (const float*)d_in[7];
    const float* Wa     = (const float*)d_in[8];
    const float* Wb     = (const float*)d_in[9];
    const float* Wr     = (const float*)d_in[10];
    const float* Wo     = (const float*)d_in[11];
    const float* bo     = (const float*)d_in[12];
    const float* gamma  = (const float*)d_in[13];
    const float* beta   = (const float*)d_in[14];
    const float* adj    = (const float*)d_in[15];
    const float* spec   = (const float*)d_in[16];

    float* out    = (float*)d_out;
    float* pi_out = out + NORMED_ELEMS;

    float *pQ, *pK, *pV, *pA, *pB, *pR, *pComb, *pRes;
    cudaGetSymbolAddress((void**)&pQ,    g_Q);
    cudaGetSymbolAddress((void**)&pK,    g_K);
    cudaGetSymbolAddress((void**)&pV,    g_V);
    cudaGetSymbolAddress((void**)&pA,    g_A);
    cudaGetSymbolAddress((void**)&pB,    g_Bm);
    cudaGetSymbolAddress((void**)&pR,    g_R);
    cudaGetSymbolAddress((void**)&pComb, g_comb);
    cudaGetSymbolAddress((void**)&pRes,  g_res);

    dim3 thr(256);
    gemm_xwt<<<dim3( 1, 32), thr>>>(x, Wq, pQ, BS, DV, Dd);
    gemm_xwt<<<dim3( 1, 32), thr>>>(x, Wk, pK, BS, DV, Dd);
    gemm_xwt<<<dim3(12, 32), thr>>>(x, Wv, pV, BS, Dd, Dd);
    gemm_xwt<<<dim3( 4, 32), thr>>>(x, Wa, pA, BS, D3, Dd);
    gemm_xwt<<<dim3( 4, 32), thr>>>(x, Wb, pB, BS, D3, Dd);
    gemm_xwt<<<dim3( 4, 32), thr>>>(x, Wr, pR, BS, D3, Dd);
    prep_emb_kernel<<<1, 256>>>(vemb, spec, Wspec, adj);
    gate_mean_kernel<<<64, 256>>>(vgates);
    attn_kernel<<<dim3(Ss, Bb), 256>>>(pi_out);
    reduce_rows_kernel<<<BS, 256>>>();
    combine_kernel<<<dim3(4, 16, 6), 256>>>();
    gemm_xwt<<<dim3(12, 32), thr>>>(pComb, Wo, pRes, BS, Dd, Dd);
    ln_kernel<<<BS, 256>>>(bo, gamma, beta, out);
}

// round 2
// speedup vs baseline: 1.5116x; 1.5116x over previous
#include <cuda_runtime.h>

#define Bb 2
#define Ss 1024
#define Dd 768
#define DV 32
#define NV 64
#define D3 256
#define BS (Bb*Ss)
#define Kd 768
#define EPSV 1e-8f
#define LNEPS 1e-5f
#define NORMED_ELEMS ((size_t)Bb*Ss*Dd)

// ---------------- scratch ----------------
__device__ float g_QK[BS*64];            // cols 0-31 = Q, 32-63 = K
__device__ float g_V[BS*Dd];
__device__ float g_ABR[BS*Dd];           // cols 0-255 = A, 256-511 = B, 512-767 = R
__device__ float g_emb2[NV*DV];
__device__ float g_gm[NV];
__device__ float g_ws [(size_t)BS*Ss];
__device__ float g_wap[(size_t)BS*Ss];
__device__ float g_wbd[(size_t)BS*Ss];
__device__ float g_wrs[(size_t)BS*Ss];
__device__ float g_invden[4*BS];
__device__ float g_comb[BS*Dd];
__device__ float g_res[BS*Dd];

// ---------------- C = X(2048xK) @ Wsel(NxK)^T, 128x64 tiles, 8x4/thread ----------------
__global__ __launch_bounds__(256)
void gemm_big(const float* __restrict__ X,
              const float* __restrict__ W0, const float* __restrict__ W1,
              const float* __restrict__ W2, int s1, int s2,
              float* __restrict__ C, int N)
{
    __shared__ float Xs[8][132];
    __shared__ float Wsm[8][68];
    int tid = threadIdx.x;
    int m0 = blockIdx.y * 128, n0 = blockIdx.x * 64;
    int tm = tid >> 4, tn = tid & 15;

    float acc[8][4];
    #pragma unroll
    for (int a = 0; a < 8; a++)
        #pragma unroll
        for (int c = 0; c < 4; c++) acc[a][c] = 0.f;

    int xrow = tid >> 1, xk = (tid & 1) * 4;
    const float* xptr = X + (size_t)(m0 + xrow) * Kd + xk;

    const float* wptr = W0;
    int wk = 0;
    if (tid < 128) {
        int wrow = tid >> 1; wk = (tid & 1) * 4;
        int r = n0 + wrow;
        wptr = (r < s1) ? (W0 + (size_t)r * Kd)
             : (r < s2) ? (W1 + (size_t)(r - s1) * Kd)
                        : (W2 + (size_t)(r - s2) * Kd);
    }

    for (int k0 = 0; k0 < Kd; k0 += 8) {
        float4 xv = *(const float4*)(xptr + k0);
        float4 wv = make_float4(0.f,0.f,0.f,0.f);
        if (tid < 128) wv = *(const float4*)(wptr + k0 + wk);
        __syncthreads();
        Xs[xk+0][xrow] = xv.x; Xs[xk+1][xrow] = xv.y;
        Xs[xk+2][xrow] = xv.z; Xs[xk+3][xrow] = xv.w;
        if (tid < 128) {
            int wrow = tid >> 1;
            Wsm[wk+0][wrow] = wv.x; Wsm[wk+1][wrow] = wv.y;
            Wsm[wk+2][wrow] = wv.z; Wsm[wk+3][wrow] = wv.w;
        }
        __syncthreads();
        #pragma unroll
        for (int kk = 0; kk < 8; kk++) {
            float4 a0 = *(const float4*)&Xs[kk][tm*8];
            float4 a1 = *(const float4*)&Xs[kk][tm*8+4];
            float4 bv = *(const float4*)&Wsm[kk][tn*4];
            float xa[8] = {a0.x,a0.y,a0.z,a0.w,a1.x,a1.y,a1.z,a1.w};
            float bb[4] = {bv.x,bv.y,bv.z,bv.w};
            #pragma unroll
            for (int a = 0; a < 8; a++)
                #pragma unroll
                for (int c = 0; c < 4; c++)
                    acc[a][c] = fmaf(xa[a], bb[c], acc[a][c]);
        }
    }
    #pragma unroll
    for (int a = 0; a < 8; a++) {
        int m = m0 + tm*8 + a;
        float4 o = make_float4(acc[a][0], acc[a][1], acc[a][2], acc[a][3]);
        *(float4*)(C + (size_t)m * N + n0 + tn*4) = o;
    }
}

// ---------------- emb2 = (I + 0.1*adj)^T @ (vemb + 0.1*spec@Wspec^T) ----------------
__global__ void prep_emb_kernel(const float* __restrict__ vemb, const float* __restrict__ spec,
                                const float* __restrict__ Wspec, const float* __restrict__ adj)
{
    __shared__ float eb[NV*DV];
    int tid = threadIdx.x;
    for (int t = tid; t < NV*DV; t += 256) {
        int u = t / DV, d = t % DV;
        float s = vemb[t];
        #pragma unroll
        for (int h = 0; h < 6; h++) s += 0.1f * spec[u*6+h] * Wspec[d*6+h];
        eb[t] = s;
    }
    __syncthreads();
    for (int t = tid; t < NV*DV; t += 256) {
        int v = t / DV, d = t % DV;
        float s = eb[t];
        for (int u = 0; u < NV; u++) s += 0.1f * adj[u*NV + v] * eb[u*DV + d];
        g_emb2[t] = s;
    }
}

__global__ void gate_mean_kernel(const float* __restrict__ vg)
{
    int v = blockIdx.x;
    float s = 0.f;
    for (int c = threadIdx.x; c < Dd; c += 256) {
        float x = vg[(size_t)v*Dd + c];
        s += 1.f / (1.f + __expf(-x));
    }
    __shared__ float red[256];
    red[threadIdx.x] = s; __syncthreads();
    for (int off = 128; off; off >>= 1) {
        if (threadIdx.x < off) red[threadIdx.x] += red[threadIdx.x + off];
        __syncthreads();
    }
    if (threadIdx.x == 0) g_gm[v] = red[0] * (1.f / Dd);
}

// ---------------- attention: per (b,i,j-tile256); S = K @ F^T, F=q*emb2 ----------------
__global__ __launch_bounds__(256)
void attn_kernel(float* __restrict__ pi_out)
{
    int j0 = blockIdx.x * 256, i = blockIdx.y, b = blockIdx.z;
    size_t rowbase = (size_t)(b*Ss + i) * Ss;
    int tid = threadIdx.x;

    if (j0 > i) {
        float4 z = make_float4(0.f,0.f,0.f,0.f);
        float4* base = (float4*)(pi_out + (rowbase + j0) * NV);
        for (int t = tid; t < 4096; t += 256) base[t] = z;
        size_t p = rowbase + j0 + tid;
        g_ws[p] = 0.f; g_wap[p] = 0.f; g_wbd[p] = 0.f; g_wrs[p] = 0.f;
        return;
    }

    __shared__ float F[DV][NV];       // F[d][v] = q[d]*emb2[v][d]
    __shared__ float Ksm[256][33];
    __shared__ float q_s[DV];
    __shared__ float gm_s[NV];

    if (tid < DV) q_s[tid] = g_QK[(size_t)(b*Ss + i)*64 + tid];
    if (tid < NV) gm_s[tid] = g_gm[tid];
    __syncthreads();
    for (int t = tid; t < NV*DV; t += 256) {
        int v = t >> 5, d = t & 31;
        F[d][v] = q_s[d] * g_emb2[v*DV + d];
    }
    for (int t = tid; t < 2048; t += 256) {
        int r = t >> 3, q = t & 7;
        float4 kv = *(const float4*)(g_QK + (size_t)(b*Ss + j0 + r)*64 + 32 + q*4);
        Ksm[r][q*4+0] = kv.x; Ksm[r][q*4+1] = kv.y;
        Ksm[r][q*4+2] = kv.z; Ksm[r][q*4+3] = kv.w;
    }
    __syncthreads();

    int tn = tid & 3, tj = tid >> 2;          // tn: v-group (16v), tj: j-group (4j)
    float acc[4][16];
    #pragma unroll
    for (int jj = 0; jj < 4; jj++)
        #pragma unroll
        for (int q = 0; q < 16; q++) acc[jj][q] = 0.f;

    #pragma unroll 8
    for (int d = 0; d < DV; d++) {
        float kv[4];
        #pragma unroll
        for (int jj = 0; jj < 4; jj++) kv[jj] = Ksm[tj*4 + jj][d];
        float4 f0 = *(const float4*)&F[d][tn*16];
        float4 f1 = *(const float4*)&F[d][tn*16+4];
        float4 f2 = *(const float4*)&F[d][tn*16+8];
        float4 f3 = *(const float4*)&F[d][tn*16+12];
        float ff[16] = {f0.x,f0.y,f0.z,f0.w, f1.x,f1.y,f1.z,f1.w,
                        f2.x,f2.y,f2.z,f2.w, f3.x,f3.y,f3.z,f3.w};
        #pragma unroll
        for (int jj = 0; jj < 4; jj++)
            #pragma unroll
            for (int q = 0; q < 16; q++)
                acc[jj][q] = fmaf(kv[jj], ff[q], acc[jj][q]);
    }

    float gmr[16];
    #pragma unroll
    for (int q = 0; q < 16; q++) gmr[q] = gm_s[tn*16 + q];

    #pragma unroll
    for (int jj = 0; jj < 4; jj++) {
        int j = j0 + tj*4 + jj;
        size_t pair = rowbase + j;
        // max over 64 (16 local + 2 shfl over tn)
        float mx = acc[jj][0];
        #pragma unroll
        for (int q = 1; q < 16; q++) mx = fmaxf(mx, acc[jj][q]);
        mx = fmaxf(mx, __shfl_xor_sync(0xffffffffu, mx, 1));
        mx = fmaxf(mx, __shfl_xor_sync(0xffffffffu, mx, 2));
        float e[16];
        float sum = 0.f, sg = 0.f, sap = 0.f, sbd = 0.f, srs = 0.f;
        #pragma unroll
        for (int q = 0; q < 16; q++) {
            float ev = __expf(acc[jj][q] - mx);
            e[q] = ev;
            sum += ev;
            sg = fmaf(ev, gmr[q], sg);
            if (q & 1) sap += ev;
            if (q & 2) sbd += ev;
            if (q & 4) srs += ev;
        }
        sum += __shfl_xor_sync(0xffffffffu, sum, 1);
        sum += __shfl_xor_sync(0xffffffffu, sum, 2);
        sg  += __shfl_xor_sync(0xffffffffu, sg , 1);
        sg  += __shfl_xor_sync(0xffffffffu, sg , 2);
        sap += __shfl_xor_sync(0xffffffffu, sap, 1);
        sap += __shfl_xor_sync(0xffffffffu, sap, 2);
        sbd += __shfl_xor_sync(0xffffffffu, sbd, 1);
        sbd += __shfl_xor_sync(0xffffffffu, sbd, 2);
        srs += __shfl_xor_sync(0xffffffffu, srs, 1);
        srs += __shfl_xor_sync(0xffffffffu, srs, 2);

        float4* po = (float4*)(pi_out + pair*NV + tn*16);
        if (j > i) {
            float4 z = make_float4(0.f,0.f,0.f,0.f);
            po[0] = z; po[1] = z; po[2] = z; po[3] = z;
            if (tn == 0) { g_ws[pair]=0.f; g_wap[pair]=0.f; g_wbd[pair]=0.f; g_wrs[pair]=0.f; }
        } else {
            float inv = 1.f / sum;
            #pragma unroll
            for (int g = 0; g < 4; g++)
                po[g] = make_float4(e[g*4+0]*inv, e[g*4+1]*inv, e[g*4+2]*inv, e[g*4+3]*inv);
            if (tn == 0) {
                g_ws[pair]  = sg  * inv;
                g_wap[pair] = sap * inv;
                g_wbd[pair] = sbd * inv;
                g_wrs[pair] = srs * inv;
            }
        }
    }
}

// ---------------- per-row denominators ----------------
__global__ void reduce_rows_kernel()
{
    int row = blockIdx.x;
    size_t base = (size_t)row * Ss;
    int tid = threadIdx.x;
    float s0 = 0.f, s1 = 0.f, s2 = 0.f, s3 = 0.f;
    for (int j = tid; j < Ss; j += 256) {
        s0 += g_ws[base+j]; s1 += g_wap[base+j];
        s2 += g_wbd[base+j]; s3 += g_wrs[base+j];
    }
    __shared__ float r0[256], r1[256], r2[256], r3[256];
    r0[tid]=s0; r1[tid]=s1; r2[tid]=s2; r3[tid]=s3;
    __syncthreads();
    for (int off = 128; off; off >>= 1) {
        if (tid < off) { r0[tid]+=r0[tid+off]; r1[tid]+=r1[tid+off];
                         r2[tid]+=r2[tid+off]; r3[tid]+=r3[tid+off]; }
        __syncthreads();
    }
    if (tid == 0) {
        g_invden[row] = 1.f / (r0[0] + EPSV);
        float S1, d1, S2;
        S1 = r1[0]; d1 = S1 + EPSV; S2 = S1/d1; g_invden[1*BS+row] = 1.f/(d1*(S2+EPSV));
        S1 = r2[0]; d1 = S1 + EPSV; S2 = S1/d1; g_invden[2*BS+row] = 1.f/(d1*(S2+EPSV));
        S1 = r3[0]; d1 = S1 + EPSV; S2 = S1/d1; g_invden[3*BS+row] = 1.f/(d1*(S2+EPSV));
    }
}

// ---------------- combined = is*(ws@Vslice) + it*(wt@Tslice); 128x64 tiles ----------------
__global__ __launch_bounds__(256)
void combine_kernel()
{
    int bz = blockIdx.z;
    int b = bz >> 1 >> 0; // placeholder, recomputed below
    b = bz / 3;
    int t = bz % 3;
    const float* Wt = (t == 0) ? g_wap : (t == 1) ? g_wbd : g_wrs;
    int m0 = blockIdx.y * 128, n0 = blockIdx.x * 64;
    int colbase = t * D3 + n0;

    __shared__ float Ssm[8][132], Stm[8][132];
    __shared__ float Bv[8][68], Bt[8][68];
    int tid = threadIdx.x;
    int tm = tid >> 4, tn = tid & 15;

    float accs[8][4], acct[8][4];
    #pragma unroll
    for (int a = 0; a < 8; a++)
        #pragma unroll
        for (int c = 0; c < 4; c++) { accs[a][c] = 0.f; acct[a][c] = 0.f; }

    int wrow = tid >> 1, wkoff = (tid & 1) * 4;
    size_t wbase = (size_t)(b*Ss + m0 + wrow) * Ss + wkoff;
    int lk = (tid & 127) >> 4, ln4 = (tid & 15) * 4;

    int kmax = m0 + 128;
    for (int k0 = 0; k0 < kmax; k0 += 8) {
        float4 sv = *(const float4*)(g_ws + wbase + k0);
        float4 tv = *(const float4*)(Wt   + wbase + k0);
        float4 bv;
        if (tid < 128)
            bv = *(const float4*)(g_V   + (size_t)(b*Ss + k0 + lk)*Dd + colbase + ln4);
        else
            bv = *(const float4*)(g_ABR + (size_t)(b*Ss + k0 + lk)*Dd + colbase + ln4);
        __syncthreads();
        Ssm[wkoff+0][wrow]=sv.x; Ssm[wkoff+1][wrow]=sv.y;
        Ssm[wkoff+2][wrow]=sv.z; Ssm[wkoff+3][wrow]=sv.w;
        Stm[wkoff+0][wrow]=tv.x; Stm[wkoff+1][wrow]=tv.y;
        Stm[wkoff+2][wrow]=tv.z; Stm[wkoff+3][wrow]=tv.w;
        if (tid < 128) { *(float4*)&Bv[lk][ln4] = bv; }
        else           { *(float4*)&Bt[lk][ln4] = bv; }
        __syncthreads();
        #pragma unroll
        for (int kk = 0; kk < 8; kk++) {
            float4 s0 = *(const float4*)&Ssm[kk][tm*8];
            float4 s1 = *(const float4*)&Ssm[kk][tm*8+4];
            float4 t0 = *(const float4*)&Stm[kk][tm*8];
            float4 t1 = *(const float4*)&Stm[kk][tm*8+4];
            float4 vv = *(const float4*)&Bv[kk][tn*4];
            float4 mm = *(const float4*)&Bt[kk][tn*4];
            float xs[8] = {s0.x,s0.y,s0.z,s0.w, s1.x,s1.y,s1.z,s1.w};
            float xt[8] = {t0.x,t0.y,t0.z,t0.w, t1.x,t1.y,t1.z,t1.w};
            float bvv[4] = {vv.x,vv.y,vv.z,vv.w};
            float btt[4] = {mm.x,mm.y,mm.z,mm.w};
            #pragma unroll
            for (int a = 0; a < 8; a++)
                #pragma unroll
                for (int c = 0; c < 4; c++) {
                    accs[a][c] = fmaf(xs[a], bvv[c], accs[a][c]);
                    acct[a][c] = fmaf(xt[a], btt[c], acct[a][c]);
                }
        }
    }
    #pragma unroll
    for (int a = 0; a < 8; a++) {
        int m = m0 + tm*8 + a;
        float is = g_invden[b*Ss + m];
        float it = g_invden[(t+1)*BS + b*Ss + m];
        float4 o = make_float4(is*accs[a][0] + it*acct[a][0],
                               is*accs[a][1] + it*acct[a][1],
                               is*accs[a][2] + it*acct[a][2],
                               is*accs[a][3] + it*acct[a][3]);
        *(float4*)(g_comb + (size_t)(b*Ss + m)*Dd + colbase + tn*4) = o;
    }
}

// ---------------- result -> layernorm -> out ----------------
__global__ void ln_kernel(const float* __restrict__ bo, const float* __restrict__ gamma,
                          const float* __restrict__ beta, float* __restrict__ out)
{
    int row = blockIdx.x, tid = threadIdx.x;
    const float* r = g_res + (size_t)row * Dd;
    float v[3];
    float s = 0.f;
    #pragma unroll
    for (int q = 0; q < 3; q++) { int c = tid + q*256; v[q] = r[c] + bo[c]; s += v[q]; }
    __shared__ float red[256];
    __shared__ float mu_s, inv_s;
    red[tid] = s; __syncthreads();
    for (int off = 128; off; off >>= 1) {
        if (tid < off) red[tid] += red[tid + off];
        __syncthreads();
    }
    if (tid == 0) mu_s = red[0] * (1.f / Dd);
    __syncthreads();
    float mu = mu_s;
    float s2 = 0.f;
    #pragma unroll
    for (int q = 0; q < 3; q++) { float d = v[q] - mu; s2 += d*d; }
    __syncthreads();
    red[tid] = s2; __syncthreads();
    for (int off = 128; off; off >>= 1) {
        if (tid < off) red[tid] += red[tid + off];
        __syncthreads();
    }
    if (tid == 0) inv_s = rsqrtf(red[0] * (1.f / Dd) + LNEPS);
    __syncthreads();
    float inv = inv_s;
    #pragma unroll
    for (int q = 0; q < 3; q++) {
        int c = tid + q*256;
        out[(size_t)row*Dd + c] = (v[q] - mu) * inv * gamma[c] + beta[c];
    }
}

// ---------------- launch ----------------
extern "C" void kernel_launch(void* const* d_in, const int* in_sizes, int n_in,
                              void* d_out, int out_size)
{
    const float* x      = (const float*)d_in[0];
    const float* Wq     = (const float*)d_in[2];
    const float* Wk     = (const float*)d_in[3];
    const float* vemb   = (const float*)d_in[4];
    const float* vgates = (const float*)d_in[5];
    const float* Wv     = (const float*)d_in[6];
    const float* Wspec  = (const float*)d_in[7];
    const float* Wa     = (const float*)d_in[8];
    const float* Wb     = (const float*)d_in[9];
    const float* Wr     = (const float*)d_in[10];
    const float* Wo     = (const float*)d_in[11];
    const float* bo     = (const float*)d_in[12];
    const float* gamma  = (const float*)d_in[13];
    const float* beta   = (const float*)d_in[14];
    const float* adj    = (const float*)d_in[15];
    const float* spec   = (const float*)d_in[16];

    float* out    = (float*)d_out;
    float* pi_out = out + NORMED_ELEMS;

    float *pQK, *pV, *pABR, *pComb, *pRes;
    cudaGetSymbolAddress((void**)&pQK,   g_QK);
    cudaGetSymbolAddress((void**)&pV,    g_V);
    cudaGetSymbolAddress((void**)&pABR,  g_ABR);
    cudaGetSymbolAddress((void**)&pComb, g_comb);
    cudaGetSymbolAddress((void**)&pRes,  g_res);

    dim3 thr(256);
    const int BIG = 1 << 30;
    // QK: rows 0-31 from Wq, 32-63 from Wk
    gemm_big<<<dim3( 1, 16), thr>>>(x, Wq, Wk, Wk, 32, BIG, pQK, 64);
    gemm_big<<<dim3(12, 16), thr>>>(x, Wv, Wv, Wv, BIG, BIG, pV, Dd);
    gemm_big<<<dim3(12, 16), thr>>>(x, Wa, Wb, Wr, 256, 512, pABR, Dd);

    prep_emb_kernel<<<1, 256>>>(vemb, spec, Wspec, adj);
    gate_mean_kernel<<<64, 256>>>(vgates);

    attn_kernel<<<dim3(4, Ss, Bb), 256>>>(pi_out);
    reduce_rows_kernel<<<BS, 256>>>();
    combine_kernel<<<dim3(4, 8, 6), 256>>>();

    gemm_big<<<dim3(12, 16), thr>>>(pComb, Wo, Wo, Wo, BIG, BIG, pRes, Dd);
    ln_kernel<<<BS, 256>>>(bo, gamma, beta, out);
}

// round 3
// speedup vs baseline: 2.2793x; 1.5078x over previous
#include <cuda_runtime.h>

#define Bb 2
#define Ss 1024
#define Dd 768
#define DV 32
#define NV 64
#define D3 256
#define BS (Bb*Ss)
#define Kd 768
#define EPSV 1e-8f
#define LNEPS 1e-5f
#define NORMED_ELEMS ((size_t)Bb*Ss*Dd)

// ---------------- scratch ----------------
__device__ float g_QK[BS*64];            // cols 0-31 = Q, 32-63 = K
__device__ float g_V[BS*Dd];
__device__ float g_ABR[BS*Dd];           // cols 0-255 = A, 256-511 = B, 512-767 = R
__device__ float g_emb2[NV*DV];
__device__ float g_gm[NV];
__device__ float g_ws [(size_t)BS*Ss];
__device__ float g_wap[(size_t)BS*Ss];
__device__ float g_wbd[(size_t)BS*Ss];
__device__ float g_wrs[(size_t)BS*Ss];
__device__ float g_invden[4*BS];
__device__ float g_comb[BS*Dd];
__device__ float g_res[BS*Dd];

// ---------------- tf32 helpers ----------------
__device__ __forceinline__ float f2tf32(float f) {
    unsigned r;
    asm("cvt.rna.tf32.f32 %0, %1;" : "=r"(r) : "f"(f));
    return __uint_as_float(r);
}
__device__ __forceinline__ void mma_tf32(float* c, const unsigned* a, const unsigned* b) {
    asm volatile("mma.sync.aligned.m16n8k8.row.col.f32.tf32.tf32.f32 "
                 "{%0,%1,%2,%3}, {%4,%5,%6,%7}, {%8,%9}, {%0,%1,%2,%3};"
                 : "+f"(c[0]), "+f"(c[1]), "+f"(c[2]), "+f"(c[3])
                 : "r"(a[0]), "r"(a[1]), "r"(a[2]), "r"(a[3]), "r"(b[0]), "r"(b[1]));
}

// ======== TF32 GEMM: C = X(MxK) @ Wsel(NxK)^T ; BM=128 BN=64 BK=16 ========
__global__ __launch_bounds__(256)
void gemm_tc(const float* __restrict__ X,
             const float* __restrict__ W0, const float* __restrict__ W1,
             const float* __restrict__ W2, int s1, int s2,
             float* __restrict__ C, int N)
{
    __shared__ float As[16][136];
    __shared__ float Bs[16][72];
    int tid = threadIdx.x;
    int lane = tid & 31, warp = tid >> 5;
    int wm = warp & 3, wn = warp >> 2;
    int gid = lane >> 2, tig = lane & 3;
    int m0 = blockIdx.y * 128, n0 = blockIdx.x * 64;

    float c[2][4][4];
    #pragma unroll
    for (int mt = 0; mt < 2; mt++)
        #pragma unroll
        for (int nt = 0; nt < 4; nt++)
            #pragma unroll
            for (int e = 0; e < 4; e++) c[mt][nt][e] = 0.f;

    int ra = tid >> 2;                 // 0..63
    int ka = (tid & 3) * 4;
    int sw = 8 * (tid & 3);            // XOR swizzle for the 4 k's this thread stores
    const float* xp0 = X + (size_t)(m0 + ra) * Kd + ka;
    const float* xp1 = X + (size_t)(m0 + ra + 64) * Kd + ka;
    int rW = n0 + ra;
    const float* wp = (rW < s1) ? (W0 + (size_t)rW * Kd + ka)
                    : (rW < s2) ? (W1 + (size_t)(rW - s1) * Kd + ka)
                                : (W2 + (size_t)(rW - s2) * Kd + ka);

    for (int k0 = 0; k0 < Kd; k0 += 16) {
        float4 av0 = *(const float4*)(xp0 + k0);
        float4 av1 = *(const float4*)(xp1 + k0);
        float4 bv  = *(const float4*)(wp  + k0);
        __syncthreads();
        int ca = ra ^ sw, ca1 = (ra + 64) ^ sw;
        As[ka+0][ca]  = f2tf32(av0.x); As[ka+1][ca]  = f2tf32(av0.y);
        As[ka+2][ca]  = f2tf32(av0.z); As[ka+3][ca]  = f2tf32(av0.w);
        As[ka+0][ca1] = f2tf32(av1.x); As[ka+1][ca1] = f2tf32(av1.y);
        As[ka+2][ca1] = f2tf32(av1.z); As[ka+3][ca1] = f2tf32(av1.w);
        Bs[ka+0][ca & 127] = f2tf32(bv.x); Bs[ka+1][ca & 127] = f2tf32(bv.y);
        Bs[ka+2][ca & 127] = f2tf32(bv.z); Bs[ka+3][ca & 127] = f2tf32(bv.w);
        __syncthreads();
        #pragma unroll
        for (int ks = 0; ks < 16; ks += 8) {
            int swl = 8 * (ks >> 2), swh = swl + 8;
            int klo = ks + tig, khi = ks + tig + 4;
            unsigned a[2][4], b[4][2];
            #pragma unroll
            for (int mt = 0; mt < 2; mt++) {
                int mr = wm*32 + mt*16 + gid;
                a[mt][0] = __float_as_uint(As[klo][ mr      ^ swl]);
                a[mt][1] = __float_as_uint(As[klo][(mr + 8) ^ swl]);
                a[mt][2] = __float_as_uint(As[khi][ mr      ^ swh]);
                a[mt][3] = __float_as_uint(As[khi][(mr + 8) ^ swh]);
            }
            #pragma unroll
            for (int nt = 0; nt < 4; nt++) {
                int nc = wn*32 + nt*8 + gid;
                b[nt][0] = __float_as_uint(Bs[klo][nc ^ swl]);
                b[nt][1] = __float_as_uint(Bs[khi][nc ^ swh]);
            }
            #pragma unroll
            for (int mt = 0; mt < 2; mt++)
                #pragma unroll
                for (int nt = 0; nt < 4; nt++)
                    mma_tf32(c[mt][nt], a[mt], b[nt]);
        }
    }
    #pragma unroll
    for (int mt = 0; mt < 2; mt++) {
        int r0 = m0 + wm*32 + mt*16 + gid;
        #pragma unroll
        for (int nt = 0; nt < 4; nt++) {
            int cc = n0 + wn*32 + nt*8 + tig*2;
            *(float2*)(C + (size_t)r0 * N + cc)       = make_float2(c[mt][nt][0], c[mt][nt][1]);
            *(float2*)(C + (size_t)(r0+8) * N + cc)   = make_float2(c[mt][nt][2], c[mt][nt][3]);
        }
    }
}

// ======== TF32 combine: comb = (is*ws)@Vslice + (it*wt)@Tslice ========
__global__ __launch_bounds__(256)
void combine_tc()
{
    int bz = blockIdx.z;
    int b = bz / 3, t = bz % 3;
    const float* Wt = (t == 0) ? g_wap : (t == 1) ? g_wbd : g_wrs;
    int m0 = blockIdx.y * 128, n0 = blockIdx.x * 64;
    int colbase = t * D3 + n0;

    __shared__ float As[16][136];
    __shared__ float Bs[16][72];
    int tid = threadIdx.x;
    int lane = tid & 31, warp = tid >> 5;
    int wm = warp & 3, wn = warp >> 2;
    int gid = lane >> 2, tig = lane & 3;

    float c[2][4][4];
    #pragma unroll
    for (int mt = 0; mt < 2; mt++)
        #pragma unroll
        for (int nt = 0; nt < 4; nt++)
            #pragma unroll
            for (int e = 0; e < 4; e++) c[mt][nt][e] = 0.f;

    int ra = tid >> 2, ka = (tid & 3) * 4;
    int sw = 8 * (tid & 3);
    int kb = tid >> 4;                  // B load: k-local 0..15
    int nb = (tid & 15) * 4;            // n 0..60
    int swb = 8 * (kb >> 2);

    int kmax = m0 + 128;

    #pragma unroll
    for (int p = 0; p < 2; p++) {
        const float* Am = p ? Wt : g_ws;
        const float* Bm = p ? g_ABR : g_V;
        const float* dscale = g_invden + (p ? (t+1)*BS : 0) + b*Ss;
        float sc0 = dscale[m0 + ra];
        float sc1 = dscale[m0 + ra + 64];
        const float* ap0 = Am + (size_t)(b*Ss + m0 + ra) * Ss + ka;
        const float* ap1 = Am + (size_t)(b*Ss + m0 + ra + 64) * Ss + ka;

        for (int k0 = 0; k0 < kmax; k0 += 16) {
            float4 av0 = *(const float4*)(ap0 + k0);
            float4 av1 = *(const float4*)(ap1 + k0);
            float4 bv  = *(const float4*)(Bm + (size_t)(b*Ss + k0 + kb) * Dd + colbase + nb);
            __syncthreads();
            int ca = ra ^ sw, ca1 = (ra + 64) ^ sw;
            As[ka+0][ca]  = f2tf32(av0.x * sc0); As[ka+1][ca]  = f2tf32(av0.y * sc0);
            As[ka+2][ca]  = f2tf32(av0.z * sc0); As[ka+3][ca]  = f2tf32(av0.w * sc0);
            As[ka+0][ca1] = f2tf32(av1.x * sc1); As[ka+1][ca1] = f2tf32(av1.y * sc1);
            As[ka+2][ca1] = f2tf32(av1.z * sc1); As[ka+3][ca1] = f2tf32(av1.w * sc1);
            Bs[kb][(nb+0) ^ swb] = f2tf32(bv.x);
            Bs[kb][(nb+1) ^ swb] = f2tf32(bv.y);
            Bs[kb][(nb+2) ^ swb] = f2tf32(bv.z);
            Bs[kb][(nb+3) ^ swb] = f2tf32(bv.w);
            __syncthreads();
            #pragma unroll
            for (int ks = 0; ks < 16; ks += 8) {
                int swl = 8 * (ks >> 2), swh = swl + 8;
                int klo = ks + tig, khi = ks + tig + 4;
                unsigned a[2][4], bfr[4][2];
                #pragma unroll
                for (int mt = 0; mt < 2; mt++) {
                    int mr = wm*32 + mt*16 + gid;
                    a[mt][0] = __float_as_uint(As[klo][ mr      ^ swl]);
                    a[mt][1] = __float_as_uint(As[klo][(mr + 8) ^ swl]);
                    a[mt][2] = __float_as_uint(As[khi][ mr      ^ swh]);
                    a[mt][3] = __float_as_uint(As[khi][(mr + 8) ^ swh]);
                }
                #pragma unroll
                for (int nt = 0; nt < 4; nt++) {
                    int nc = wn*32 + nt*8 + gid;
                    bfr[nt][0] = __float_as_uint(Bs[klo][nc ^ swl]);
                    bfr[nt][1] = __float_as_uint(Bs[khi][nc ^ swh]);
                }
                #pragma unroll
                for (int mt = 0; mt < 2; mt++)
                    #pragma unroll
                    for (int nt = 0; nt < 4; nt++)
                        mma_tf32(c[mt][nt], a[mt], bfr[nt]);
            }
        }
        __syncthreads();
    }
    #pragma unroll
    for (int mt = 0; mt < 2; mt++) {
        int r0 = b*Ss + m0 + wm*32 + mt*16 + gid;
        #pragma unroll
        for (int nt = 0; nt < 4; nt++) {
            int cc = colbase + wn*32 + nt*8 + tig*2;
            *(float2*)(g_comb + (size_t)r0 * Dd + cc)     = make_float2(c[mt][nt][0], c[mt][nt][1]);
            *(float2*)(g_comb + (size_t)(r0+8) * Dd + cc) = make_float2(c[mt][nt][2], c[mt][nt][3]);
        }
    }
}

// ---------------- emb2 = (I + 0.1*adj)^T @ (vemb + 0.1*spec@Wspec^T) ----------------
__global__ __launch_bounds__(1024)
void prep_emb_kernel(const float* __restrict__ vemb, const float* __restrict__ spec,
                     const float* __restrict__ Wspec, const float* __restrict__ adj)
{
    __shared__ float eb[NV*DV];
    __shared__ float adj_s[NV*NV];
    int tid = threadIdx.x;
    for (int t = tid; t < NV*DV; t += 1024) {
        int u = t / DV, d = t % DV;
        float s = vemb[t];
        #pragma unroll
        for (int h = 0; h < 6; h++) s += 0.1f * spec[u*6+h] * Wspec[d*6+h];
        eb[t] = s;
    }
    for (int t = tid; t < NV*NV; t += 1024) adj_s[t] = adj[t];
    __syncthreads();
    for (int t = tid; t < NV*DV; t += 1024) {
        int v = t / DV, d = t % DV;
        float s = eb[t];
        #pragma unroll 8
        for (int u = 0; u < NV; u++) s += 0.1f * adj_s[u*NV + v] * eb[u*DV + d];
        g_emb2[t] = s;
    }
}

__global__ void gate_mean_kernel(const float* __restrict__ vg)
{
    int v = blockIdx.x;
    float s = 0.f;
    for (int c = threadIdx.x; c < Dd; c += 256) {
        float x = vg[(size_t)v*Dd + c];
        s += 1.f / (1.f + __expf(-x));
    }
    __shared__ float red[256];
    red[threadIdx.x] = s; __syncthreads();
    for (int off = 128; off; off >>= 1) {
        if (threadIdx.x < off) red[threadIdx.x] += red[threadIdx.x + off];
        __syncthreads();
    }
    if (threadIdx.x == 0) g_gm[v] = red[0] * (1.f / Dd);
}

// ---------------- attention: per (b,i,j-tile256); S = K @ F^T, F=q*emb2 ----------------
__global__ __launch_bounds__(256)
void attn_kernel(float* __restrict__ pi_out)
{
    int j0 = blockIdx.x * 256, i = blockIdx.y, b = blockIdx.z;
    size_t rowbase = (size_t)(b*Ss + i) * Ss;
    int tid = threadIdx.x;

    if (j0 > i) {
        float4 z = make_float4(0.f,0.f,0.f,0.f);
        float4* base = (float4*)(pi_out + (rowbase + j0) * NV);
        for (int t = tid; t < 4096; t += 256) base[t] = z;
        size_t p = rowbase + j0 + tid;
        g_ws[p] = 0.f; g_wap[p] = 0.f; g_wbd[p] = 0.f; g_wrs[p] = 0.f;
        return;
    }

    __shared__ float F[DV][NV];       // F[d][v] = q[d]*emb2[v][d]
    __shared__ float Ksm[256][33];
    __shared__ float q_s[DV];
    __shared__ float gm_s[NV];

    if (tid < DV) q_s[tid] = g_QK[(size_t)(b*Ss + i)*64 + tid];
    if (tid < NV) gm_s[tid] = g_gm[tid];
    __syncthreads();
    for (int t = tid; t < NV*DV; t += 256) {
        int v = t >> 5, d = t & 31;
        F[d][v] = q_s[d] * g_emb2[v*DV + d];
    }
    for (int t = tid; t < 2048; t += 256) {
        int r = t >> 3, q = t & 7;
        float4 kv = *(const float4*)(g_QK + (size_t)(b*Ss + j0 + r)*64 + 32 + q*4);
        Ksm[r][q*4+0] = kv.x; Ksm[r][q*4+1] = kv.y;
        Ksm[r][q*4+2] = kv.z; Ksm[r][q*4+3] = kv.w;
    }
    __syncthreads();

    int tn = tid & 3, tj = tid >> 2;
    float acc[4][16];
    #pragma unroll
    for (int jj = 0; jj < 4; jj++)
        #pragma unroll
        for (int q = 0; q < 16; q++) acc[jj][q] = 0.f;

    #pragma unroll 8
    for (int d = 0; d < DV; d++) {
        float kv[4];
        #pragma unroll
        for (int jj = 0; jj < 4; jj++) kv[jj] = Ksm[tj*4 + jj][d];
        float4 f0 = *(const float4*)&F[d][tn*16];
        float4 f1 = *(const float4*)&F[d][tn*16+4];
        float4 f2 = *(const float4*)&F[d][tn*16+8];
        float4 f3 = *(const float4*)&F[d][tn*16+12];
        float ff[16] = {f0.x,f0.y,f0.z,f0.w, f1.x,f1.y,f1.z,f1.w,
                        f2.x,f2.y,f2.z,f2.w, f3.x,f3.y,f3.z,f3.w};
        #pragma unroll
        for (int jj = 0; jj < 4; jj++)
            #pragma unroll
            for (int q = 0; q < 16; q++)
                acc[jj][q] = fmaf(kv[jj], ff[q], acc[jj][q]);
    }

    float gmr[16];
    #pragma unroll
    for (int q = 0; q < 16; q++) gmr[q] = gm_s[tn*16 + q];

    #pragma unroll
    for (int jj = 0; jj < 4; jj++) {
        int j = j0 + tj*4 + jj;
        size_t pair = rowbase + j;
        float mx = acc[jj][0];
        #pragma unroll
        for (int q = 1; q < 16; q++) mx = fmaxf(mx, acc[jj][q]);
        mx = fmaxf(mx, __shfl_xor_sync(0xffffffffu, mx, 1));
        mx = fmaxf(mx, __shfl_xor_sync(0xffffffffu, mx, 2));
        float e[16];
        float sum = 0.f, sg = 0.f, sap = 0.f, sbd = 0.f, srs = 0.f;
        #pragma unroll
        for (int q = 0; q < 16; q++) {
            float ev = __expf(acc[jj][q] - mx);
            e[q] = ev;
            sum += ev;
            sg = fmaf(ev, gmr[q], sg);
            if (q & 1) sap += ev;
            if (q & 2) sbd += ev;
            if (q & 4) srs += ev;
        }
        sum += __shfl_xor_sync(0xffffffffu, sum, 1);
        sum += __shfl_xor_sync(0xffffffffu, sum, 2);
        sg  += __shfl_xor_sync(0xffffffffu, sg , 1);
        sg  += __shfl_xor_sync(0xffffffffu, sg , 2);
        sap += __shfl_xor_sync(0xffffffffu, sap, 1);
        sap += __shfl_xor_sync(0xffffffffu, sap, 2);
        sbd += __shfl_xor_sync(0xffffffffu, sbd, 1);
        sbd += __shfl_xor_sync(0xffffffffu, sbd, 2);
        srs += __shfl_xor_sync(0xffffffffu, srs, 1);
        srs += __shfl_xor_sync(0xffffffffu, srs, 2);

        float4* po = (float4*)(pi_out + pair*NV + tn*16);
        if (j > i) {
            float4 z = make_float4(0.f,0.f,0.f,0.f);
            po[0] = z; po[1] = z; po[2] = z; po[3] = z;
            if (tn == 0) { g_ws[pair]=0.f; g_wap[pair]=0.f; g_wbd[pair]=0.f; g_wrs[pair]=0.f; }
        } else {
            float inv = 1.f / sum;
            #pragma unroll
            for (int g = 0; g < 4; g++)
                po[g] = make_float4(e[g*4+0]*inv, e[g*4+1]*inv, e[g*4+2]*inv, e[g*4+3]*inv);
            if (tn == 0) {
                g_ws[pair]  = sg  * inv;
                g_wap[pair] = sap * inv;
                g_wbd[pair] = sbd * inv;
                g_wrs[pair] = srs * inv;
            }
        }
    }
}

// ---------------- per-row denominators ----------------
__global__ void reduce_rows_kernel()
{
    int row = blockIdx.x;
    size_t base = (size_t)row * Ss;
    int tid = threadIdx.x;
    float s0 = 0.f, s1 = 0.f, s2 = 0.f, s3 = 0.f;
    for (int j = tid; j < Ss; j += 256) {
        s0 += g_ws[base+j]; s1 += g_wap[base+j];
        s2 += g_wbd[base+j]; s3 += g_wrs[base+j];
    }
    __shared__ float r0[256], r1[256], r2[256], r3[256];
    r0[tid]=s0; r1[tid]=s1; r2[tid]=s2; r3[tid]=s3;
    __syncthreads();
    for (int off = 128; off; off >>= 1) {
        if (tid < off) { r0[tid]+=r0[tid+off]; r1[tid]+=r1[tid+off];
                         r2[tid]+=r2[tid+off]; r3[tid]+=r3[tid+off]; }
        __syncthreads();
    }
    if (tid == 0) {
        g_invden[row] = 1.f / (r0[0] + EPSV);
        float S1, d1, S2;
        S1 = r1[0]; d1 = S1 + EPSV; S2 = S1/d1; g_invden[1*BS+row] = 1.f/(d1*(S2+EPSV));
        S1 = r2[0]; d1 = S1 + EPSV; S2 = S1/d1; g_invden[2*BS+row] = 1.f/(d1*(S2+EPSV));
        S1 = r3[0]; d1 = S1 + EPSV; S2 = S1/d1; g_invden[3*BS+row] = 1.f/(d1*(S2+EPSV));
    }
}

// ---------------- layernorm ----------------
__global__ void ln_kernel(const float* __restrict__ bo, const float* __restrict__ gamma,
                          const float* __restrict__ beta, float* __restrict__ out)
{
    int row = blockIdx.x, tid = threadIdx.x;
    const float* r = g_res + (size_t)row * Dd;
    float v[3];
    float s = 0.f;
    #pragma unroll
    for (int q = 0; q < 3; q++) { int c = tid + q*256; v[q] = r[c] + bo[c]; s += v[q]; }
    __shared__ float red[256];
    __shared__ float mu_s, inv_s;
    red[tid] = s; __syncthreads();
    for (int off = 128; off; off >>= 1) {
        if (tid < off) red[tid] += red[tid + off];
        __syncthreads();
    }
    if (tid == 0) mu_s = red[0] * (1.f / Dd);
    __syncthreads();
    float mu = mu_s;
    float s2 = 0.f;
    #pragma unroll
    for (int q = 0; q < 3; q++) { float d = v[q] - mu; s2 += d*d; }
    __syncthreads();
    red[tid] = s2; __syncthreads();
    for (int off = 128; off; off >>= 1) {
        if (tid < off) red[tid] += red[tid + off];
        __syncthreads();
    }
    if (tid == 0) inv_s = rsqrtf(red[0] * (1.f / Dd) + LNEPS);
    __syncthreads();
    float inv = inv_s;
    #pragma unroll
    for (int q = 0; q < 3; q++) {
        int c = tid + q*256;
        out[(size_t)row*Dd + c] = (v[q] - mu) * inv * gamma[c] + beta[c];
    }
}

// ---------------- launch ----------------
extern "C" void kernel_launch(void* const* d_in, const int* in_sizes, int n_in,
                              void* d_out, int out_size)
{
    const float* x      = (const float*)d_in[0];
    const float* Wq     = (const float*)d_in[2];
    const float* Wk     = (const float*)d_in[3];
    const float* vemb   = (const float*)d_in[4];
    const float* vgates = (const float*)d_in[5];
    const float* Wv     = (const float*)d_in[6];
    const float* Wspec  = (const float*)d_in[7];
    const float* Wa     = (const float*)d_in[8];
    const float* Wb     = (const float*)d_in[9];
    const float* Wr     = (const float*)d_in[10];
    const float* Wo     = (const float*)d_in[11];
    const float* bo     = (const float*)d_in[12];
    const float* gamma  = (const float*)d_in[13];
    const float* beta   = (const float*)d_in[14];
    const float* adj    = (const float*)d_in[15];
    const float* spec   = (const float*)d_in[16];

    float* out    = (float*)d_out;
    float* pi_out = out + NORMED_ELEMS;

    float *pQK, *pV, *pABR, *pComb, *pRes;
    cudaGetSymbolAddress((void**)&pQK,   g_QK);
    cudaGetSymbolAddress((void**)&pV,    g_V);
    cudaGetSymbolAddress((void**)&pABR,  g_ABR);
    cudaGetSymbolAddress((void**)&pComb, g_comb);
    cudaGetSymbolAddress((void**)&pRes,  g_res);

    dim3 thr(256);
    const int BIG = 1 << 30;
    gemm_tc<<<dim3( 1, 16), thr>>>(x, Wq, Wk, Wk, 32, BIG, pQK, 64);
    gemm_tc<<<dim3(12, 16), thr>>>(x, Wv, Wv, Wv, BIG, BIG, pV, Dd);
    gemm_tc<<<dim3(12, 16), thr>>>(x, Wa, Wb, Wr, 256, 512, pABR, Dd);

    prep_emb_kernel<<<1, 1024>>>(vemb, spec, Wspec, adj);
    gate_mean_kernel<<<64, 256>>>(vgates);

    attn_kernel<<<dim3(4, Ss, Bb), 256>>>(pi_out);
    reduce_rows_kernel<<<BS, 256>>>();
    combine_tc<<<dim3(4, 8, 6), 256>>>();

    gemm_tc<<<dim3(12, 16), thr>>>(pComb, Wo, Wo, Wo, BIG, BIG, pRes, Dd);
    ln_kernel<<<BS, 256>>>(bo, gamma, beta, out);
}

// round 4
// speedup vs baseline: 2.8694x; 1.2589x over previous
#include <cuda_runtime.h>

#define Bb 2
#define Ss 1024
#define Dd 768
#define DV 32
#define NV 64
#define D3 256
#define BS (Bb*Ss)
#define Kd 768
#define EPSV 1e-8f
#define LNEPS 1e-5f
#define NORMED_ELEMS ((size_t)Bb*Ss*Dd)

// ---------------- scratch ----------------
__device__ float g_QK[BS*64];            // cols 0-31 = Q, 32-63 = K
__device__ float g_V[BS*Dd];
__device__ float g_ABR[BS*Dd];
__device__ float g_emb2[NV*DV];
__device__ float g_gm[NV];
__device__ float g_ws [(size_t)BS*Ss];
__device__ float g_wap[(size_t)BS*Ss];
__device__ float g_wbd[(size_t)BS*Ss];
__device__ float g_wrs[(size_t)BS*Ss];
__device__ float g_rowpart[16*BS];       // [jblk][scalar][row]
__device__ float g_invden[4*BS];
__device__ float g_comb[BS*Dd];
__device__ float g_res[BS*Dd];

// ---------------- tf32 helpers ----------------
__device__ __forceinline__ float f2tf32(float f) {
    unsigned r;
    asm("cvt.rna.tf32.f32 %0, %1;" : "=r"(r) : "f"(f));
    return __uint_as_float(r);
}
__device__ __forceinline__ void mma_tf32(float* c, const unsigned* a, const unsigned* b) {
    asm volatile("mma.sync.aligned.m16n8k8.row.col.f32.tf32.tf32.f32 "
                 "{%0,%1,%2,%3}, {%4,%5,%6,%7}, {%8,%9}, {%0,%1,%2,%3};"
                 : "+f"(c[0]), "+f"(c[1]), "+f"(c[2]), "+f"(c[3])
                 : "r"(a[0]), "r"(a[1]), "r"(a[2]), "r"(a[3]), "r"(b[0]), "r"(b[1]));
}

// ======== TF32 GEMM: C = X(MxK) @ Wsel(NxK)^T ; BM=128 BN=64 BK=16 ========
__global__ __launch_bounds__(256)
void gemm_tc(const float* __restrict__ X,
             const float* __restrict__ W0, const float* __restrict__ W1,
             const float* __restrict__ W2, int s1, int s2,
             float* __restrict__ C, int N)
{
    __shared__ float As[16][136];
    __shared__ float Bs[16][72];
    int tid = threadIdx.x;
    int lane = tid & 31, warp = tid >> 5;
    int wm = warp & 3, wn = warp >> 2;
    int gid = lane >> 2, tig = lane & 3;
    int m0 = blockIdx.y * 128, n0 = blockIdx.x * 64;

    float c[2][4][4];
    #pragma unroll
    for (int mt = 0; mt < 2; mt++)
        #pragma unroll
        for (int nt = 0; nt < 4; nt++)
            #pragma unroll
            for (int e = 0; e < 4; e++) c[mt][nt][e] = 0.f;

    int ra = tid >> 2;
    int ka = (tid & 3) * 4;
    int sw = 8 * (tid & 3);
    const float* xp0 = X + (size_t)(m0 + ra) * Kd + ka;
    const float* xp1 = X + (size_t)(m0 + ra + 64) * Kd + ka;
    int rW = n0 + ra;
    const float* wp = (rW < s1) ? (W0 + (size_t)rW * Kd + ka)
                    : (rW < s2) ? (W1 + (size_t)(rW - s1) * Kd + ka)
                                : (W2 + (size_t)(rW - s2) * Kd + ka);

    for (int k0 = 0; k0 < Kd; k0 += 16) {
        float4 av0 = *(const float4*)(xp0 + k0);
        float4 av1 = *(const float4*)(xp1 + k0);
        float4 bv  = *(const float4*)(wp  + k0);
        __syncthreads();
        int ca = ra ^ sw, ca1 = (ra + 64) ^ sw;
        As[ka+0][ca]  = f2tf32(av0.x); As[ka+1][ca]  = f2tf32(av0.y);
        As[ka+2][ca]  = f2tf32(av0.z); As[ka+3][ca]  = f2tf32(av0.w);
        As[ka+0][ca1] = f2tf32(av1.x); As[ka+1][ca1] = f2tf32(av1.y);
        As[ka+2][ca1] = f2tf32(av1.z); As[ka+3][ca1] = f2tf32(av1.w);
        Bs[ka+0][ca & 127] = f2tf32(bv.x); Bs[ka+1][ca & 127] = f2tf32(bv.y);
        Bs[ka+2][ca & 127] = f2tf32(bv.z); Bs[ka+3][ca & 127] = f2tf32(bv.w);
        __syncthreads();
        #pragma unroll
        for (int ks = 0; ks < 16; ks += 8) {
            int swl = 8 * (ks >> 2), swh = swl + 8;
            int klo = ks + tig, khi = ks + tig + 4;
            unsigned a[2][4], b[4][2];
            #pragma unroll
            for (int mt = 0; mt < 2; mt++) {
                int mr = wm*32 + mt*16 + gid;
                a[mt][0] = __float_as_uint(As[klo][ mr      ^ swl]);
                a[mt][1] = __float_as_uint(As[klo][(mr + 8) ^ swl]);
                a[mt][2] = __float_as_uint(As[khi][ mr      ^ swh]);
                a[mt][3] = __float_as_uint(As[khi][(mr + 8) ^ swh]);
            }
            #pragma unroll
            for (int nt = 0; nt < 4; nt++) {
                int nc = wn*32 + nt*8 + gid;
                b[nt][0] = __float_as_uint(Bs[klo][nc ^ swl]);
                b[nt][1] = __float_as_uint(Bs[khi][nc ^ swh]);
            }
            #pragma unroll
            for (int mt = 0; mt < 2; mt++)
                #pragma unroll
                for (int nt = 0; nt < 4; nt++)
                    mma_tf32(c[mt][nt], a[mt], b[nt]);
        }
    }
    #pragma unroll
    for (int mt = 0; mt < 2; mt++) {
        int r0 = m0 + wm*32 + mt*16 + gid;
        #pragma unroll
        for (int nt = 0; nt < 4; nt++) {
            int cc = n0 + wn*32 + nt*8 + tig*2;
            *(float2*)(C + (size_t)r0 * N + cc)       = make_float2(c[mt][nt][0], c[mt][nt][1]);
            *(float2*)(C + (size_t)(r0+8) * N + cc)   = make_float2(c[mt][nt][2], c[mt][nt][3]);
        }
    }
}

// ======== TF32 combine: comb = (is*ws)@Vslice + (it*wt)@Tslice ========
__global__ __launch_bounds__(256)
void combine_tc()
{
    int bz = blockIdx.z;
    int b = bz / 3, t = bz % 3;
    const float* Wt = (t == 0) ? g_wap : (t == 1) ? g_wbd : g_wrs;
    int m0 = blockIdx.y * 128, n0 = blockIdx.x * 64;
    int colbase = t * D3 + n0;

    __shared__ float As[16][136];
    __shared__ float Bs[16][72];
    int tid = threadIdx.x;
    int lane = tid & 31, warp = tid >> 5;
    int wm = warp & 3, wn = warp >> 2;
    int gid = lane >> 2, tig = lane & 3;

    float c[2][4][4];
    #pragma unroll
    for (int mt = 0; mt < 2; mt++)
        #pragma unroll
        for (int nt = 0; nt < 4; nt++)
            #pragma unroll
            for (int e = 0; e < 4; e++) c[mt][nt][e] = 0.f;

    int ra = tid >> 2, ka = (tid & 3) * 4;
    int sw = 8 * (tid & 3);
    int kb = tid >> 4;
    int nb = (tid & 15) * 4;
    int swb = 8 * (kb >> 2);

    int kmax = m0 + 128;

    #pragma unroll
    for (int p = 0; p < 2; p++) {
        const float* Am = p ? Wt : g_ws;
        const float* Bm = p ? g_ABR : g_V;
        const float* dscale = g_invden + (p ? (t+1)*BS : 0) + b*Ss;
        float sc0 = dscale[m0 + ra];
        float sc1 = dscale[m0 + ra + 64];
        const float* ap0 = Am + (size_t)(b*Ss + m0 + ra) * Ss + ka;
        const float* ap1 = Am + (size_t)(b*Ss + m0 + ra + 64) * Ss + ka;

        for (int k0 = 0; k0 < kmax; k0 += 16) {
            float4 av0 = *(const float4*)(ap0 + k0);
            float4 av1 = *(const float4*)(ap1 + k0);
            float4 bv  = *(const float4*)(Bm + (size_t)(b*Ss + k0 + kb) * Dd + colbase + nb);
            __syncthreads();
            int ca = ra ^ sw, ca1 = (ra + 64) ^ sw;
            As[ka+0][ca]  = f2tf32(av0.x * sc0); As[ka+1][ca]  = f2tf32(av0.y * sc0);
            As[ka+2][ca]  = f2tf32(av0.z * sc0); As[ka+3][ca]  = f2tf32(av0.w * sc0);
            As[ka+0][ca1] = f2tf32(av1.x * sc1); As[ka+1][ca1] = f2tf32(av1.y * sc1);
            As[ka+2][ca1] = f2tf32(av1.z * sc1); As[ka+3][ca1] = f2tf32(av1.w * sc1);
            Bs[kb][(nb+0) ^ swb] = f2tf32(bv.x);
            Bs[kb][(nb+1) ^ swb] = f2tf32(bv.y);
            Bs[kb][(nb+2) ^ swb] = f2tf32(bv.z);
            Bs[kb][(nb+3) ^ swb] = f2tf32(bv.w);
            __syncthreads();
            #pragma unroll
            for (int ks = 0; ks < 16; ks += 8) {
                int swl = 8 * (ks >> 2), swh = swl + 8;
                int klo = ks + tig, khi = ks + tig + 4;
                unsigned a[2][4], bfr[4][2];
                #pragma unroll
                for (int mt = 0; mt < 2; mt++) {
                    int mr = wm*32 + mt*16 + gid;
                    a[mt][0] = __float_as_uint(As[klo][ mr      ^ swl]);
                    a[mt][1] = __float_as_uint(As[klo][(mr + 8) ^ swl]);
                    a[mt][2] = __float_as_uint(As[khi][ mr      ^ swh]);
                    a[mt][3] = __float_as_uint(As[khi][(mr + 8) ^ swh]);
                }
                #pragma unroll
                for (int nt = 0; nt < 4; nt++) {
                    int nc = wn*32 + nt*8 + gid;
                    bfr[nt][0] = __float_as_uint(Bs[klo][nc ^ swl]);
                    bfr[nt][1] = __float_as_uint(Bs[khi][nc ^ swh]);
                }
                #pragma unroll
                for (int mt = 0; mt < 2; mt++)
                    #pragma unroll
                    for (int nt = 0; nt < 4; nt++)
                        mma_tf32(c[mt][nt], a[mt], bfr[nt]);
            }
        }
        __syncthreads();
    }
    #pragma unroll
    for (int mt = 0; mt < 2; mt++) {
        int r0 = b*Ss + m0 + wm*32 + mt*16 + gid;
        #pragma unroll
        for (int nt = 0; nt < 4; nt++) {
            int cc = colbase + wn*32 + nt*8 + tig*2;
            *(float2*)(g_comb + (size_t)r0 * Dd + cc)     = make_float2(c[mt][nt][0], c[mt][nt][1]);
            *(float2*)(g_comb + (size_t)(r0+8) * Dd + cc) = make_float2(c[mt][nt][2], c[mt][nt][3]);
        }
    }
}

// ---------------- merged setup: block0 = emb2 prep, blocks 1..64 = gate means ----------------
__global__ __launch_bounds__(256)
void setup_kernel(const float* __restrict__ vemb, const float* __restrict__ spec,
                  const float* __restrict__ Wspec, const float* __restrict__ adj,
                  const float* __restrict__ vg)
{
    int tid = threadIdx.x;
    if (blockIdx.x == 0) {
        __shared__ float eb[NV*DV];
        __shared__ float adj_s[NV*NV];
        for (int t = tid; t < NV*DV; t += 256) {
            int u = t / DV, d = t % DV;
            float s = vemb[t];
            #pragma unroll
            for (int h = 0; h < 6; h++) s += 0.1f * spec[u*6+h] * Wspec[d*6+h];
            eb[t] = s;
        }
        for (int t = tid; t < NV*NV; t += 256) adj_s[t] = adj[t];
        __syncthreads();
        for (int t = tid; t < NV*DV; t += 256) {
            int v = t / DV, d = t % DV;
            float s = eb[t];
            #pragma unroll 8
            for (int u = 0; u < NV; u++) s += 0.1f * adj_s[u*NV + v] * eb[u*DV + d];
            g_emb2[t] = s;
        }
    } else {
        int v = blockIdx.x - 1;
        float s = 0.f;
        for (int c = tid; c < Dd; c += 256) {
            float x = vg[(size_t)v*Dd + c];
            s += 1.f / (1.f + __expf(-x));
        }
        __shared__ float red[256];
        red[tid] = s; __syncthreads();
        for (int off = 128; off; off >>= 1) {
            if (tid < off) red[tid] += red[tid + off];
            __syncthreads();
        }
        if (tid == 0) g_gm[v] = red[0] * (1.f / Dd);
    }
}

// ---------------- attention via TF32 mma: S = K(256x32) @ F(64x32)^T ----------------
__global__ __launch_bounds__(256)
void attn_mma(float* __restrict__ pi_out)
{
    int j0 = blockIdx.x * 256, i = blockIdx.y, b = blockIdx.z;
    int row_g = b*Ss + i;
    size_t rowbase = (size_t)row_g * Ss;
    int tid = threadIdx.x;

    if (j0 > i) {
        float4 z = make_float4(0.f,0.f,0.f,0.f);
        float4* base = (float4*)(pi_out + (rowbase + j0) * NV);
        for (int t = tid; t < 4096; t += 256) base[t] = z;
        size_t p = rowbase + j0 + tid;
        g_ws[p] = 0.f; g_wap[p] = 0.f; g_wbd[p] = 0.f; g_wrs[p] = 0.f;
        if (tid < 4) g_rowpart[(blockIdx.x*4 + tid)*BS + row_g] = 0.f;
        return;
    }

    __shared__ float Ks[256][36];
    __shared__ float Fs[32][72];
    __shared__ float q_s[DV];
    __shared__ float gm_s[NV];
    __shared__ float wred[8][4];

    if (tid < DV) q_s[tid] = g_QK[(size_t)row_g*64 + tid];
    if (tid >= 64 && tid < 128) gm_s[tid-64] = g_gm[tid-64];
    __syncthreads();
    for (int t = tid; t < 2048; t += 256) {
        int d = t >> 6, v = t & 63;
        Fs[d][v] = f2tf32(q_s[d] * g_emb2[v*DV + d]);
    }
    for (int t = tid; t < 2048; t += 256) {
        int r = t >> 3, q = t & 7;
        float4 kv = *(const float4*)(g_QK + (size_t)(b*Ss + j0 + r)*64 + 32 + q*4);
        Ks[r][q*4+0] = f2tf32(kv.x); Ks[r][q*4+1] = f2tf32(kv.y);
        Ks[r][q*4+2] = f2tf32(kv.z); Ks[r][q*4+3] = f2tf32(kv.w);
    }
    __syncthreads();

    int warp = tid >> 5, lane = tid & 31;
    int gid = lane >> 2, tig = lane & 3;

    float c[2][8][4];
    #pragma unroll
    for (int mt = 0; mt < 2; mt++)
        #pragma unroll
        for (int nt = 0; nt < 8; nt++)
            #pragma unroll
            for (int e = 0; e < 4; e++) c[mt][nt][e] = 0.f;

    #pragma unroll
    for (int ks = 0; ks < 32; ks += 8) {
        unsigned a[2][4], bf[8][2];
        #pragma unroll
        for (int mt = 0; mt < 2; mt++) {
            int mr = warp*32 + mt*16 + gid;
            a[mt][0] = __float_as_uint(Ks[mr  ][ks+tig]);
            a[mt][1] = __float_as_uint(Ks[mr+8][ks+tig]);
            a[mt][2] = __float_as_uint(Ks[mr  ][ks+tig+4]);
            a[mt][3] = __float_as_uint(Ks[mr+8][ks+tig+4]);
        }
        #pragma unroll
        for (int nt = 0; nt < 8; nt++) {
            int nc = nt*8 + gid;
            bf[nt][0] = __float_as_uint(Fs[ks+tig  ][nc]);
            bf[nt][1] = __float_as_uint(Fs[ks+tig+4][nc]);
        }
        #pragma unroll
        for (int mt = 0; mt < 2; mt++)
            #pragma unroll
            for (int nt = 0; nt < 8; nt++)
                mma_tf32(c[mt][nt], a[mt], bf[nt]);
    }

    float gmr[16];
    #pragma unroll
    for (int nt = 0; nt < 8; nt++) {
        gmr[nt*2]   = gm_s[nt*8 + tig*2];
        gmr[nt*2+1] = gm_s[nt*8 + tig*2 + 1];
    }

    float bws = 0.f, bap = 0.f, bbd = 0.f, brs = 0.f;
    #pragma unroll
    for (int mt = 0; mt < 2; mt++)
    #pragma unroll
    for (int rh = 0; rh < 2; rh++) {
        int j = j0 + warp*32 + mt*16 + rh*8 + gid;
        size_t pair = rowbase + j;
        float e[16];
        float mx = -1e30f;
        #pragma unroll
        for (int nt = 0; nt < 8; nt++) {
            e[nt*2]   = c[mt][nt][rh*2];
            e[nt*2+1] = c[mt][nt][rh*2+1];
            mx = fmaxf(mx, fmaxf(e[nt*2], e[nt*2+1]));
        }
        mx = fmaxf(mx, __shfl_xor_sync(0xffffffffu, mx, 1));
        mx = fmaxf(mx, __shfl_xor_sync(0xffffffffu, mx, 2));
        float sum = 0.f, sg = 0.f, sap = 0.f;
        #pragma unroll
        for (int q = 0; q < 16; q++) {
            float ev = __expf(e[q] - mx);
            e[q] = ev;
            sum += ev;
            sg = fmaf(ev, gmr[q], sg);
            if (q & 1) sap += ev;
        }
        float sbd = (tig & 1) ? sum : 0.f;
        float srs = (tig & 2) ? sum : 0.f;
        sum += __shfl_xor_sync(0xffffffffu, sum, 1);
        sum += __shfl_xor_sync(0xffffffffu, sum, 2);
        sg  += __shfl_xor_sync(0xffffffffu, sg , 1);
        sg  += __shfl_xor_sync(0xffffffffu, sg , 2);
        sap += __shfl_xor_sync(0xffffffffu, sap, 1);
        sap += __shfl_xor_sync(0xffffffffu, sap, 2);
        sbd += __shfl_xor_sync(0xffffffffu, sbd, 1);
        sbd += __shfl_xor_sync(0xffffffffu, sbd, 2);
        srs += __shfl_xor_sync(0xffffffffu, srs, 1);
        srs += __shfl_xor_sync(0xffffffffu, srs, 2);

        float* po = pi_out + pair*NV + tig*2;
        if (j > i) {
            float2 z = make_float2(0.f, 0.f);
            #pragma unroll
            for (int nt = 0; nt < 8; nt++) *(float2*)(po + nt*8) = z;
            if (tig == 0) {
                g_ws[pair] = 0.f; g_wap[pair] = 0.f;
                g_wbd[pair] = 0.f; g_wrs[pair] = 0.f;
            }
        } else {
            float inv = 1.f / sum;
            #pragma unroll
            for (int nt = 0; nt < 8; nt++)
                *(float2*)(po + nt*8) = make_float2(e[nt*2]*inv, e[nt*2+1]*inv);
            if (tig == 0) {
                float ws = sg*inv, ap = sap*inv, bd = sbd*inv, rs = srs*inv;
                g_ws[pair] = ws; g_wap[pair] = ap; g_wbd[pair] = bd; g_wrs[pair] = rs;
                bws += ws; bap += ap; bbd += bd; brs += rs;
            }
        }
    }
    #pragma unroll
    for (int off = 16; off; off >>= 1) {
        bws += __shfl_xor_sync(0xffffffffu, bws, off);
        bap += __shfl_xor_sync(0xffffffffu, bap, off);
        bbd += __shfl_xor_sync(0xffffffffu, bbd, off);
        brs += __shfl_xor_sync(0xffffffffu, brs, off);
    }
    if (lane == 0) {
        wred[warp][0] = bws; wred[warp][1] = bap;
        wred[warp][2] = bbd; wred[warp][3] = brs;
    }
    __syncthreads();
    if (tid < 4) {
        float s = 0.f;
        #pragma unroll
        for (int w = 0; w < 8; w++) s += wred[w][tid];
        g_rowpart[(blockIdx.x*4 + tid)*BS + row_g] = s;
    }
}

// ---------------- invden from 4 partials per row ----------------
__global__ void invden_kernel()
{
    int row = blockIdx.x * 256 + threadIdx.x;
    float s[4];
    #pragma unroll
    for (int q = 0; q < 4; q++) {
        float acc = 0.f;
        #pragma unroll
        for (int jb = 0; jb < 4; jb++) acc += g_rowpart[(jb*4 + q)*BS + row];
        s[q] = acc;
    }
    g_invden[row] = 1.f / (s[0] + EPSV);
    #pragma unroll
    for (int q = 1; q < 4; q++) {
        float S1 = s[q], d1 = S1 + EPSV, S2 = S1 / d1;
        g_invden[q*BS + row] = 1.f / (d1 * (S2 + EPSV));
    }
}

// ---------------- layernorm ----------------
__global__ void ln_kernel(const float* __restrict__ bo, const float* __restrict__ gamma,
                          const float* __restrict__ beta, float* __restrict__ out)
{
    int row = blockIdx.x, tid = threadIdx.x;
    const float* r = g_res + (size_t)row * Dd;
    float v[3];
    float s = 0.f;
    #pragma unroll
    for (int q = 0; q < 3; q++) { int c = tid + q*256; v[q] = r[c] + bo[c]; s += v[q]; }
    __shared__ float red[256];
    __shared__ float mu_s, inv_s;
    red[tid] = s; __syncthreads();
    for (int off = 128; off; off >>= 1) {
        if (tid < off) red[tid] += red[tid + off];
        __syncthreads();
    }
    if (tid == 0) mu_s = red[0] * (1.f / Dd);
    __syncthreads();
    float mu = mu_s;
    float s2 = 0.f;
    #pragma unroll
    for (int q = 0; q < 3; q++) { float d = v[q] - mu; s2 += d*d; }
    __syncthreads();
    red[tid] = s2; __syncthreads();
    for (int off = 128; off; off >>= 1) {
        if (tid < off) red[tid] += red[tid + off];
        __syncthreads();
    }
    if (tid == 0) inv_s = rsqrtf(red[0] * (1.f / Dd) + LNEPS);
    __syncthreads();
    float inv = inv_s;
    #pragma unroll
    for (int q = 0; q < 3; q++) {
        int c = tid + q*256;
        out[(size_t)row*Dd + c] = (v[q] - mu) * inv * gamma[c] + beta[c];
    }
}

// ---------------- launch ----------------
extern "C" void kernel_launch(void* const* d_in, const int* in_sizes, int n_in,
                              void* d_out, int out_size)
{
    const float* x      = (const float*)d_in[0];
    const float* Wq     = (const float*)d_in[2];
    const float* Wk     = (const float*)d_in[3];
    const float* vemb   = (const float*)d_in[4];
    const float* vgates = (const float*)d_in[5];
    const float* Wv     = (const float*)d_in[6];
    const float* Wspec  = (const float*)d_in[7];
    const float* Wa     = (const float*)d_in[8];
    const float* Wb     = (const float*)d_in[9];
    const float* Wr     = (const float*)d_in[10];
    const float* Wo     = (const float*)d_in[11];
    const float* bo     = (const float*)d_in[12];
    const float* gamma  = (const float*)d_in[13];
    const float* beta   = (const float*)d_in[14];
    const float* adj    = (const float*)d_in[15];
    const float* spec   = (const float*)d_in[16];

    float* out    = (float*)d_out;
    float* pi_out = out + NORMED_ELEMS;

    float *pQK, *pV, *pABR, *pComb, *pRes;
    cudaGetSymbolAddress((void**)&pQK,   g_QK);
    cudaGetSymbolAddress((void**)&pV,    g_V);
    cudaGetSymbolAddress((void**)&pABR,  g_ABR);
    cudaGetSymbolAddress((void**)&pComb, g_comb);
    cudaGetSymbolAddress((void**)&pRes,  g_res);

    dim3 thr(256);
    const int BIG = 1 << 30;
    setup_kernel<<<65, thr>>>(vemb, spec, Wspec, adj, vgates);
    gemm_tc<<<dim3( 1, 16), thr>>>(x, Wq, Wk, Wk, 32, BIG, pQK, 64);
    gemm_tc<<<dim3(12, 16), thr>>>(x, Wv, Wv, Wv, BIG, BIG, pV, Dd);
    gemm_tc<<<dim3(12, 16), thr>>>(x, Wa, Wb, Wr, 256, 512, pABR, Dd);

    attn_mma<<<dim3(4, Ss, Bb), thr>>>(pi_out);
    invden_kernel<<<8, thr>>>();
    combine_tc<<<dim3(4, 8, 6), thr>>>();

    gemm_tc<<<dim3(12, 16), thr>>>(pComb, Wo, Wo, Wo, BIG, BIG, pRes, Dd);
    ln_kernel<<<BS, 256>>>(bo, gamma, beta, out);
}

// round 6
// speedup vs baseline: 3.3207x; 1.1573x over previous
#include <cuda_runtime.h>

#define Bb 2
#define Ss 1024
#define Dd 768
#define DV 32
#define NV 64
#define D3 256
#define BS (Bb*Ss)
#define Kd 768
#define EPSV 1e-8f
#define LNEPS 1e-5f
#define NORMED_ELEMS ((size_t)Bb*Ss*Dd)

// ---------------- scratch ----------------
__device__ float g_QK[BS*64];            // cols 0-31 = Q, 32-63 = K
__device__ float g_V[BS*Dd];
__device__ float g_ABR[BS*Dd];
__device__ float g_emb2[NV*DV];
__device__ float g_gm[NV];
__device__ float g_ws [(size_t)BS*Ss];
__device__ float g_wap[(size_t)BS*Ss];
__device__ float g_wbd[(size_t)BS*Ss];
__device__ float g_wrs[(size_t)BS*Ss];
__device__ float g_rowpart[16*BS];
__device__ float g_invden[4*BS];
__device__ float g_comb[BS*Dd];
__device__ float g_res[BS*Dd];

// ---------------- tf32 helpers ----------------
__device__ __forceinline__ float f2tf32(float f) {
    unsigned r;
    asm("cvt.rna.tf32.f32 %0, %1;" : "=r"(r) : "f"(f));
    return __uint_as_float(r);
}
__device__ __forceinline__ void mma_tf32(float* c, const unsigned* a, const unsigned* b) {
    asm volatile("mma.sync.aligned.m16n8k8.row.col.f32.tf32.tf32.f32 "
                 "{%0,%1,%2,%3}, {%4,%5,%6,%7}, {%8,%9}, {%0,%1,%2,%3};"
                 : "+f"(c[0]), "+f"(c[1]), "+f"(c[2]), "+f"(c[3])
                 : "r"(a[0]), "r"(a[1]), "r"(a[2]), "r"(a[3]), "r"(b[0]), "r"(b[1]));
}

// ======== fused projection GEMM: [QK | V | ABR] = X @ W^T, pipelined ========
__global__ __launch_bounds__(256)
void gemm_fused(const float* __restrict__ X,
                const float* __restrict__ Wq, const float* __restrict__ Wk,
                const float* __restrict__ Wv, const float* __restrict__ Wa,
                const float* __restrict__ Wb, const float* __restrict__ Wr,
                float* __restrict__ Cqk, float* __restrict__ Cv, float* __restrict__ Cabr)
{
    __shared__ float As[2][16][136];
    __shared__ float Bs[2][16][72];
    int tid = threadIdx.x;
    int lane = tid & 31, warp = tid >> 5;
    int wm = warp & 3, wn = warp >> 2;
    int gid = lane >> 2, tig = lane & 3;
    int m0 = blockIdx.y * 128, n0 = blockIdx.x * 64;

    float c[2][4][4];
    #pragma unroll
    for (int mt = 0; mt < 2; mt++)
        #pragma unroll
        for (int nt = 0; nt < 4; nt++)
            #pragma unroll
            for (int e = 0; e < 4; e++) c[mt][nt][e] = 0.f;

    int ra = tid >> 2;
    int ka = (tid & 3) * 4;
    int sw = 8 * (tid & 3);
    const float* xp0 = X + (size_t)(m0 + ra) * Kd + ka;
    const float* xp1 = X + (size_t)(m0 + ra + 64) * Kd + ka;
    int rW = n0 + ra;
    const float* wp;
    if      (rW <   32) wp = Wq + (size_t)rW * Kd;
    else if (rW <   64) wp = Wk + (size_t)(rW -   32) * Kd;
    else if (rW <  832) wp = Wv + (size_t)(rW -   64) * Kd;
    else if (rW < 1088) wp = Wa + (size_t)(rW -  832) * Kd;
    else if (rW < 1344) wp = Wb + (size_t)(rW - 1088) * Kd;
    else                wp = Wr + (size_t)(rW - 1344) * Kd;
    wp += ka;

    int ca = ra ^ sw, ca1 = (ra + 64) ^ sw, cb = ca & 127;

    // prologue
    {
        float4 av0 = *(const float4*)(xp0);
        float4 av1 = *(const float4*)(xp1);
        float4 bv  = *(const float4*)(wp);
        As[0][ka+0][ca]  = f2tf32(av0.x); As[0][ka+1][ca]  = f2tf32(av0.y);
        As[0][ka+2][ca]  = f2tf32(av0.z); As[0][ka+3][ca]  = f2tf32(av0.w);
        As[0][ka+0][ca1] = f2tf32(av1.x); As[0][ka+1][ca1] = f2tf32(av1.y);
        As[0][ka+2][ca1] = f2tf32(av1.z); As[0][ka+3][ca1] = f2tf32(av1.w);
        Bs[0][ka+0][cb] = f2tf32(bv.x); Bs[0][ka+1][cb] = f2tf32(bv.y);
        Bs[0][ka+2][cb] = f2tf32(bv.z); Bs[0][ka+3][cb] = f2tf32(bv.w);
    }
    __syncthreads();

    const int NIT = Kd / 16;   // 48
    for (int it = 0; it < NIT; it++) {
        int cur = it & 1;
        float4 nav0, nav1, nbv;
        if (it + 1 < NIT) {
            int k0 = (it + 1) * 16;
            nav0 = *(const float4*)(xp0 + k0);
            nav1 = *(const float4*)(xp1 + k0);
            nbv  = *(const float4*)(wp  + k0);
        }
        #pragma unroll
        for (int ks = 0; ks < 16; ks += 8) {
            int swl = 8 * (ks >> 2), swh = swl + 8;
            int klo = ks + tig, khi = ks + tig + 4;
            unsigned a[2][4], b[4][2];
            #pragma unroll
            for (int mt = 0; mt < 2; mt++) {
                int mr = wm*32 + mt*16 + gid;
                a[mt][0] = __float_as_uint(As[cur][klo][ mr      ^ swl]);
                a[mt][1] = __float_as_uint(As[cur][klo][(mr + 8) ^ swl]);
                a[mt][2] = __float_as_uint(As[cur][khi][ mr      ^ swh]);
                a[mt][3] = __float_as_uint(As[cur][khi][(mr + 8) ^ swh]);
            }
            #pragma unroll
            for (int nt = 0; nt < 4; nt++) {
                int nc = wn*32 + nt*8 + gid;
                b[nt][0] = __float_as_uint(Bs[cur][klo][nc ^ swl]);
                b[nt][1] = __float_as_uint(Bs[cur][khi][nc ^ swh]);
            }
            #pragma unroll
            for (int mt = 0; mt < 2; mt++)
                #pragma unroll
                for (int nt = 0; nt < 4; nt++)
                    mma_tf32(c[mt][nt], a[mt], b[nt]);
        }
        if (it + 1 < NIT) {
            int nx = cur ^ 1;
            As[nx][ka+0][ca]  = f2tf32(nav0.x); As[nx][ka+1][ca]  = f2tf32(nav0.y);
            As[nx][ka+2][ca]  = f2tf32(nav0.z); As[nx][ka+3][ca]  = f2tf32(nav0.w);
            As[nx][ka+0][ca1] = f2tf32(nav1.x); As[nx][ka+1][ca1] = f2tf32(nav1.y);
            As[nx][ka+2][ca1] = f2tf32(nav1.z); As[nx][ka+3][ca1] = f2tf32(nav1.w);
            Bs[nx][ka+0][cb] = f2tf32(nbv.x); Bs[nx][ka+1][cb] = f2tf32(nbv.y);
            Bs[nx][ka+2][cb] = f2tf32(nbv.z); Bs[nx][ka+3][cb] = f2tf32(nbv.w);
        }
        __syncthreads();
    }

    float* Cd; int strideN, cbase;
    if (n0 == 0)       { Cd = Cqk;  strideN = 64;  cbase = 0; }
    else if (n0 < 832) { Cd = Cv;   strideN = Dd;  cbase = n0 - 64; }
    else               { Cd = Cabr; strideN = Dd;  cbase = n0 - 832; }

    #pragma unroll
    for (int mt = 0; mt < 2; mt++) {
        int r0 = m0 + wm*32 + mt*16 + gid;
        #pragma unroll
        for (int nt = 0; nt < 4; nt++) {
            int cc = cbase + wn*32 + nt*8 + tig*2;
            *(float2*)(Cd + (size_t)r0 * strideN + cc)     = make_float2(c[mt][nt][0], c[mt][nt][1]);
            *(float2*)(Cd + (size_t)(r0+8) * strideN + cc) = make_float2(c[mt][nt][2], c[mt][nt][3]);
        }
    }
}

// ======== generic pipelined TF32 GEMM (used for Wo) ========
__global__ __launch_bounds__(256)
void gemm_tc(const float* __restrict__ X, const float* __restrict__ W0,
             float* __restrict__ C, int N)
{
    __shared__ float As[2][16][136];
    __shared__ float Bs[2][16][72];
    int tid = threadIdx.x;
    int lane = tid & 31, warp = tid >> 5;
    int wm = warp & 3, wn = warp >> 2;
    int gid = lane >> 2, tig = lane & 3;
    int m0 = blockIdx.y * 128, n0 = blockIdx.x * 64;

    float c[2][4][4];
    #pragma unroll
    for (int mt = 0; mt < 2; mt++)
        #pragma unroll
        for (int nt = 0; nt < 4; nt++)
            #pragma unroll
            for (int e = 0; e < 4; e++) c[mt][nt][e] = 0.f;

    int ra = tid >> 2;
    int ka = (tid & 3) * 4;
    int sw = 8 * (tid & 3);
    const float* xp0 = X + (size_t)(m0 + ra) * Kd + ka;
    const float* xp1 = X + (size_t)(m0 + ra + 64) * Kd + ka;
    const float* wp  = W0 + (size_t)(n0 + ra) * Kd + ka;
    int ca = ra ^ sw, ca1 = (ra + 64) ^ sw, cb = ca & 127;

    {
        float4 av0 = *(const float4*)(xp0);
        float4 av1 = *(const float4*)(xp1);
        float4 bv  = *(const float4*)(wp);
        As[0][ka+0][ca]  = f2tf32(av0.x); As[0][ka+1][ca]  = f2tf32(av0.y);
        As[0][ka+2][ca]  = f2tf32(av0.z); As[0][ka+3][ca]  = f2tf32(av0.w);
        As[0][ka+0][ca1] = f2tf32(av1.x); As[0][ka+1][ca1] = f2tf32(av1.y);
        As[0][ka+2][ca1] = f2tf32(av1.z); As[0][ka+3][ca1] = f2tf32(av1.w);
        Bs[0][ka+0][cb] = f2tf32(bv.x); Bs[0][ka+1][cb] = f2tf32(bv.y);
        Bs[0][ka+2][cb] = f2tf32(bv.z); Bs[0][ka+3][cb] = f2tf32(bv.w);
    }
    __syncthreads();

    const int NIT = Kd / 16;
    for (int it = 0; it < NIT; it++) {
        int cur = it & 1;
        float4 nav0, nav1, nbv;
        if (it + 1 < NIT) {
            int k0 = (it + 1) * 16;
            nav0 = *(const float4*)(xp0 + k0);
            nav1 = *(const float4*)(xp1 + k0);
            nbv  = *(const float4*)(wp  + k0);
        }
        #pragma unroll
        for (int ks = 0; ks < 16; ks += 8) {
            int swl = 8 * (ks >> 2), swh = swl + 8;
            int klo = ks + tig, khi = ks + tig + 4;
            unsigned a[2][4], b[4][2];
            #pragma unroll
            for (int mt = 0; mt < 2; mt++) {
                int mr = wm*32 + mt*16 + gid;
                a[mt][0] = __float_as_uint(As[cur][klo][ mr      ^ swl]);
                a[mt][1] = __float_as_uint(As[cur][klo][(mr + 8) ^ swl]);
                a[mt][2] = __float_as_uint(As[cur][khi][ mr      ^ swh]);
                a[mt][3] = __float_as_uint(As[cur][khi][(mr + 8) ^ swh]);
            }
            #pragma unroll
            for (int nt = 0; nt < 4; nt++) {
                int nc = wn*32 + nt*8 + gid;
                b[nt][0] = __float_as_uint(Bs[cur][klo][nc ^ swl]);
                b[nt][1] = __float_as_uint(Bs[cur][khi][nc ^ swh]);
            }
            #pragma unroll
            for (int mt = 0; mt < 2; mt++)
                #pragma unroll
                for (int nt = 0; nt < 4; nt++)
                    mma_tf32(c[mt][nt], a[mt], b[nt]);
        }
        if (it + 1 < NIT) {
            int nx = cur ^ 1;
            As[nx][ka+0][ca]  = f2tf32(nav0.x); As[nx][ka+1][ca]  = f2tf32(nav0.y);
            As[nx][ka+2][ca]  = f2tf32(nav0.z); As[nx][ka+3][ca]  = f2tf32(nav0.w);
            As[nx][ka+0][ca1] = f2tf32(nav1.x); As[nx][ka+1][ca1] = f2tf32(nav1.y);
            As[nx][ka+2][ca1] = f2tf32(nav1.z); As[nx][ka+3][ca1] = f2tf32(nav1.w);
            Bs[nx][ka+0][cb] = f2tf32(nbv.x); Bs[nx][ka+1][cb] = f2tf32(nbv.y);
            Bs[nx][ka+2][cb] = f2tf32(nbv.z); Bs[nx][ka+3][cb] = f2tf32(nbv.w);
        }
        __syncthreads();
    }
    #pragma unroll
    for (int mt = 0; mt < 2; mt++) {
        int r0 = m0 + wm*32 + mt*16 + gid;
        #pragma unroll
        for (int nt = 0; nt < 4; nt++) {
            int cc = n0 + wn*32 + nt*8 + tig*2;
            *(float2*)(C + (size_t)r0 * N + cc)     = make_float2(c[mt][nt][0], c[mt][nt][1]);
            *(float2*)(C + (size_t)(r0+8) * N + cc) = make_float2(c[mt][nt][2], c[mt][nt][3]);
        }
    }
}

// ======== TF32 combine (pipelined): comb = (is*ws)@Vslice + (it*wt)@Tslice ========
__global__ __launch_bounds__(256)
void combine_tc()
{
    int bz = blockIdx.z;
    int b = bz / 3, t = bz % 3;
    const float* Wt = (t == 0) ? g_wap : (t == 1) ? g_wbd : g_wrs;
    int m0 = blockIdx.y * 128, n0 = blockIdx.x * 64;
    int colbase = t * D3 + n0;

    __shared__ float As[2][16][136];
    __shared__ float Bs[2][16][72];
    int tid = threadIdx.x;
    int lane = tid & 31, warp = tid >> 5;
    int wm = warp & 3, wn = warp >> 2;
    int gid = lane >> 2, tig = lane & 3;

    float c[2][4][4];
    #pragma unroll
    for (int mt = 0; mt < 2; mt++)
        #pragma unroll
        for (int nt = 0; nt < 4; nt++)
            #pragma unroll
            for (int e = 0; e < 4; e++) c[mt][nt][e] = 0.f;

    int ra = tid >> 2, ka = (tid & 3) * 4;
    int sw = 8 * (tid & 3);
    int kb = tid >> 4;
    int nb = (tid & 15) * 4;
    int swb = 8 * (kb >> 2);
    int ca = ra ^ sw, ca1 = (ra + 64) ^ sw;

    const int NIT = (m0 + 128) / 16;

    #pragma unroll
    for (int p = 0; p < 2; p++) {
        const float* Am = p ? Wt : g_ws;
        const float* Bm = p ? g_ABR : g_V;
        const float* dscale = g_invden + (p ? (t+1)*BS : 0) + b*Ss;
        float sc0 = dscale[m0 + ra];
        float sc1 = dscale[m0 + ra + 64];
        const float* ap0 = Am + (size_t)(b*Ss + m0 + ra) * Ss + ka;
        const float* ap1 = Am + (size_t)(b*Ss + m0 + ra + 64) * Ss + ka;
        const float* bp  = Bm + (size_t)(b*Ss + kb) * Dd + colbase + nb;

        {
            float4 av0 = *(const float4*)(ap0);
            float4 av1 = *(const float4*)(ap1);
            float4 bv  = *(const float4*)(bp);
            As[0][ka+0][ca]  = f2tf32(av0.x * sc0); As[0][ka+1][ca]  = f2tf32(av0.y * sc0);
            As[0][ka+2][ca]  = f2tf32(av0.z * sc0); As[0][ka+3][ca]  = f2tf32(av0.w * sc0);
            As[0][ka+0][ca1] = f2tf32(av1.x * sc1); As[0][ka+1][ca1] = f2tf32(av1.y * sc1);
            As[0][ka+2][ca1] = f2tf32(av1.z * sc1); As[0][ka+3][ca1] = f2tf32(av1.w * sc1);
            Bs[0][kb][(nb+0) ^ swb] = f2tf32(bv.x);
            Bs[0][kb][(nb+1) ^ swb] = f2tf32(bv.y);
            Bs[0][kb][(nb+2) ^ swb] = f2tf32(bv.z);
            Bs[0][kb][(nb+3) ^ swb] = f2tf32(bv.w);
        }
        __syncthreads();

        for (int it = 0; it < NIT; it++) {
            int cur = it & 1;
            float4 nav0, nav1, nbv;
            if (it + 1 < NIT) {
                int k0 = (it + 1) * 16;
                nav0 = *(const float4*)(ap0 + k0);
                nav1 = *(const float4*)(ap1 + k0);
                nbv  = *(const float4*)(bp + (size_t)k0 * Dd);
            }
            #pragma unroll
            for (int ks = 0; ks < 16; ks += 8) {
                int swl = 8 * (ks >> 2), swh = swl + 8;
                int klo = ks + tig, khi = ks + tig + 4;
                unsigned a[2][4], bfr[4][2];
                #pragma unroll
                for (int mt = 0; mt < 2; mt++) {
                    int mr = wm*32 + mt*16 + gid;
                    a[mt][0] = __float_as_uint(As[cur][klo][ mr      ^ swl]);
                    a[mt][1] = __float_as_uint(As[cur][klo][(mr + 8) ^ swl]);
                    a[mt][2] = __float_as_uint(As[cur][khi][ mr      ^ swh]);
                    a[mt][3] = __float_as_uint(As[cur][khi][(mr + 8) ^ swh]);
                }
                #pragma unroll
                for (int nt = 0; nt < 4; nt++) {
                    int nc = wn*32 + nt*8 + gid;
                    bfr[nt][0] = __float_as_uint(Bs[cur][klo][nc ^ swl]);
                    bfr[nt][1] = __float_as_uint(Bs[cur][khi][nc ^ swh]);
                }
                #pragma unroll
                for (int mt = 0; mt < 2; mt++)
                    #pragma unroll
                    for (int nt = 0; nt < 4; nt++)
                        mma_tf32(c[mt][nt], a[mt], bfr[nt]);
            }
            if (it + 1 < NIT) {
                int nx = cur ^ 1;
                As[nx][ka+0][ca]  = f2tf32(nav0.x * sc0); As[nx][ka+1][ca]  = f2tf32(nav0.y * sc0);
                As[nx][ka+2][ca]  = f2tf32(nav0.z * sc0); As[nx][ka+3][ca]  = f2tf32(nav0.w * sc0);
                As[nx][ka+0][ca1] = f2tf32(nav1.x * sc1); As[nx][ka+1][ca1] = f2tf32(nav1.y * sc1);
                As[nx][ka+2][ca1] = f2tf32(nav1.z * sc1); As[nx][ka+3][ca1] = f2tf32(nav1.w * sc1);
                Bs[nx][kb][(nb+0) ^ swb] = f2tf32(nbv.x);
                Bs[nx][kb][(nb+1) ^ swb] = f2tf32(nbv.y);
                Bs[nx][kb][(nb+2) ^ swb] = f2tf32(nbv.z);
                Bs[nx][kb][(nb+3) ^ swb] = f2tf32(nbv.w);
            }
            __syncthreads();
        }
    }
    #pragma unroll
    for (int mt = 0; mt < 2; mt++) {
        int r0 = b*Ss + m0 + wm*32 + mt*16 + gid;
        #pragma unroll
        for (int nt = 0; nt < 4; nt++) {
            int cc = colbase + wn*32 + nt*8 + tig*2;
            *(float2*)(g_comb + (size_t)r0 * Dd + cc)     = make_float2(c[mt][nt][0], c[mt][nt][1]);
            *(float2*)(g_comb + (size_t)(r0+8) * Dd + cc) = make_float2(c[mt][nt][2], c[mt][nt][3]);
        }
    }
}

// ---------------- merged setup ----------------
__global__ __launch_bounds__(256)
void setup_kernel(const float* __restrict__ vemb, const float* __restrict__ spec,
                  const float* __restrict__ Wspec, const float* __restrict__ adj,
                  const float* __restrict__ vg)
{
    int tid = threadIdx.x;
    if (blockIdx.x == 0) {
        __shared__ float eb[NV*DV];
        __shared__ float adj_s[NV*NV];
        for (int t = tid; t < NV*DV; t += 256) {
            int u = t / DV, d = t % DV;
            float s = vemb[t];
            #pragma unroll
            for (int h = 0; h < 6; h++) s += 0.1f * spec[u*6+h] * Wspec[d*6+h];
            eb[t] = s;
        }
        for (int t = tid; t < NV*NV; t += 256) adj_s[t] = adj[t];
        __syncthreads();
        for (int t = tid; t < NV*DV; t += 256) {
            int v = t / DV, d = t % DV;
            float s = eb[t];
            #pragma unroll 8
            for (int u = 0; u < NV; u++) s += 0.1f * adj_s[u*NV + v] * eb[u*DV + d];
            g_emb2[t] = s;
        }
    } else {
        int v = blockIdx.x - 1;
        float s = 0.f;
        for (int c = tid; c < Dd; c += 256) {
            float x = vg[(size_t)v*Dd + c];
            s += 1.f / (1.f + __expf(-x));
        }
        __shared__ float red[256];
        red[tid] = s; __syncthreads();
        for (int off = 128; off; off >>= 1) {
            if (tid < off) red[tid] += red[tid + off];
            __syncthreads();
        }
        if (tid == 0) g_gm[v] = red[0] * (1.f / Dd);
    }
}

// ---------------- attention via TF32 mma ----------------
__global__ __launch_bounds__(256)
void attn_mma(float* __restrict__ pi_out)
{
    int j0 = blockIdx.x * 256, i = blockIdx.y, b = blockIdx.z;
    int row_g = b*Ss + i;
    size_t rowbase = (size_t)row_g * Ss;
    int tid = threadIdx.x;

    if (j0 > i) {
        float4 z = make_float4(0.f,0.f,0.f,0.f);
        float4* base = (float4*)(pi_out + (rowbase + j0) * NV);
        for (int t = tid; t < 4096; t += 256) base[t] = z;
        size_t p = rowbase + j0 + tid;
        g_ws[p] = 0.f; g_wap[p] = 0.f; g_wbd[p] = 0.f; g_wrs[p] = 0.f;
        if (tid < 4) g_rowpart[(blockIdx.x*4 + tid)*BS + row_g] = 0.f;
        return;
    }

    __shared__ float Ks[256][36];
    __shared__ float Fs[32][72];
    __shared__ float q_s[DV];
    __shared__ float gm_s[NV];
    __shared__ float wred[8][4];

    if (tid < DV) q_s[tid] = g_QK[(size_t)row_g*64 + tid];
    if (tid >= 64 && tid < 128) gm_s[tid-64] = g_gm[tid-64];
    __syncthreads();
    for (int t = tid; t < 2048; t += 256) {
        int d = t >> 6, v = t & 63;
        Fs[d][v] = f2tf32(q_s[d] * g_emb2[v*DV + d]);
    }
    for (int t = tid; t < 2048; t += 256) {
        int r = t >> 3, q = t & 7;
        float4 kv = *(const float4*)(g_QK + (size_t)(b*Ss + j0 + r)*64 + 32 + q*4);
        Ks[r][q*4+0] = f2tf32(kv.x); Ks[r][q*4+1] = f2tf32(kv.y);
        Ks[r][q*4+2] = f2tf32(kv.z); Ks[r][q*4+3] = f2tf32(kv.w);
    }
    __syncthreads();

    int warp = tid >> 5, lane = tid & 31;
    int gid = lane >> 2, tig = lane & 3;

    float c[2][8][4];
    #pragma unroll
    for (int mt = 0; mt < 2; mt++)
        #pragma unroll
        for (int nt = 0; nt < 8; nt++)
            #pragma unroll
            for (int e = 0; e < 4; e++) c[mt][nt][e] = 0.f;

    #pragma unroll
    for (int ks = 0; ks < 32; ks += 8) {
        unsigned a[2][4], bf[8][2];
        #pragma unroll
        for (int mt = 0; mt < 2; mt++) {
            int mr = warp*32 + mt*16 + gid;
            a[mt][0] = __float_as_uint(Ks[mr  ][ks+tig]);
            a[mt][1] = __float_as_uint(Ks[mr+8][ks+tig]);
            a[mt][2] = __float_as_uint(Ks[mr  ][ks+tig+4]);
            a[mt][3] = __float_as_uint(Ks[mr+8][ks+tig+4]);
        }
        #pragma unroll
        for (int nt = 0; nt < 8; nt++) {
            int nc = nt*8 + gid;
            bf[nt][0] = __float_as_uint(Fs[ks+tig  ][nc]);
            bf[nt][1] = __float_as_uint(Fs[ks+tig+4][nc]);
        }
        #pragma unroll
        for (int mt = 0; mt < 2; mt++)
            #pragma unroll
            for (int nt = 0; nt < 8; nt++)
                mma_tf32(c[mt][nt], a[mt], bf[nt]);
    }

    float gmr[16];
    #pragma unroll
    for (int nt = 0; nt < 8; nt++) {
        gmr[nt*2]   = gm_s[nt*8 + tig*2];
        gmr[nt*2+1] = gm_s[nt*8 + tig*2 + 1];
    }

    float bws = 0.f, bap = 0.f, bbd = 0.f, brs = 0.f;
    #pragma unroll
    for (int mt = 0; mt < 2; mt++)
    #pragma unroll
    for (int rh = 0; rh < 2; rh++) {
        int j = j0 + warp*32 + mt*16 + rh*8 + gid;
        size_t pair = rowbase + j;
        float e[16];
        float mx = -1e30f;
        #pragma unroll
        for (int nt = 0; nt < 8; nt++) {
            e[nt*2]   = c[mt][nt][rh*2];
            e[nt*2+1] = c[mt][nt][rh*2+1];
            mx = fmaxf(mx, fmaxf(e[nt*2], e[nt*2+1]));
        }
        mx = fmaxf(mx, __shfl_xor_sync(0xffffffffu, mx, 1));
        mx = fmaxf(mx, __shfl_xor_sync(0xffffffffu, mx, 2));
        float sum = 0.f, sg = 0.f, sap = 0.f;
        #pragma unroll
        for (int q = 0; q < 16; q++) {
            float ev = __expf(e[q] - mx);
            e[q] = ev;
            sum += ev;
            sg = fmaf(ev, gmr[q], sg);
            if (q & 1) sap += ev;
        }
        float sbd = (tig & 1) ? sum : 0.f;
        float srs = (tig & 2) ? sum : 0.f;
        sum += __shfl_xor_sync(0xffffffffu, sum, 1);
        sum += __shfl_xor_sync(0xffffffffu, sum, 2);
        sg  += __shfl_xor_sync(0xffffffffu, sg , 1);
        sg  += __shfl_xor_sync(0xffffffffu, sg , 2);
        sap += __shfl_xor_sync(0xffffffffu, sap, 1);
        sap += __shfl_xor_sync(0xffffffffu, sap, 2);
        sbd += __shfl_xor_sync(0xffffffffu, sbd, 1);
        sbd += __shfl_xor_sync(0xffffffffu, sbd, 2);
        srs += __shfl_xor_sync(0xffffffffu, srs, 1);
        srs += __shfl_xor_sync(0xffffffffu, srs, 2);

        float* po = pi_out + pair*NV + tig*2;
        if (j > i) {
            float2 z = make_float2(0.f, 0.f);
            #pragma unroll
            for (int nt = 0; nt < 8; nt++) *(float2*)(po + nt*8) = z;
            if (tig == 0) {
                g_ws[pair] = 0.f; g_wap[pair] = 0.f;
                g_wbd[pair] = 0.f; g_wrs[pair] = 0.f;
            }
        } else {
            float inv = 1.f / sum;
            #pragma unroll
            for (int nt = 0; nt < 8; nt++)
                *(float2*)(po + nt*8) = make_float2(e[nt*2]*inv, e[nt*2+1]*inv);
            if (tig == 0) {
                float ws = sg*inv, ap = sap*inv, bd = sbd*inv, rs = srs*inv;
                g_ws[pair] = ws; g_wap[pair] = ap; g_wbd[pair] = bd; g_wrs[pair] = rs;
                bws += ws; bap += ap; bbd += bd; brs += rs;
            }
        }
    }
    #pragma unroll
    for (int off = 16; off; off >>= 1) {
        bws += __shfl_xor_sync(0xffffffffu, bws, off);
        bap += __shfl_xor_sync(0xffffffffu, bap, off);
        bbd += __shfl_xor_sync(0xffffffffu, bbd, off);
        brs += __shfl_xor_sync(0xffffffffu, brs, off);
    }
    if (lane == 0) {
        wred[warp][0] = bws; wred[warp][1] = bap;
        wred[warp][2] = bbd; wred[warp][3] = brs;
    }
    __syncthreads();
    if (tid < 4) {
        float s = 0.f;
        #pragma unroll
        for (int w = 0; w < 8; w++) s += wred[w][tid];
        g_rowpart[(blockIdx.x*4 + tid)*BS + row_g] = s;
    }
}

// ---------------- invden ----------------
__global__ void invden_kernel()
{
    int row = blockIdx.x * 256 + threadIdx.x;
    float s[4];
    #pragma unroll
    for (int q = 0; q < 4; q++) {
        float acc = 0.f;
        #pragma unroll
        for (int jb = 0; jb < 4; jb++) acc += g_rowpart[(jb*4 + q)*BS + row];
        s[q] = acc;
    }
    g_invden[row] = 1.f / (s[0] + EPSV);
    #pragma unroll
    for (int q = 1; q < 4; q++) {
        float S1 = s[q], d1 = S1 + EPSV, S2 = S1 / d1;
        g_invden[q*BS + row] = 1.f / (d1 * (S2 + EPSV));
    }
}

// ---------------- layernorm ----------------
__global__ void ln_kernel(const float* __restrict__ bo, const float* __restrict__ gamma,
                          const float* __restrict__ beta, float* __restrict__ out)
{
    int row = blockIdx.x, tid = threadIdx.x;
    const float* r = g_res + (size_t)row * Dd;
    float v[3];
    float s = 0.f;
    #pragma unroll
    for (int q = 0; q < 3; q++) { int c = tid + q*256; v[q] = r[c] + bo[c]; s += v[q]; }
    __shared__ float red[256];
    __shared__ float mu_s, inv_s;
    red[tid] = s; __syncthreads();
    for (int off = 128; off; off >>= 1) {
        if (tid < off) red[tid] += red[tid + off];
        __syncthreads();
    }
    if (tid == 0) mu_s = red[0] * (1.f / Dd);
    __syncthreads();
    float mu = mu_s;
    float s2 = 0.f;
    #pragma unroll
    for (int q = 0; q < 3; q++) { float d = v[q] - mu; s2 += d*d; }
    __syncthreads();
    red[tid] = s2; __syncthreads();
    for (int off = 128; off; off >>= 1) {
        if (tid < off) red[tid] += red[tid + off];
        __syncthreads();
    }
    if (tid == 0) inv_s = rsqrtf(red[0] * (1.f / Dd) + LNEPS);
    __syncthreads();
    float inv = inv_s;
    #pragma unroll
    for (int q = 0; q < 3; q++) {
        int c = tid + q*256;
        out[(size_t)row*Dd + c] = (v[q] - mu) * inv * gamma[c] + beta[c];
    }
}

// ---------------- launch ----------------
extern "C" void kernel_launch(void* const* d_in, const int* in_sizes, int n_in,
                              void* d_out, int out_size)
{
    const float* x      = (const float*)d_in[0];
    const float* Wq     = (const float*)d_in[2];
    const float* Wk     = (const float*)d_in[3];
    const float* vemb   = (const float*)d_in[4];
    const float* vgates = (const float*)d_in[5];
    const float* Wv     = (const float*)d_in[6];
    const float* Wspec  = (const float*)d_in[7];
    const float* Wa     = (const float*)d_in[8];
    const float* Wb     = (const float*)d_in[9];
    const float* Wr     = (const float*)d_in[10];
    const float* Wo     = (const float*)d_in[11];
    const float* bo     = (const float*)d_in[12];
    const float* gamma  = (const float*)d_in[13];
    const float* beta   = (const float*)d_in[14];
    const float* adj    = (const float*)d_in[15];
    const float* spec   = (const float*)d_in[16];

    float* out    = (float*)d_out;
    float* pi_out = out + NORMED_ELEMS;

    float *pQK, *pV, *pABR, *pComb, *pRes;
    cudaGetSymbolAddress((void**)&pQK,   g_QK);
    cudaGetSymbolAddress((void**)&pV,    g_V);
    cudaGetSymbolAddress((void**)&pABR,  g_ABR);
    cudaGetSymbolAddress((void**)&pComb, g_comb);
    cudaGetSymbolAddress((void**)&pRes,  g_res);

    dim3 thr(256);
    setup_kernel<<<65, thr>>>(vemb, spec, Wspec, adj, vgates);
    gemm_fused<<<dim3(25, 16), thr>>>(x, Wq, Wk, Wv, Wa, Wb, Wr, pQK, pV, pABR);

    attn_mma<<<dim3(4, Ss, Bb), thr>>>(pi_out);
    invden_kernel<<<8, thr>>>();
    combine_tc<<<dim3(4, 8, 6), thr>>>();

    gemm_tc<<<dim3(12, 16), thr>>>(pComb, Wo, pRes, Dd);
    ln_kernel<<<BS, 256>>>(bo, gamma, beta, out);
}

// round 7
// speedup vs baseline: 3.5248x; 1.0615x over previous
#include <cuda_runtime.h>

#define Bb 2
#define Ss 1024
#define Dd 768
#define DV 32
#define NV 64
#define D3 256
#define BS (Bb*Ss)
#define Kd 768
#define EPSV 1e-8f
#define LNEPS 1e-5f
#define NORMED_ELEMS ((size_t)Bb*Ss*Dd)

// ---------------- scratch ----------------
__device__ float g_QK[BS*64];            // cols 0-31 = Q, 32-63 = K
__device__ float g_V[BS*Dd];
__device__ float g_ABR[BS*Dd];
__device__ float g_emb2[NV*DV];
__device__ float g_gm[NV];
__device__ float g_ws [(size_t)BS*Ss];
__device__ float g_wap[(size_t)BS*Ss];
__device__ float g_wbd[(size_t)BS*Ss];
__device__ float g_wrs[(size_t)BS*Ss];
__device__ float g_invden[4*BS];
__device__ float g_comb[BS*Dd];
__device__ float g_res[BS*Dd];

// ---------------- tf32 helpers ----------------
__device__ __forceinline__ float f2tf32(float f) {
    unsigned r;
    asm("cvt.rna.tf32.f32 %0, %1;" : "=r"(r) : "f"(f));
    return __uint_as_float(r);
}
__device__ __forceinline__ void mma_tf32(float* c, const unsigned* a, const unsigned* b) {
    asm volatile("mma.sync.aligned.m16n8k8.row.col.f32.tf32.tf32.f32 "
                 "{%0,%1,%2,%3}, {%4,%5,%6,%7}, {%8,%9}, {%0,%1,%2,%3};"
                 : "+f"(c[0]), "+f"(c[1]), "+f"(c[2]), "+f"(c[3])
                 : "r"(a[0]), "r"(a[1]), "r"(a[2]), "r"(a[3]), "r"(b[0]), "r"(b[1]));
}

// ======== fused projection GEMM: [QK | V | ABR] = X @ W^T, pipelined ========
__global__ __launch_bounds__(256)
void gemm_fused(const float* __restrict__ X,
                const float* __restrict__ Wq, const float* __restrict__ Wk,
                const float* __restrict__ Wv, const float* __restrict__ Wa,
                const float* __restrict__ Wb, const float* __restrict__ Wr,
                float* __restrict__ Cqk, float* __restrict__ Cv, float* __restrict__ Cabr)
{
    __shared__ float As[2][16][136];
    __shared__ float Bs[2][16][72];
    int tid = threadIdx.x;
    int lane = tid & 31, warp = tid >> 5;
    int wm = warp & 3, wn = warp >> 2;
    int gid = lane >> 2, tig = lane & 3;
    int m0 = blockIdx.y * 128, n0 = blockIdx.x * 64;

    float c[2][4][4];
    #pragma unroll
    for (int mt = 0; mt < 2; mt++)
        #pragma unroll
        for (int nt = 0; nt < 4; nt++)
            #pragma unroll
            for (int e = 0; e < 4; e++) c[mt][nt][e] = 0.f;

    int ra = tid >> 2;
    int ka = (tid & 3) * 4;
    int sw = 8 * (tid & 3);
    const float* xp0 = X + (size_t)(m0 + ra) * Kd + ka;
    const float* xp1 = X + (size_t)(m0 + ra + 64) * Kd + ka;
    int rW = n0 + ra;
    const float* wp;
    if      (rW <   32) wp = Wq + (size_t)rW * Kd;
    else if (rW <   64) wp = Wk + (size_t)(rW -   32) * Kd;
    else if (rW <  832) wp = Wv + (size_t)(rW -   64) * Kd;
    else if (rW < 1088) wp = Wa + (size_t)(rW -  832) * Kd;
    else if (rW < 1344) wp = Wb + (size_t)(rW - 1088) * Kd;
    else                wp = Wr + (size_t)(rW - 1344) * Kd;
    wp += ka;

    int ca = ra ^ sw, ca1 = (ra + 64) ^ sw, cb = ca & 127;

    {
        float4 av0 = *(const float4*)(xp0);
        float4 av1 = *(const float4*)(xp1);
        float4 bv  = *(const float4*)(wp);
        As[0][ka+0][ca]  = f2tf32(av0.x); As[0][ka+1][ca]  = f2tf32(av0.y);
        As[0][ka+2][ca]  = f2tf32(av0.z); As[0][ka+3][ca]  = f2tf32(av0.w);
        As[0][ka+0][ca1] = f2tf32(av1.x); As[0][ka+1][ca1] = f2tf32(av1.y);
        As[0][ka+2][ca1] = f2tf32(av1.z); As[0][ka+3][ca1] = f2tf32(av1.w);
        Bs[0][ka+0][cb] = f2tf32(bv.x); Bs[0][ka+1][cb] = f2tf32(bv.y);
        Bs[0][ka+2][cb] = f2tf32(bv.z); Bs[0][ka+3][cb] = f2tf32(bv.w);
    }
    __syncthreads();

    const int NIT = Kd / 16;
    for (int it = 0; it < NIT; it++) {
        int cur = it & 1;
        float4 nav0, nav1, nbv;
        if (it + 1 < NIT) {
            int k0 = (it + 1) * 16;
            nav0 = *(const float4*)(xp0 + k0);
            nav1 = *(const float4*)(xp1 + k0);
            nbv  = *(const float4*)(wp  + k0);
        }
        #pragma unroll
        for (int ks = 0; ks < 16; ks += 8) {
            int swl = 8 * (ks >> 2), swh = swl + 8;
            int klo = ks + tig, khi = ks + tig + 4;
            unsigned a[2][4], b[4][2];
            #pragma unroll
            for (int mt = 0; mt < 2; mt++) {
                int mr = wm*32 + mt*16 + gid;
                a[mt][0] = __float_as_uint(As[cur][klo][ mr      ^ swl]);
                a[mt][1] = __float_as_uint(As[cur][klo][(mr + 8) ^ swl]);
                a[mt][2] = __float_as_uint(As[cur][khi][ mr      ^ swh]);
                a[mt][3] = __float_as_uint(As[cur][khi][(mr + 8) ^ swh]);
            }
            #pragma unroll
            for (int nt = 0; nt < 4; nt++) {
                int nc = wn*32 + nt*8 + gid;
                b[nt][0] = __float_as_uint(Bs[cur][klo][nc ^ swl]);
                b[nt][1] = __float_as_uint(Bs[cur][khi][nc ^ swh]);
            }
            #pragma unroll
            for (int mt = 0; mt < 2; mt++)
                #pragma unroll
                for (int nt = 0; nt < 4; nt++)
                    mma_tf32(c[mt][nt], a[mt], b[nt]);
        }
        if (it + 1 < NIT) {
            int nx = cur ^ 1;
            As[nx][ka+0][ca]  = f2tf32(nav0.x); As[nx][ka+1][ca]  = f2tf32(nav0.y);
            As[nx][ka+2][ca]  = f2tf32(nav0.z); As[nx][ka+3][ca]  = f2tf32(nav0.w);
            As[nx][ka+0][ca1] = f2tf32(nav1.x); As[nx][ka+1][ca1] = f2tf32(nav1.y);
            As[nx][ka+2][ca1] = f2tf32(nav1.z); As[nx][ka+3][ca1] = f2tf32(nav1.w);
            Bs[nx][ka+0][cb] = f2tf32(nbv.x); Bs[nx][ka+1][cb] = f2tf32(nbv.y);
            Bs[nx][ka+2][cb] = f2tf32(nbv.z); Bs[nx][ka+3][cb] = f2tf32(nbv.w);
        }
        __syncthreads();
    }

    float* Cd; int strideN, cbase;
    if (n0 == 0)       { Cd = Cqk;  strideN = 64;  cbase = 0; }
    else if (n0 < 832) { Cd = Cv;   strideN = Dd;  cbase = n0 - 64; }
    else               { Cd = Cabr; strideN = Dd;  cbase = n0 - 832; }

    #pragma unroll
    for (int mt = 0; mt < 2; mt++) {
        int r0 = m0 + wm*32 + mt*16 + gid;
        #pragma unroll
        for (int nt = 0; nt < 4; nt++) {
            int cc = cbase + wn*32 + nt*8 + tig*2;
            *(float2*)(Cd + (size_t)r0 * strideN + cc)     = make_float2(c[mt][nt][0], c[mt][nt][1]);
            *(float2*)(Cd + (size_t)(r0+8) * strideN + cc) = make_float2(c[mt][nt][2], c[mt][nt][3]);
        }
    }
}

// ======== generic pipelined TF32 GEMM (used for Wo) ========
__global__ __launch_bounds__(256)
void gemm_tc(const float* __restrict__ X, const float* __restrict__ W0,
             float* __restrict__ C, int N)
{
    __shared__ float As[2][16][136];
    __shared__ float Bs[2][16][72];
    int tid = threadIdx.x;
    int lane = tid & 31, warp = tid >> 5;
    int wm = warp & 3, wn = warp >> 2;
    int gid = lane >> 2, tig = lane & 3;
    int m0 = blockIdx.y * 128, n0 = blockIdx.x * 64;

    float c[2][4][4];
    #pragma unroll
    for (int mt = 0; mt < 2; mt++)
        #pragma unroll
        for (int nt = 0; nt < 4; nt++)
            #pragma unroll
            for (int e = 0; e < 4; e++) c[mt][nt][e] = 0.f;

    int ra = tid >> 2;
    int ka = (tid & 3) * 4;
    int sw = 8 * (tid & 3);
    const float* xp0 = X + (size_t)(m0 + ra) * Kd + ka;
    const float* xp1 = X + (size_t)(m0 + ra + 64) * Kd + ka;
    const float* wp  = W0 + (size_t)(n0 + ra) * Kd + ka;
    int ca = ra ^ sw, ca1 = (ra + 64) ^ sw, cb = ca & 127;

    {
        float4 av0 = *(const float4*)(xp0);
        float4 av1 = *(const float4*)(xp1);
        float4 bv  = *(const float4*)(wp);
        As[0][ka+0][ca]  = f2tf32(av0.x); As[0][ka+1][ca]  = f2tf32(av0.y);
        As[0][ka+2][ca]  = f2tf32(av0.z); As[0][ka+3][ca]  = f2tf32(av0.w);
        As[0][ka+0][ca1] = f2tf32(av1.x); As[0][ka+1][ca1] = f2tf32(av1.y);
        As[0][ka+2][ca1] = f2tf32(av1.z); As[0][ka+3][ca1] = f2tf32(av1.w);
        Bs[0][ka+0][cb] = f2tf32(bv.x); Bs[0][ka+1][cb] = f2tf32(bv.y);
        Bs[0][ka+2][cb] = f2tf32(bv.z); Bs[0][ka+3][cb] = f2tf32(bv.w);
    }
    __syncthreads();

    const int NIT = Kd / 16;
    for (int it = 0; it < NIT; it++) {
        int cur = it & 1;
        float4 nav0, nav1, nbv;
        if (it + 1 < NIT) {
            int k0 = (it + 1) * 16;
            nav0 = *(const float4*)(xp0 + k0);
            nav1 = *(const float4*)(xp1 + k0);
            nbv  = *(const float4*)(wp  + k0);
        }
        #pragma unroll
        for (int ks = 0; ks < 16; ks += 8) {
            int swl = 8 * (ks >> 2), swh = swl + 8;
            int klo = ks + tig, khi = ks + tig + 4;
            unsigned a[2][4], b[4][2];
            #pragma unroll
            for (int mt = 0; mt < 2; mt++) {
                int mr = wm*32 + mt*16 + gid;
                a[mt][0] = __float_as_uint(As[cur][klo][ mr      ^ swl]);
                a[mt][1] = __float_as_uint(As[cur][klo][(mr + 8) ^ swl]);
                a[mt][2] = __float_as_uint(As[cur][khi][ mr      ^ swh]);
                a[mt][3] = __float_as_uint(As[cur][khi][(mr + 8) ^ swh]);
            }
            #pragma unroll
            for (int nt = 0; nt < 4; nt++) {
                int nc = wn*32 + nt*8 + gid;
                b[nt][0] = __float_as_uint(Bs[cur][klo][nc ^ swl]);
                b[nt][1] = __float_as_uint(Bs[cur][khi][nc ^ swh]);
            }
            #pragma unroll
            for (int mt = 0; mt < 2; mt++)
                #pragma unroll
                for (int nt = 0; nt < 4; nt++)
                    mma_tf32(c[mt][nt], a[mt], b[nt]);
        }
        if (it + 1 < NIT) {
            int nx = cur ^ 1;
            As[nx][ka+0][ca]  = f2tf32(nav0.x); As[nx][ka+1][ca]  = f2tf32(nav0.y);
            As[nx][ka+2][ca]  = f2tf32(nav0.z); As[nx][ka+3][ca]  = f2tf32(nav0.w);
            As[nx][ka+0][ca1] = f2tf32(nav1.x); As[nx][ka+1][ca1] = f2tf32(nav1.y);
            As[nx][ka+2][ca1] = f2tf32(nav1.z); As[nx][ka+3][ca1] = f2tf32(nav1.w);
            Bs[nx][ka+0][cb] = f2tf32(nbv.x); Bs[nx][ka+1][cb] = f2tf32(nbv.y);
            Bs[nx][ka+2][cb] = f2tf32(nbv.z); Bs[nx][ka+3][cb] = f2tf32(nbv.w);
        }
        __syncthreads();
    }
    #pragma unroll
    for (int mt = 0; mt < 2; mt++) {
        int r0 = m0 + wm*32 + mt*16 + gid;
        #pragma unroll
        for (int nt = 0; nt < 4; nt++) {
            int cc = n0 + wn*32 + nt*8 + tig*2;
            *(float2*)(C + (size_t)r0 * N + cc)     = make_float2(c[mt][nt][0], c[mt][nt][1]);
            *(float2*)(C + (size_t)(r0+8) * N + cc) = make_float2(c[mt][nt][2], c[mt][nt][3]);
        }
    }
}

// ======== TF32 combine (pipelined) ========
__global__ __launch_bounds__(256)
void combine_tc()
{
    int bz = blockIdx.z;
    int b = bz / 3, t = bz % 3;
    const float* Wt = (t == 0) ? g_wap : (t == 1) ? g_wbd : g_wrs;
    int m0 = blockIdx.y * 128, n0 = blockIdx.x * 64;
    int colbase = t * D3 + n0;

    __shared__ float As[2][16][136];
    __shared__ float Bs[2][16][72];
    int tid = threadIdx.x;
    int lane = tid & 31, warp = tid >> 5;
    int wm = warp & 3, wn = warp >> 2;
    int gid = lane >> 2, tig = lane & 3;

    float c[2][4][4];
    #pragma unroll
    for (int mt = 0; mt < 2; mt++)
        #pragma unroll
        for (int nt = 0; nt < 4; nt++)
            #pragma unroll
            for (int e = 0; e < 4; e++) c[mt][nt][e] = 0.f;

    int ra = tid >> 2, ka = (tid & 3) * 4;
    int sw = 8 * (tid & 3);
    int kb = tid >> 4;
    int nb = (tid & 15) * 4;
    int swb = 8 * (kb >> 2);
    int ca = ra ^ sw, ca1 = (ra + 64) ^ sw;

    const int NIT = (m0 + 128) / 16;

    #pragma unroll
    for (int p = 0; p < 2; p++) {
        const float* Am = p ? Wt : g_ws;
        const float* Bm = p ? g_ABR : g_V;
        const float* dscale = g_invden + (p ? (t+1)*BS : 0) + b*Ss;
        float sc0 = dscale[m0 + ra];
        float sc1 = dscale[m0 + ra + 64];
        const float* ap0 = Am + (size_t)(b*Ss + m0 + ra) * Ss + ka;
        const float* ap1 = Am + (size_t)(b*Ss + m0 + ra + 64) * Ss + ka;
        const float* bp  = Bm + (size_t)(b*Ss + kb) * Dd + colbase + nb;

        {
            float4 av0 = *(const float4*)(ap0);
            float4 av1 = *(const float4*)(ap1);
            float4 bv  = *(const float4*)(bp);
            As[0][ka+0][ca]  = f2tf32(av0.x * sc0); As[0][ka+1][ca]  = f2tf32(av0.y * sc0);
            As[0][ka+2][ca]  = f2tf32(av0.z * sc0); As[0][ka+3][ca]  = f2tf32(av0.w * sc0);
            As[0][ka+0][ca1] = f2tf32(av1.x * sc1); As[0][ka+1][ca1] = f2tf32(av1.y * sc1);
            As[0][ka+2][ca1] = f2tf32(av1.z * sc1); As[0][ka+3][ca1] = f2tf32(av1.w * sc1);
            Bs[0][kb][(nb+0) ^ swb] = f2tf32(bv.x);
            Bs[0][kb][(nb+1) ^ swb] = f2tf32(bv.y);
            Bs[0][kb][(nb+2) ^ swb] = f2tf32(bv.z);
            Bs[0][kb][(nb+3) ^ swb] = f2tf32(bv.w);
        }
        __syncthreads();

        for (int it = 0; it < NIT; it++) {
            int cur = it & 1;
            float4 nav0, nav1, nbv;
            if (it + 1 < NIT) {
                int k0 = (it + 1) * 16;
                nav0 = *(const float4*)(ap0 + k0);
                nav1 = *(const float4*)(ap1 + k0);
                nbv  = *(const float4*)(bp + (size_t)k0 * Dd);
            }
            #pragma unroll
            for (int ks = 0; ks < 16; ks += 8) {
                int swl = 8 * (ks >> 2), swh = swl + 8;
                int klo = ks + tig, khi = ks + tig + 4;
                unsigned a[2][4], bfr[4][2];
                #pragma unroll
                for (int mt = 0; mt < 2; mt++) {
                    int mr = wm*32 + mt*16 + gid;
                    a[mt][0] = __float_as_uint(As[cur][klo][ mr      ^ swl]);
                    a[mt][1] = __float_as_uint(As[cur][klo][(mr + 8) ^ swl]);
                    a[mt][2] = __float_as_uint(As[cur][khi][ mr      ^ swh]);
                    a[mt][3] = __float_as_uint(As[cur][khi][(mr + 8) ^ swh]);
                }
                #pragma unroll
                for (int nt = 0; nt < 4; nt++) {
                    int nc = wn*32 + nt*8 + gid;
                    bfr[nt][0] = __float_as_uint(Bs[cur][klo][nc ^ swl]);
                    bfr[nt][1] = __float_as_uint(Bs[cur][khi][nc ^ swh]);
                }
                #pragma unroll
                for (int mt = 0; mt < 2; mt++)
                    #pragma unroll
                    for (int nt = 0; nt < 4; nt++)
                        mma_tf32(c[mt][nt], a[mt], bfr[nt]);
            }
            if (it + 1 < NIT) {
                int nx = cur ^ 1;
                As[nx][ka+0][ca]  = f2tf32(nav0.x * sc0); As[nx][ka+1][ca]  = f2tf32(nav0.y * sc0);
                As[nx][ka+2][ca]  = f2tf32(nav0.z * sc0); As[nx][ka+3][ca]  = f2tf32(nav0.w * sc0);
                As[nx][ka+0][ca1] = f2tf32(nav1.x * sc1); As[nx][ka+1][ca1] = f2tf32(nav1.y * sc1);
                As[nx][ka+2][ca1] = f2tf32(nav1.z * sc1); As[nx][ka+3][ca1] = f2tf32(nav1.w * sc1);
                Bs[nx][kb][(nb+0) ^ swb] = f2tf32(nbv.x);
                Bs[nx][kb][(nb+1) ^ swb] = f2tf32(nbv.y);
                Bs[nx][kb][(nb+2) ^ swb] = f2tf32(nbv.z);
                Bs[nx][kb][(nb+3) ^ swb] = f2tf32(nbv.w);
            }
            __syncthreads();
        }
    }
    #pragma unroll
    for (int mt = 0; mt < 2; mt++) {
        int r0 = b*Ss + m0 + wm*32 + mt*16 + gid;
        #pragma unroll
        for (int nt = 0; nt < 4; nt++) {
            int cc = colbase + wn*32 + nt*8 + tig*2;
            *(float2*)(g_comb + (size_t)r0 * Dd + cc)     = make_float2(c[mt][nt][0], c[mt][nt][1]);
            *(float2*)(g_comb + (size_t)(r0+8) * Dd + cc) = make_float2(c[mt][nt][2], c[mt][nt][3]);
        }
    }
}

// ---------------- merged setup ----------------
__global__ __launch_bounds__(256)
void setup_kernel(const float* __restrict__ vemb, const float* __restrict__ spec,
                  const float* __restrict__ Wspec, const float* __restrict__ adj,
                  const float* __restrict__ vg)
{
    int tid = threadIdx.x;
    if (blockIdx.x == 0) {
        __shared__ float eb[NV*DV];
        __shared__ float adj_s[NV*NV];
        for (int t = tid; t < NV*DV; t += 256) {
            int u = t / DV, d = t % DV;
            float s = vemb[t];
            #pragma unroll
            for (int h = 0; h < 6; h++) s += 0.1f * spec[u*6+h] * Wspec[d*6+h];
            eb[t] = s;
        }
        for (int t = tid; t < NV*NV; t += 256) adj_s[t] = adj[t];
        __syncthreads();
        for (int t = tid; t < NV*DV; t += 256) {
            int v = t / DV, d = t % DV;
            float s = eb[t];
            #pragma unroll 8
            for (int u = 0; u < NV; u++) s += 0.1f * adj_s[u*NV + v] * eb[u*DV + d];
            g_emb2[t] = s;
        }
    } else {
        int v = blockIdx.x - 1;
        float s = 0.f;
        for (int c = tid; c < Dd; c += 256) {
            float x = vg[(size_t)v*Dd + c];
            s += 1.f / (1.f + __expf(-x));
        }
        __shared__ float red[256];
        red[tid] = s; __syncthreads();
        for (int off = 128; off; off >>= 1) {
            if (tid < off) red[tid] += red[tid + off];
            __syncthreads();
        }
        if (tid == 0) g_gm[v] = red[0] * (1.f / Dd);
    }
}

// ---------------- row-persistent attention: one block per (b,i) ----------------
__global__ __launch_bounds__(256)
void attn_row(float* __restrict__ pi_out)
{
    int i = blockIdx.x, b = blockIdx.y;
    int row_g = b*Ss + i;
    size_t rowbase = (size_t)row_g * Ss;
    int tid = threadIdx.x;
    int warp = tid >> 5, lane = tid & 31;
    int gid = lane >> 2, tig = lane & 3;

    __shared__ float Ks[256][36];
    __shared__ float Fs[32][72];
    __shared__ float q_s[DV];
    __shared__ float gm_s[NV];
    __shared__ float wred[8][4];

    if (tid < DV) q_s[tid] = g_QK[(size_t)row_g*64 + tid];
    if (tid >= 64 && tid < 128) gm_s[tid-64] = g_gm[tid-64];
    __syncthreads();
    for (int t = tid; t < 2048; t += 256) {
        int d = t >> 6, v = t & 63;
        Fs[d][v] = f2tf32(q_s[d] * g_emb2[v*DV + d]);
    }

    float gmr[16];
    #pragma unroll
    for (int nt = 0; nt < 8; nt++) {
        gmr[nt*2]   = gm_s[nt*8 + tig*2];
        gmr[nt*2+1] = gm_s[nt*8 + tig*2 + 1];
    }

    float bws = 0.f, bap = 0.f, bbd = 0.f, brs = 0.f;
    int ntiles = (i >> 8) + 1;

    for (int jt = 0; jt < ntiles; jt++) {
        int j0 = jt * 256;
        __syncthreads();   // protect Ks reuse (mma of prev tile done; Fs written on jt==0)
        for (int t = tid; t < 2048; t += 256) {
            int r = t >> 3, q = t & 7;
            float4 kv = *(const float4*)(g_QK + (size_t)(b*Ss + j0 + r)*64 + 32 + q*4);
            Ks[r][q*4+0] = f2tf32(kv.x); Ks[r][q*4+1] = f2tf32(kv.y);
            Ks[r][q*4+2] = f2tf32(kv.z); Ks[r][q*4+3] = f2tf32(kv.w);
        }
        __syncthreads();

        float c[2][8][4];
        #pragma unroll
        for (int mt = 0; mt < 2; mt++)
            #pragma unroll
            for (int nt = 0; nt < 8; nt++)
                #pragma unroll
                for (int e = 0; e < 4; e++) c[mt][nt][e] = 0.f;

        #pragma unroll
        for (int ks = 0; ks < 32; ks += 8) {
            unsigned a[2][4], bf[8][2];
            #pragma unroll
            for (int mt = 0; mt < 2; mt++) {
                int mr = warp*32 + mt*16 + gid;
                a[mt][0] = __float_as_uint(Ks[mr  ][ks+tig]);
                a[mt][1] = __float_as_uint(Ks[mr+8][ks+tig]);
                a[mt][2] = __float_as_uint(Ks[mr  ][ks+tig+4]);
                a[mt][3] = __float_as_uint(Ks[mr+8][ks+tig+4]);
            }
            #pragma unroll
            for (int nt = 0; nt < 8; nt++) {
                int nc = nt*8 + gid;
                bf[nt][0] = __float_as_uint(Fs[ks+tig  ][nc]);
                bf[nt][1] = __float_as_uint(Fs[ks+tig+4][nc]);
            }
            #pragma unroll
            for (int mt = 0; mt < 2; mt++)
                #pragma unroll
                for (int nt = 0; nt < 8; nt++)
                    mma_tf32(c[mt][nt], a[mt], bf[nt]);
        }

        #pragma unroll
        for (int mt = 0; mt < 2; mt++)
        #pragma unroll
        for (int rh = 0; rh < 2; rh++) {
            int j = j0 + warp*32 + mt*16 + rh*8 + gid;
            size_t pair = rowbase + j;
            float e[16];
            float mx = -1e30f;
            #pragma unroll
            for (int nt = 0; nt < 8; nt++) {
                e[nt*2]   = c[mt][nt][rh*2];
                e[nt*2+1] = c[mt][nt][rh*2+1];
                mx = fmaxf(mx, fmaxf(e[nt*2], e[nt*2+1]));
            }
            mx = fmaxf(mx, __shfl_xor_sync(0xffffffffu, mx, 1));
            mx = fmaxf(mx, __shfl_xor_sync(0xffffffffu, mx, 2));
            float sum = 0.f, sg = 0.f, sap = 0.f;
            #pragma unroll
            for (int q = 0; q < 16; q++) {
                float ev = __expf(e[q] - mx);
                e[q] = ev;
                sum += ev;
                sg = fmaf(ev, gmr[q], sg);
                if (q & 1) sap += ev;
            }
            float sbd = (tig & 1) ? sum : 0.f;
            float srs = (tig & 2) ? sum : 0.f;
            sum += __shfl_xor_sync(0xffffffffu, sum, 1);
            sum += __shfl_xor_sync(0xffffffffu, sum, 2);
            sg  += __shfl_xor_sync(0xffffffffu, sg , 1);
            sg  += __shfl_xor_sync(0xffffffffu, sg , 2);
            sap += __shfl_xor_sync(0xffffffffu, sap, 1);
            sap += __shfl_xor_sync(0xffffffffu, sap, 2);
            sbd += __shfl_xor_sync(0xffffffffu, sbd, 1);
            sbd += __shfl_xor_sync(0xffffffffu, sbd, 2);
            srs += __shfl_xor_sync(0xffffffffu, srs, 1);
            srs += __shfl_xor_sync(0xffffffffu, srs, 2);

            float* po = pi_out + pair*NV + tig*2;
            if (j > i) {
                float2 z = make_float2(0.f, 0.f);
                #pragma unroll
                for (int nt = 0; nt < 8; nt++) __stcs((float2*)(po + nt*8), z);
                if (tig == 0) {
                    g_ws[pair] = 0.f; g_wap[pair] = 0.f;
                    g_wbd[pair] = 0.f; g_wrs[pair] = 0.f;
                }
            } else {
                float inv = 1.f / sum;
                #pragma unroll
                for (int nt = 0; nt < 8; nt++)
                    __stcs((float2*)(po + nt*8), make_float2(e[nt*2]*inv, e[nt*2+1]*inv));
                if (tig == 0) {
                    float ws = sg*inv, ap = sap*inv, bd = sbd*inv, rs = srs*inv;
                    g_ws[pair] = ws; g_wap[pair] = ap; g_wbd[pair] = bd; g_wrs[pair] = rs;
                    bws += ws; bap += ap; bbd += bd; brs += rs;
                }
            }
        }
    }

    // zero-fill tail: j in [ntiles*256, Ss)
    {
        int jz0 = ntiles * 256;
        if (jz0 < Ss) {
            float4 z4 = make_float4(0.f,0.f,0.f,0.f);
            float4* base = (float4*)(pi_out + (rowbase + jz0) * NV);
            int n4 = (Ss - jz0) * 16;
            for (int t = tid; t < n4; t += 256) __stcs(base + t, z4);
            for (int j = jz0 + tid; j < Ss; j += 256) {
                size_t p = rowbase + j;
                g_ws[p] = 0.f; g_wap[p] = 0.f; g_wbd[p] = 0.f; g_wrs[p] = 0.f;
            }
        }
    }

    // in-block invden
    #pragma unroll
    for (int off = 16; off; off >>= 1) {
        bws += __shfl_xor_sync(0xffffffffu, bws, off);
        bap += __shfl_xor_sync(0xffffffffu, bap, off);
        bbd += __shfl_xor_sync(0xffffffffu, bbd, off);
        brs += __shfl_xor_sync(0xffffffffu, brs, off);
    }
    if (lane == 0) {
        wred[warp][0] = bws; wred[warp][1] = bap;
        wred[warp][2] = bbd; wred[warp][3] = brs;
    }
    __syncthreads();
    if (tid < 4) {
        float s = 0.f;
        #pragma unroll
        for (int w = 0; w < 8; w++) s += wred[w][tid];
        if (tid == 0) {
            g_invden[row_g] = 1.f / (s + EPSV);
        } else {
            float d1 = s + EPSV, S2 = s / d1;
            g_invden[tid*BS + row_g] = 1.f / (d1 * (S2 + EPSV));
        }
    }
}

// ---------------- layernorm ----------------
__global__ void ln_kernel(const float* __restrict__ bo, const float* __restrict__ gamma,
                          const float* __restrict__ beta, float* __restrict__ out)
{
    int row = blockIdx.x, tid = threadIdx.x;
    const float* r = g_res + (size_t)row * Dd;
    float v[3];
    float s = 0.f;
    #pragma unroll
    for (int q = 0; q < 3; q++) { int c = tid + q*256; v[q] = r[c] + bo[c]; s += v[q]; }
    __shared__ float red[256];
    __shared__ float mu_s, inv_s;
    red[tid] = s; __syncthreads();
    for (int off = 128; off; off >>= 1) {
        if (tid < off) red[tid] += red[tid + off];
        __syncthreads();
    }
    if (tid == 0) mu_s = red[0] * (1.f / Dd);
    __syncthreads();
    float mu = mu_s;
    float s2 = 0.f;
    #pragma unroll
    for (int q = 0; q < 3; q++) { float d = v[q] - mu; s2 += d*d; }
    __syncthreads();
    red[tid] = s2; __syncthreads();
    for (int off = 128; off; off >>= 1) {
        if (tid < off) red[tid] += red[tid + off];
        __syncthreads();
    }
    if (tid == 0) inv_s = rsqrtf(red[0] * (1.f / Dd) + LNEPS);
    __syncthreads();
    float inv = inv_s;
    #pragma unroll
    for (int q = 0; q < 3; q++) {
        int c = tid + q*256;
        out[(size_t)row*Dd + c] = (v[q] - mu) * inv * gamma[c] + beta[c];
    }
}

// ---------------- launch ----------------
extern "C" void kernel_launch(void* const* d_in, const int* in_sizes, int n_in,
                              void* d_out, int out_size)
{
    const float* x      = (const float*)d_in[0];
    const float* Wq     = (const float*)d_in[2];
    const float* Wk     = (const float*)d_in[3];
    const float* vemb   = (const float*)d_in[4];
    const float* vgates = (const float*)d_in[5];
    const float* Wv     = (const float*)d_in[6];
    const float* Wspec  = (const float*)d_in[7];
    const float* Wa     = (const float*)d_in[8];
    const float* Wb     = (const float*)d_in[9];
    const float* Wr     = (const float*)d_in[10];
    const float* Wo     = (const float*)d_in[11];
    const float* bo     = (const float*)d_in[12];
    const float* gamma  = (const float*)d_in[13];
    const float* beta   = (const float*)d_in[14];
    const float* adj    = (const float*)d_in[15];
    const float* spec   = (const float*)d_in[16];

    float* out    = (float*)d_out;
    float* pi_out = out + NORMED_ELEMS;

    float *pQK, *pV, *pABR, *pComb, *pRes;
    cudaGetSymbolAddress((void**)&pQK,   g_QK);
    cudaGetSymbolAddress((void**)&pV,    g_V);
    cudaGetSymbolAddress((void**)&pABR,  g_ABR);
    cudaGetSymbolAddress((void**)&pComb, g_comb);
    cudaGetSymbolAddress((void**)&pRes,  g_res);

    dim3 thr(256);
    setup_kernel<<<65, thr>>>(vemb, spec, Wspec, adj, vgates);
    gemm_fused<<<dim3(25, 16), thr>>>(x, Wq, Wk, Wv, Wa, Wb, Wr, pQK, pV, pABR);

    attn_row<<<dim3(Ss, Bb), thr>>>(pi_out);
    combine_tc<<<dim3(4, 8, 6), thr>>>();

    gemm_tc<<<dim3(12, 16), thr>>>(pComb, Wo, pRes, Dd);
    ln_kernel<<<BS, 256>>>(bo, gamma, beta, out);
}

// round 8
// speedup vs baseline: 3.6794x; 1.0439x over previous
#include <cuda_runtime.h>

#define Bb 2
#define Ss 1024
#define Dd 768
#define DV 32
#define NV 64
#define D3 256
#define BS (Bb*Ss)
#define Kd 768
#define EPSV 1e-8f
#define LNEPS 1e-5f
#define NORMED_ELEMS ((size_t)Bb*Ss*Dd)

// ---------------- scratch ----------------
__device__ float g_QK[BS*64];
__device__ float g_V[BS*Dd];
__device__ float g_ABR[BS*Dd];
__device__ float g_emb2[NV*DV];
__device__ float g_gm[NV];
__device__ float g_ws [(size_t)BS*Ss];
__device__ float g_wap[(size_t)BS*Ss];
__device__ float g_wbd[(size_t)BS*Ss];
__device__ float g_wrs[(size_t)BS*Ss];
__device__ float g_invden[4*BS];
__device__ float g_comb[BS*Dd];
__device__ float g_res[BS*Dd];

// ---------------- tf32 helpers ----------------
__device__ __forceinline__ float f2tf32(float f) {
    unsigned r;
    asm("cvt.rna.tf32.f32 %0, %1;" : "=r"(r) : "f"(f));
    return __uint_as_float(r);
}
__device__ __forceinline__ void mma_tf32(float* c, const unsigned* a, const unsigned* b) {
    asm volatile("mma.sync.aligned.m16n8k8.row.col.f32.tf32.tf32.f32 "
                 "{%0,%1,%2,%3}, {%4,%5,%6,%7}, {%8,%9}, {%0,%1,%2,%3};"
                 : "+f"(c[0]), "+f"(c[1]), "+f"(c[2]), "+f"(c[3])
                 : "r"(a[0]), "r"(a[1]), "r"(a[2]), "r"(a[3]), "r"(b[0]), "r"(b[1]));
}

// ======== fused projection GEMM: [QK | V | ABR] = X @ W^T, pipelined ========
__global__ __launch_bounds__(256)
void gemm_fused(const float* __restrict__ X,
                const float* __restrict__ Wq, const float* __restrict__ Wk,
                const float* __restrict__ Wv, const float* __restrict__ Wa,
                const float* __restrict__ Wb, const float* __restrict__ Wr,
                float* __restrict__ Cqk, float* __restrict__ Cv, float* __restrict__ Cabr)
{
    __shared__ float As[2][16][136];
    __shared__ float Bs[2][16][72];
    int tid = threadIdx.x;
    int lane = tid & 31, warp = tid >> 5;
    int wm = warp & 3, wn = warp >> 2;
    int gid = lane >> 2, tig = lane & 3;
    int m0 = blockIdx.y * 128, n0 = blockIdx.x * 64;

    float c[2][4][4];
    #pragma unroll
    for (int mt = 0; mt < 2; mt++)
        #pragma unroll
        for (int nt = 0; nt < 4; nt++)
            #pragma unroll
            for (int e = 0; e < 4; e++) c[mt][nt][e] = 0.f;

    int ra = tid >> 2;
    int ka = (tid & 3) * 4;
    int sw = 8 * (tid & 3);
    const float* xp0 = X + (size_t)(m0 + ra) * Kd + ka;
    const float* xp1 = X + (size_t)(m0 + ra + 64) * Kd + ka;
    int rW = n0 + ra;
    const float* wp;
    if      (rW <   32) wp = Wq + (size_t)rW * Kd;
    else if (rW <   64) wp = Wk + (size_t)(rW -   32) * Kd;
    else if (rW <  832) wp = Wv + (size_t)(rW -   64) * Kd;
    else if (rW < 1088) wp = Wa + (size_t)(rW -  832) * Kd;
    else if (rW < 1344) wp = Wb + (size_t)(rW - 1088) * Kd;
    else                wp = Wr + (size_t)(rW - 1344) * Kd;
    wp += ka;

    int ca = ra ^ sw, ca1 = (ra + 64) ^ sw, cb = ca & 127;

    {
        float4 av0 = *(const float4*)(xp0);
        float4 av1 = *(const float4*)(xp1);
        float4 bv  = *(const float4*)(wp);
        As[0][ka+0][ca]  = f2tf32(av0.x); As[0][ka+1][ca]  = f2tf32(av0.y);
        As[0][ka+2][ca]  = f2tf32(av0.z); As[0][ka+3][ca]  = f2tf32(av0.w);
        As[0][ka+0][ca1] = f2tf32(av1.x); As[0][ka+1][ca1] = f2tf32(av1.y);
        As[0][ka+2][ca1] = f2tf32(av1.z); As[0][ka+3][ca1] = f2tf32(av1.w);
        Bs[0][ka+0][cb] = f2tf32(bv.x); Bs[0][ka+1][cb] = f2tf32(bv.y);
        Bs[0][ka+2][cb] = f2tf32(bv.z); Bs[0][ka+3][cb] = f2tf32(bv.w);
    }
    __syncthreads();

    const int NIT = Kd / 16;
    for (int it = 0; it < NIT; it++) {
        int cur = it & 1;
        float4 nav0, nav1, nbv;
        if (it + 1 < NIT) {
            int k0 = (it + 1) * 16;
            nav0 = *(const float4*)(xp0 + k0);
            nav1 = *(const float4*)(xp1 + k0);
            nbv  = *(const float4*)(wp  + k0);
        }
        #pragma unroll
        for (int ks = 0; ks < 16; ks += 8) {
            int swl = 8 * (ks >> 2), swh = swl + 8;
            int klo = ks + tig, khi = ks + tig + 4;
            unsigned a[2][4], b[4][2];
            #pragma unroll
            for (int mt = 0; mt < 2; mt++) {
                int mr = wm*32 + mt*16 + gid;
                a[mt][0] = __float_as_uint(As[cur][klo][ mr      ^ swl]);
                a[mt][1] = __float_as_uint(As[cur][klo][(mr + 8) ^ swl]);
                a[mt][2] = __float_as_uint(As[cur][khi][ mr      ^ swh]);
                a[mt][3] = __float_as_uint(As[cur][khi][(mr + 8) ^ swh]);
            }
            #pragma unroll
            for (int nt = 0; nt < 4; nt++) {
                int nc = wn*32 + nt*8 + gid;
                b[nt][0] = __float_as_uint(Bs[cur][klo][nc ^ swl]);
                b[nt][1] = __float_as_uint(Bs[cur][khi][nc ^ swh]);
            }
            #pragma unroll
            for (int mt = 0; mt < 2; mt++)
                #pragma unroll
                for (int nt = 0; nt < 4; nt++)
                    mma_tf32(c[mt][nt], a[mt], b[nt]);
        }
        if (it + 1 < NIT) {
            int nx = cur ^ 1;
            As[nx][ka+0][ca]  = f2tf32(nav0.x); As[nx][ka+1][ca]  = f2tf32(nav0.y);
            As[nx][ka+2][ca]  = f2tf32(nav0.z); As[nx][ka+3][ca]  = f2tf32(nav0.w);
            As[nx][ka+0][ca1] = f2tf32(nav1.x); As[nx][ka+1][ca1] = f2tf32(nav1.y);
            As[nx][ka+2][ca1] = f2tf32(nav1.z); As[nx][ka+3][ca1] = f2tf32(nav1.w);
            Bs[nx][ka+0][cb] = f2tf32(nbv.x); Bs[nx][ka+1][cb] = f2tf32(nbv.y);
            Bs[nx][ka+2][cb] = f2tf32(nbv.z); Bs[nx][ka+3][cb] = f2tf32(nbv.w);
        }
        __syncthreads();
    }

    float* Cd; int strideN, cbase;
    if (n0 == 0)       { Cd = Cqk;  strideN = 64;  cbase = 0; }
    else if (n0 < 832) { Cd = Cv;   strideN = Dd;  cbase = n0 - 64; }
    else               { Cd = Cabr; strideN = Dd;  cbase = n0 - 832; }

    #pragma unroll
    for (int mt = 0; mt < 2; mt++) {
        int r0 = m0 + wm*32 + mt*16 + gid;
        #pragma unroll
        for (int nt = 0; nt < 4; nt++) {
            int cc = cbase + wn*32 + nt*8 + tig*2;
            *(float2*)(Cd + (size_t)r0 * strideN + cc)     = make_float2(c[mt][nt][0], c[mt][nt][1]);
            *(float2*)(Cd + (size_t)(r0+8) * strideN + cc) = make_float2(c[mt][nt][2], c[mt][nt][3]);
        }
    }
}

// ======== generic pipelined TF32 GEMM (used for Wo) ========
__global__ __launch_bounds__(256)
void gemm_tc(const float* __restrict__ X, const float* __restrict__ W0,
             float* __restrict__ C, int N)
{
    __shared__ float As[2][16][136];
    __shared__ float Bs[2][16][72];
    int tid = threadIdx.x;
    int lane = tid & 31, warp = tid >> 5;
    int wm = warp & 3, wn = warp >> 2;
    int gid = lane >> 2, tig = lane & 3;
    int m0 = blockIdx.y * 128, n0 = blockIdx.x * 64;

    float c[2][4][4];
    #pragma unroll
    for (int mt = 0; mt < 2; mt++)
        #pragma unroll
        for (int nt = 0; nt < 4; nt++)
            #pragma unroll
            for (int e = 0; e < 4; e++) c[mt][nt][e] = 0.f;

    int ra = tid >> 2;
    int ka = (tid & 3) * 4;
    int sw = 8 * (tid & 3);
    const float* xp0 = X + (size_t)(m0 + ra) * Kd + ka;
    const float* xp1 = X + (size_t)(m0 + ra + 64) * Kd + ka;
    const float* wp  = W0 + (size_t)(n0 + ra) * Kd + ka;
    int ca = ra ^ sw, ca1 = (ra + 64) ^ sw, cb = ca & 127;

    {
        float4 av0 = *(const float4*)(xp0);
        float4 av1 = *(const float4*)(xp1);
        float4 bv  = *(const float4*)(wp);
        As[0][ka+0][ca]  = f2tf32(av0.x); As[0][ka+1][ca]  = f2tf32(av0.y);
        As[0][ka+2][ca]  = f2tf32(av0.z); As[0][ka+3][ca]  = f2tf32(av0.w);
        As[0][ka+0][ca1] = f2tf32(av1.x); As[0][ka+1][ca1] = f2tf32(av1.y);
        As[0][ka+2][ca1] = f2tf32(av1.z); As[0][ka+3][ca1] = f2tf32(av1.w);
        Bs[0][ka+0][cb] = f2tf32(bv.x); Bs[0][ka+1][cb] = f2tf32(bv.y);
        Bs[0][ka+2][cb] = f2tf32(bv.z); Bs[0][ka+3][cb] = f2tf32(bv.w);
    }
    __syncthreads();

    const int NIT = Kd / 16;
    for (int it = 0; it < NIT; it++) {
        int cur = it & 1;
        float4 nav0, nav1, nbv;
        if (it + 1 < NIT) {
            int k0 = (it + 1) * 16;
            nav0 = *(const float4*)(xp0 + k0);
            nav1 = *(const float4*)(xp1 + k0);
            nbv  = *(const float4*)(wp  + k0);
        }
        #pragma unroll
        for (int ks = 0; ks < 16; ks += 8) {
            int swl = 8 * (ks >> 2), swh = swl + 8;
            int klo = ks + tig, khi = ks + tig + 4;
            unsigned a[2][4], b[4][2];
            #pragma unroll
            for (int mt = 0; mt < 2; mt++) {
                int mr = wm*32 + mt*16 + gid;
                a[mt][0] = __float_as_uint(As[cur][klo][ mr      ^ swl]);
                a[mt][1] = __float_as_uint(As[cur][klo][(mr + 8) ^ swl]);
                a[mt][2] = __float_as_uint(As[cur][khi][ mr      ^ swh]);
                a[mt][3] = __float_as_uint(As[cur][khi][(mr + 8) ^ swh]);
            }
            #pragma unroll
            for (int nt = 0; nt < 4; nt++) {
                int nc = wn*32 + nt*8 + gid;
                b[nt][0] = __float_as_uint(Bs[cur][klo][nc ^ swl]);
                b[nt][1] = __float_as_uint(Bs[cur][khi][nc ^ swh]);
            }
            #pragma unroll
            for (int mt = 0; mt < 2; mt++)
                #pragma unroll
                for (int nt = 0; nt < 4; nt++)
                    mma_tf32(c[mt][nt], a[mt], b[nt]);
        }
        if (it + 1 < NIT) {
            int nx = cur ^ 1;
            As[nx][ka+0][ca]  = f2tf32(nav0.x); As[nx][ka+1][ca]  = f2tf32(nav0.y);
            As[nx][ka+2][ca]  = f2tf32(nav0.z); As[nx][ka+3][ca]  = f2tf32(nav0.w);
            As[nx][ka+0][ca1] = f2tf32(nav1.x); As[nx][ka+1][ca1] = f2tf32(nav1.y);
            As[nx][ka+2][ca1] = f2tf32(nav1.z); As[nx][ka+3][ca1] = f2tf32(nav1.w);
            Bs[nx][ka+0][cb] = f2tf32(nbv.x); Bs[nx][ka+1][cb] = f2tf32(nbv.y);
            Bs[nx][ka+2][cb] = f2tf32(nbv.z); Bs[nx][ka+3][cb] = f2tf32(nbv.w);
        }
        __syncthreads();
    }
    #pragma unroll
    for (int mt = 0; mt < 2; mt++) {
        int r0 = m0 + wm*32 + mt*16 + gid;
        #pragma unroll
        for (int nt = 0; nt < 4; nt++) {
            int cc = n0 + wn*32 + nt*8 + tig*2;
            *(float2*)(C + (size_t)r0 * N + cc)     = make_float2(c[mt][nt][0], c[mt][nt][1]);
            *(float2*)(C + (size_t)(r0+8) * N + cc) = make_float2(c[mt][nt][2], c[mt][nt][3]);
        }
    }
}

// ======== combine v2: BM=64, BN=64, BOTH passes in one k-loop ========
// comb[b*S+m][t*256+n] = sum_k is*ws[m][k]*V[k][t*256+n] + it*wt[m][k]*ABR[k][t*256+n]
__global__ __launch_bounds__(256)
void combine_tc2()
{
    int bz = blockIdx.z;
    int b = bz / 3, t = bz % 3;
    const float* Wt = (t == 0) ? g_wap : (t == 1) ? g_wbd : g_wrs;
    int m0 = blockIdx.y * 64, n0 = blockIdx.x * 64;
    int colbase = t * D3 + n0;

    // [buf][pass][k][col]
    __shared__ float As[2][2][16][72];
    __shared__ float Bs[2][2][16][72];
    int tid = threadIdx.x;
    int lane = tid & 31, warp = tid >> 5;
    int wm = warp & 3, wn = warp >> 2;      // 4 m-subtiles x 2 n-subtiles
    int gid = lane >> 2, tig = lane & 3;

    float c[2][4][4];
    #pragma unroll
    for (int p = 0; p < 2; p++)
        #pragma unroll
        for (int nt = 0; nt < 4; nt++)
            #pragma unroll
            for (int e = 0; e < 4; e++) c[p][nt][e] = 0.f;

    int ra = tid >> 2;                 // 0..63 (A row)
    int ka = (tid & 3) * 4;            // A k
    int sw = 8 * (tid & 3);
    int kb = tid >> 4;                 // 0..15 (B k)
    int nb = (tid & 15) * 4;           // B col
    int swb = 8 * (kb >> 2);
    int ca = ra ^ sw;

    float sc0 = g_invden[b*Ss + m0 + ra];
    float sc1 = g_invden[(t+1)*BS + b*Ss + m0 + ra];
    const float* aws = g_ws + (size_t)(b*Ss + m0 + ra) * Ss + ka;
    const float* awt = Wt   + (size_t)(b*Ss + m0 + ra) * Ss + ka;
    const float* bpv = g_V   + (size_t)(b*Ss + kb) * Dd + colbase + nb;
    const float* bpt = g_ABR + (size_t)(b*Ss + kb) * Dd + colbase + nb;

    const int NIT = m0/16 + 4;   // k up to m0+63 inclusive

    {
        float4 a0 = *(const float4*)(aws);
        float4 a1 = *(const float4*)(awt);
        float4 b0 = *(const float4*)(bpv);
        float4 b1 = *(const float4*)(bpt);
        As[0][0][ka+0][ca] = f2tf32(a0.x * sc0); As[0][0][ka+1][ca] = f2tf32(a0.y * sc0);
        As[0][0][ka+2][ca] = f2tf32(a0.z * sc0); As[0][0][ka+3][ca] = f2tf32(a0.w * sc0);
        As[0][1][ka+0][ca] = f2tf32(a1.x * sc1); As[0][1][ka+1][ca] = f2tf32(a1.y * sc1);
        As[0][1][ka+2][ca] = f2tf32(a1.z * sc1); As[0][1][ka+3][ca] = f2tf32(a1.w * sc1);
        Bs[0][0][kb][(nb+0)^swb] = f2tf32(b0.x); Bs[0][0][kb][(nb+1)^swb] = f2tf32(b0.y);
        Bs[0][0][kb][(nb+2)^swb] = f2tf32(b0.z); Bs[0][0][kb][(nb+3)^swb] = f2tf32(b0.w);
        Bs[0][1][kb][(nb+0)^swb] = f2tf32(b1.x); Bs[0][1][kb][(nb+1)^swb] = f2tf32(b1.y);
        Bs[0][1][kb][(nb+2)^swb] = f2tf32(b1.z); Bs[0][1][kb][(nb+3)^swb] = f2tf32(b1.w);
    }
    __syncthreads();

    for (int it = 0; it < NIT; it++) {
        int cur = it & 1;
        float4 na0, na1, nb0, nb1;
        if (it + 1 < NIT) {
            int k0 = (it + 1) * 16;
            na0 = *(const float4*)(aws + k0);
            na1 = *(const float4*)(awt + k0);
            nb0 = *(const float4*)(bpv + (size_t)k0 * Dd);
            nb1 = *(const float4*)(bpt + (size_t)k0 * Dd);
        }
        #pragma unroll
        for (int ks = 0; ks < 16; ks += 8) {
            int swl = 8 * (ks >> 2), swh = swl + 8;
            int klo = ks + tig, khi = ks + tig + 4;
            int mr = wm*16 + gid;
            #pragma unroll
            for (int p = 0; p < 2; p++) {
                unsigned a[4], bfr[4][2];
                a[0] = __float_as_uint(As[cur][p][klo][ mr      ^ swl]);
                a[1] = __float_as_uint(As[cur][p][klo][(mr + 8) ^ swl]);
                a[2] = __float_as_uint(As[cur][p][khi][ mr      ^ swh]);
                a[3] = __float_as_uint(As[cur][p][khi][(mr + 8) ^ swh]);
                #pragma unroll
                for (int nt = 0; nt < 4; nt++) {
                    int nc = wn*32 + nt*8 + gid;
                    bfr[nt][0] = __float_as_uint(Bs[cur][p][klo][nc ^ swl]);
                    bfr[nt][1] = __float_as_uint(Bs[cur][p][khi][nc ^ swh]);
                }
                #pragma unroll
                for (int nt = 0; nt < 4; nt++)
                    mma_tf32(c[p][nt], a, bfr[nt]);
            }
        }
        if (it + 1 < NIT) {
            int nx = cur ^ 1;
            As[nx][0][ka+0][ca] = f2tf32(na0.x * sc0); As[nx][0][ka+1][ca] = f2tf32(na0.y * sc0);
            As[nx][0][ka+2][ca] = f2tf32(na0.z * sc0); As[nx][0][ka+3][ca] = f2tf32(na0.w * sc0);
            As[nx][1][ka+0][ca] = f2tf32(na1.x * sc1); As[nx][1][ka+1][ca] = f2tf32(na1.y * sc1);
            As[nx][1][ka+2][ca] = f2tf32(na1.z * sc1); As[nx][1][ka+3][ca] = f2tf32(na1.w * sc1);
            Bs[nx][0][kb][(nb+0)^swb] = f2tf32(nb0.x); Bs[nx][0][kb][(nb+1)^swb] = f2tf32(nb0.y);
            Bs[nx][0][kb][(nb+2)^swb] = f2tf32(nb0.z); Bs[nx][0][kb][(nb+3)^swb] = f2tf32(nb0.w);
            Bs[nx][1][kb][(nb+0)^swb] = f2tf32(nb1.x); Bs[nx][1][kb][(nb+1)^swb] = f2tf32(nb1.y);
            Bs[nx][1][kb][(nb+2)^swb] = f2tf32(nb1.z); Bs[nx][1][kb][(nb+3)^swb] = f2tf32(nb1.w);
        }
        __syncthreads();
    }

    int r0 = b*Ss + m0 + wm*16 + gid;
    #pragma unroll
    for (int nt = 0; nt < 4; nt++) {
        int cc = colbase + wn*32 + nt*8 + tig*2;
        *(float2*)(g_comb + (size_t)r0 * Dd + cc) =
            make_float2(c[0][nt][0] + c[1][nt][0], c[0][nt][1] + c[1][nt][1]);
        *(float2*)(g_comb + (size_t)(r0+8) * Dd + cc) =
            make_float2(c[0][nt][2] + c[1][nt][2], c[0][nt][3] + c[1][nt][3]);
    }
}

// ---------------- merged setup ----------------
__global__ __launch_bounds__(256)
void setup_kernel(const float* __restrict__ vemb, const float* __restrict__ spec,
                  const float* __restrict__ Wspec, const float* __restrict__ adj,
                  const float* __restrict__ vg)
{
    int tid = threadIdx.x;
    if (blockIdx.x == 0) {
        __shared__ float eb[NV*DV];
        __shared__ float adj_s[NV*NV];
        for (int t = tid; t < NV*DV; t += 256) {
            int u = t / DV, d = t % DV;
            float s = vemb[t];
            #pragma unroll
            for (int h = 0; h < 6; h++) s += 0.1f * spec[u*6+h] * Wspec[d*6+h];
            eb[t] = s;
        }
        for (int t = tid; t < NV*NV; t += 256) adj_s[t] = adj[t];
        __syncthreads();
        for (int t = tid; t < NV*DV; t += 256) {
            int v = t / DV, d = t % DV;
            float s = eb[t];
            #pragma unroll 8
            for (int u = 0; u < NV; u++) s += 0.1f * adj_s[u*NV + v] * eb[u*DV + d];
            g_emb2[t] = s;
        }
    } else {
        int v = blockIdx.x - 1;
        float s = 0.f;
        for (int c = tid; c < Dd; c += 256) {
            float x = vg[(size_t)v*Dd + c];
            s += 1.f / (1.f + __expf(-x));
        }
        __shared__ float red[256];
        red[tid] = s; __syncthreads();
        for (int off = 128; off; off >>= 1) {
            if (tid < off) red[tid] += red[tid + off];
            __syncthreads();
        }
        if (tid == 0) g_gm[v] = red[0] * (1.f / Dd);
    }
}

// ---------------- row-persistent attention ----------------
__global__ __launch_bounds__(256)
void attn_row(float* __restrict__ pi_out)
{
    int i = blockIdx.x, b = blockIdx.y;
    int row_g = b*Ss + i;
    size_t rowbase = (size_t)row_g * Ss;
    int tid = threadIdx.x;
    int warp = tid >> 5, lane = tid & 31;
    int gid = lane >> 2, tig = lane & 3;

    __shared__ float Ks[256][36];
    __shared__ float Fs[32][72];
    __shared__ float q_s[DV];
    __shared__ float gm_s[NV];
    __shared__ float wred[8][4];

    if (tid < DV) q_s[tid] = g_QK[(size_t)row_g*64 + tid];
    if (tid >= 64 && tid < 128) gm_s[tid-64] = g_gm[tid-64];
    __syncthreads();
    for (int t = tid; t < 2048; t += 256) {
        int d = t >> 6, v = t & 63;
        Fs[d][v] = f2tf32(q_s[d] * g_emb2[v*DV + d]);
    }

    float gmr[16];
    #pragma unroll
    for (int nt = 0; nt < 8; nt++) {
        gmr[nt*2]   = gm_s[nt*8 + tig*2];
        gmr[nt*2+1] = gm_s[nt*8 + tig*2 + 1];
    }

    float bws = 0.f, bap = 0.f, bbd = 0.f, brs = 0.f;
    int ntiles = (i >> 8) + 1;

    for (int jt = 0; jt < ntiles; jt++) {
        int j0 = jt * 256;
        __syncthreads();
        for (int t = tid; t < 2048; t += 256) {
            int r = t >> 3, q = t & 7;
            float4 kv = *(const float4*)(g_QK + (size_t)(b*Ss + j0 + r)*64 + 32 + q*4);
            Ks[r][q*4+0] = f2tf32(kv.x); Ks[r][q*4+1] = f2tf32(kv.y);
            Ks[r][q*4+2] = f2tf32(kv.z); Ks[r][q*4+3] = f2tf32(kv.w);
        }
        __syncthreads();

        float c[2][8][4];
        #pragma unroll
        for (int mt = 0; mt < 2; mt++)
            #pragma unroll
            for (int nt = 0; nt < 8; nt++)
                #pragma unroll
                for (int e = 0; e < 4; e++) c[mt][nt][e] = 0.f;

        #pragma unroll
        for (int ks = 0; ks < 32; ks += 8) {
            unsigned a[2][4], bf[8][2];
            #pragma unroll
            for (int mt = 0; mt < 2; mt++) {
                int mr = warp*32 + mt*16 + gid;
                a[mt][0] = __float_as_uint(Ks[mr  ][ks+tig]);
                a[mt][1] = __float_as_uint(Ks[mr+8][ks+tig]);
                a[mt][2] = __float_as_uint(Ks[mr  ][ks+tig+4]);
                a[mt][3] = __float_as_uint(Ks[mr+8][ks+tig+4]);
            }
            #pragma unroll
            for (int nt = 0; nt < 8; nt++) {
                int nc = nt*8 + gid;
                bf[nt][0] = __float_as_uint(Fs[ks+tig  ][nc]);
                bf[nt][1] = __float_as_uint(Fs[ks+tig+4][nc]);
            }
            #pragma unroll
            for (int mt = 0; mt < 2; mt++)
                #pragma unroll
                for (int nt = 0; nt < 8; nt++)
                    mma_tf32(c[mt][nt], a[mt], bf[nt]);
        }

        #pragma unroll
        for (int mt = 0; mt < 2; mt++)
        #pragma unroll
        for (int rh = 0; rh < 2; rh++) {
            int j = j0 + warp*32 + mt*16 + rh*8 + gid;
            size_t pair = rowbase + j;
            float e[16];
            // scores are tiny (|s| << 1): exp without max-shift, exact same softmax
            float sum = 0.f, sg = 0.f, sap = 0.f;
            #pragma unroll
            for (int q = 0; q < 16; q++) {
                float ev = __expf(c[mt][q>>1][rh*2 + (q&1)]);
                e[q] = ev;
                sum += ev;
                sg = fmaf(ev, gmr[q], sg);
                if (q & 1) sap += ev;
            }
            float sbd = (tig & 1) ? sum : 0.f;
            float srs = (tig & 2) ? sum : 0.f;
            sum += __shfl_xor_sync(0xffffffffu, sum, 1);
            sum += __shfl_xor_sync(0xffffffffu, sum, 2);
            sg  += __shfl_xor_sync(0xffffffffu, sg , 1);
            sg  += __shfl_xor_sync(0xffffffffu, sg , 2);
            sap += __shfl_xor_sync(0xffffffffu, sap, 1);
            sap += __shfl_xor_sync(0xffffffffu, sap, 2);
            sbd += __shfl_xor_sync(0xffffffffu, sbd, 1);
            sbd += __shfl_xor_sync(0xffffffffu, sbd, 2);
            srs += __shfl_xor_sync(0xffffffffu, srs, 1);
            srs += __shfl_xor_sync(0xffffffffu, srs, 2);

            float* po = pi_out + pair*NV + tig*2;
            if (j > i) {
                float2 z = make_float2(0.f, 0.f);
                #pragma unroll
                for (int nt = 0; nt < 8; nt++) __stcs((float2*)(po + nt*8), z);
                if (tig == 0) {
                    g_ws[pair] = 0.f; g_wap[pair] = 0.f;
                    g_wbd[pair] = 0.f; g_wrs[pair] = 0.f;
                }
            } else {
                float inv = 1.f / sum;
                #pragma unroll
                for (int nt = 0; nt < 8; nt++)
                    __stcs((float2*)(po + nt*8), make_float2(e[nt*2]*inv, e[nt*2+1]*inv));
                if (tig == 0) {
                    float ws = sg*inv, ap = sap*inv, bd = sbd*inv, rs = srs*inv;
                    g_ws[pair] = ws; g_wap[pair] = ap; g_wbd[pair] = bd; g_wrs[pair] = rs;
                    bws += ws; bap += ap; bbd += bd; brs += rs;
                }
            }
        }
    }

    {
        int jz0 = ntiles * 256;
        if (jz0 < Ss) {
            float4 z4 = make_float4(0.f,0.f,0.f,0.f);
            float4* base = (float4*)(pi_out + (rowbase + jz0) * NV);
            int n4 = (Ss - jz0) * 16;
            for (int t = tid; t < n4; t += 256) __stcs(base + t, z4);
            for (int j = jz0 + tid; j < Ss; j += 256) {
                size_t p = rowbase + j;
                g_ws[p] = 0.f; g_wap[p] = 0.f; g_wbd[p] = 0.f; g_wrs[p] = 0.f;
            }
        }
    }

    #pragma unroll
    for (int off = 16; off; off >>= 1) {
        bws += __shfl_xor_sync(0xffffffffu, bws, off);
        bap += __shfl_xor_sync(0xffffffffu, bap, off);
        bbd += __shfl_xor_sync(0xffffffffu, bbd, off);
        brs += __shfl_xor_sync(0xffffffffu, brs, off);
    }
    if (lane == 0) {
        wred[warp][0] = bws; wred[warp][1] = bap;
        wred[warp][2] = bbd; wred[warp][3] = brs;
    }
    __syncthreads();
    if (tid < 4) {
        float s = 0.f;
        #pragma unroll
        for (int w = 0; w < 8; w++) s += wred[w][tid];
        if (tid == 0) {
            g_invden[row_g] = 1.f / (s + EPSV);
        } else {
            float d1 = s + EPSV, S2 = s / d1;
            g_invden[tid*BS + row_g] = 1.f / (d1 * (S2 + EPSV));
        }
    }
}

// ---------------- layernorm ----------------
__global__ void ln_kernel(const float* __restrict__ bo, const float* __restrict__ gamma,
                          const float* __restrict__ beta, float* __restrict__ out)
{
    int row = blockIdx.x, tid = threadIdx.x;
    const float* r = g_res + (size_t)row * Dd;
    float v[3];
    float s = 0.f;
    #pragma unroll
    for (int q = 0; q < 3; q++) { int c = tid + q*256; v[q] = r[c] + bo[c]; s += v[q]; }
    __shared__ float red[256];
    __shared__ float mu_s, inv_s;
    red[tid] = s; __syncthreads();
    for (int off = 128; off; off >>= 1) {
        if (tid < off) red[tid] += red[tid + off];
        __syncthreads();
    }
    if (tid == 0) mu_s = red[0] * (1.f / Dd);
    __syncthreads();
    float mu = mu_s;
    float s2 = 0.f;
    #pragma unroll
    for (int q = 0; q < 3; q++) { float d = v[q] - mu; s2 += d*d; }
    __syncthreads();
    red[tid] = s2; __syncthreads();
    for (int off = 128; off; off >>= 1) {
        if (tid < off) red[tid] += red[tid + off];
        __syncthreads();
    }
    if (tid == 0) inv_s = rsqrtf(red[0] * (1.f / Dd) + LNEPS);
    __syncthreads();
    float inv = inv_s;
    #pragma unroll
    for (int q = 0; q < 3; q++) {
        int c = tid + q*256;
        out[(size_t)row*Dd + c] = (v[q] - mu) * inv * gamma[c] + beta[c];
    }
}

// ---------------- launch ----------------
extern "C" void kernel_launch(void* const* d_in, const int* in_sizes, int n_in,
                              void* d_out, int out_size)
{
    const float* x      = (const float*)d_in[0];
    const float* Wq     = (const float*)d_in[2];
    const float* Wk     = (const float*)d_in[3];
    const float* vemb   = (const float*)d_in[4];
    const float* vgates = (const float*)d_in[5];
    const float* Wv     = (const float*)d_in[6];
    const float* Wspec  = (const float*)d_in[7];
    const float* Wa     = (const float*)d_in[8];
    const float* Wb     = (const float*)d_in[9];
    const float* Wr     = (const float*)d_in[10];
    const float* Wo     = (const float*)d_in[11];
    const float* bo     = (const float*)d_in[12];
    const float* gamma  = (const float*)d_in[13];
    const float* beta   = (const float*)d_in[14];
    const float* adj    = (const float*)d_in[15];
    const float* spec   = (const float*)d_in[16];

    float* out    = (float*)d_out;
    float* pi_out = out + NORMED_ELEMS;

    float *pQK, *pV, *pABR, *pComb, *pRes;
    cudaGetSymbolAddress((void**)&pQK,   g_QK);
    cudaGetSymbolAddress((void**)&pV,    g_V);
    cudaGetSymbolAddress((void**)&pABR,  g_ABR);
    cudaGetSymbolAddress((void**)&pComb, g_comb);
    cudaGetSymbolAddress((void**)&pRes,  g_res);

    dim3 thr(256);
    setup_kernel<<<65, thr>>>(vemb, spec, Wspec, adj, vgates);
    gemm_fused<<<dim3(25, 16), thr>>>(x, Wq, Wk, Wv, Wa, Wb, Wr, pQK, pV, pABR);

    attn_row<<<dim3(Ss, Bb), thr>>>(pi_out);
    combine_tc2<<<dim3(4, 16, 6), thr>>>();

    gemm_tc<<<dim3(12, 16), thr>>>(pComb, Wo, pRes, Dd);
    ln_kernel<<<BS, 256>>>(bo, gamma, beta, out);
}

// round 9
// speedup vs baseline: 4.2462x; 1.1541x over previous
#include <cuda_runtime.h>

#define Bb 2
#define Ss 1024
#define Dd 768
#define DV 32
#define NV 64
#define D3 256
#define BS (Bb*Ss)
#define Kd 768
#define EPSV 1e-8f
#define LNEPS 1e-5f
#define NORMED_ELEMS ((size_t)Bb*Ss*Dd)

// ---------------- scratch ----------------
__device__ float g_QK[BS*64];
__device__ float g_V[BS*Dd];
__device__ float g_ABR[BS*Dd];
__device__ float g_emb2[NV*DV];
__device__ float g_gm[NV];
__device__ float g_ws [(size_t)BS*Ss];
__device__ float g_wap[(size_t)BS*Ss];
__device__ float g_wbd[(size_t)BS*Ss];
__device__ float g_wrs[(size_t)BS*Ss];
__device__ float g_invden[4*BS];
__device__ float g_comb[BS*Dd];
__device__ float g_res[BS*Dd];

// ---------------- tf32 helpers ----------------
__device__ __forceinline__ float f2tf32(float f) {
    unsigned r;
    asm("cvt.rna.tf32.f32 %0, %1;" : "=r"(r) : "f"(f));
    return __uint_as_float(r);
}
__device__ __forceinline__ void mma_tf32(float* c, const unsigned* a, const unsigned* b) {
    asm volatile("mma.sync.aligned.m16n8k8.row.col.f32.tf32.tf32.f32 "
                 "{%0,%1,%2,%3}, {%4,%5,%6,%7}, {%8,%9}, {%0,%1,%2,%3};"
                 : "+f"(c[0]), "+f"(c[1]), "+f"(c[2]), "+f"(c[3])
                 : "r"(a[0]), "r"(a[1]), "r"(a[2]), "r"(a[3]), "r"(b[0]), "r"(b[1]));
}

// ======== fused projection GEMM: [QK | V | ABR] = X @ W^T, pipelined ========
__global__ __launch_bounds__(256)
void gemm_fused(const float* __restrict__ X,
                const float* __restrict__ Wq, const float* __restrict__ Wk,
                const float* __restrict__ Wv, const float* __restrict__ Wa,
                const float* __restrict__ Wb, const float* __restrict__ Wr,
                float* __restrict__ Cqk, float* __restrict__ Cv, float* __restrict__ Cabr)
{
    __shared__ float As[2][16][136];
    __shared__ float Bs[2][16][72];
    int tid = threadIdx.x;
    int lane = tid & 31, warp = tid >> 5;
    int wm = warp & 3, wn = warp >> 2;
    int gid = lane >> 2, tig = lane & 3;
    int m0 = blockIdx.y * 128, n0 = blockIdx.x * 64;

    float c[2][4][4];
    #pragma unroll
    for (int mt = 0; mt < 2; mt++)
        #pragma unroll
        for (int nt = 0; nt < 4; nt++)
            #pragma unroll
            for (int e = 0; e < 4; e++) c[mt][nt][e] = 0.f;

    int ra = tid >> 2;
    int ka = (tid & 3) * 4;
    int sw = 8 * (tid & 3);
    const float* xp0 = X + (size_t)(m0 + ra) * Kd + ka;
    const float* xp1 = X + (size_t)(m0 + ra + 64) * Kd + ka;
    int rW = n0 + ra;
    const float* wp;
    if      (rW <   32) wp = Wq + (size_t)rW * Kd;
    else if (rW <   64) wp = Wk + (size_t)(rW -   32) * Kd;
    else if (rW <  832) wp = Wv + (size_t)(rW -   64) * Kd;
    else if (rW < 1088) wp = Wa + (size_t)(rW -  832) * Kd;
    else if (rW < 1344) wp = Wb + (size_t)(rW - 1088) * Kd;
    else                wp = Wr + (size_t)(rW - 1344) * Kd;
    wp += ka;

    int ca = ra ^ sw, ca1 = (ra + 64) ^ sw, cb = ca & 127;

    {
        float4 av0 = *(const float4*)(xp0);
        float4 av1 = *(const float4*)(xp1);
        float4 bv  = *(const float4*)(wp);
        As[0][ka+0][ca]  = f2tf32(av0.x); As[0][ka+1][ca]  = f2tf32(av0.y);
        As[0][ka+2][ca]  = f2tf32(av0.z); As[0][ka+3][ca]  = f2tf32(av0.w);
        As[0][ka+0][ca1] = f2tf32(av1.x); As[0][ka+1][ca1] = f2tf32(av1.y);
        As[0][ka+2][ca1] = f2tf32(av1.z); As[0][ka+3][ca1] = f2tf32(av1.w);
        Bs[0][ka+0][cb] = f2tf32(bv.x); Bs[0][ka+1][cb] = f2tf32(bv.y);
        Bs[0][ka+2][cb] = f2tf32(bv.z); Bs[0][ka+3][cb] = f2tf32(bv.w);
    }
    __syncthreads();

    const int NIT = Kd / 16;
    for (int it = 0; it < NIT; it++) {
        int cur = it & 1;
        float4 nav0, nav1, nbv;
        if (it + 1 < NIT) {
            int k0 = (it + 1) * 16;
            nav0 = *(const float4*)(xp0 + k0);
            nav1 = *(const float4*)(xp1 + k0);
            nbv  = *(const float4*)(wp  + k0);
        }
        #pragma unroll
        for (int ks = 0; ks < 16; ks += 8) {
            int swl = 8 * (ks >> 2), swh = swl + 8;
            int klo = ks + tig, khi = ks + tig + 4;
            unsigned a[2][4], b[4][2];
            #pragma unroll
            for (int mt = 0; mt < 2; mt++) {
                int mr = wm*32 + mt*16 + gid;
                a[mt][0] = __float_as_uint(As[cur][klo][ mr      ^ swl]);
                a[mt][1] = __float_as_uint(As[cur][klo][(mr + 8) ^ swl]);
                a[mt][2] = __float_as_uint(As[cur][khi][ mr      ^ swh]);
                a[mt][3] = __float_as_uint(As[cur][khi][(mr + 8) ^ swh]);
            }
            #pragma unroll
            for (int nt = 0; nt < 4; nt++) {
                int nc = wn*32 + nt*8 + gid;
                b[nt][0] = __float_as_uint(Bs[cur][klo][nc ^ swl]);
                b[nt][1] = __float_as_uint(Bs[cur][khi][nc ^ swh]);
            }
            #pragma unroll
            for (int mt = 0; mt < 2; mt++)
                #pragma unroll
                for (int nt = 0; nt < 4; nt++)
                    mma_tf32(c[mt][nt], a[mt], b[nt]);
        }
        if (it + 1 < NIT) {
            int nx = cur ^ 1;
            As[nx][ka+0][ca]  = f2tf32(nav0.x); As[nx][ka+1][ca]  = f2tf32(nav0.y);
            As[nx][ka+2][ca]  = f2tf32(nav0.z); As[nx][ka+3][ca]  = f2tf32(nav0.w);
            As[nx][ka+0][ca1] = f2tf32(nav1.x); As[nx][ka+1][ca1] = f2tf32(nav1.y);
            As[nx][ka+2][ca1] = f2tf32(nav1.z); As[nx][ka+3][ca1] = f2tf32(nav1.w);
            Bs[nx][ka+0][cb] = f2tf32(nbv.x); Bs[nx][ka+1][cb] = f2tf32(nbv.y);
            Bs[nx][ka+2][cb] = f2tf32(nbv.z); Bs[nx][ka+3][cb] = f2tf32(nbv.w);
        }
        __syncthreads();
    }

    float* Cd; int strideN, cbase;
    if (n0 == 0)       { Cd = Cqk;  strideN = 64;  cbase = 0; }
    else if (n0 < 832) { Cd = Cv;   strideN = Dd;  cbase = n0 - 64; }
    else               { Cd = Cabr; strideN = Dd;  cbase = n0 - 832; }

    #pragma unroll
    for (int mt = 0; mt < 2; mt++) {
        int r0 = m0 + wm*32 + mt*16 + gid;
        #pragma unroll
        for (int nt = 0; nt < 4; nt++) {
            int cc = cbase + wn*32 + nt*8 + tig*2;
            *(float2*)(Cd + (size_t)r0 * strideN + cc)     = make_float2(c[mt][nt][0], c[mt][nt][1]);
            *(float2*)(Cd + (size_t)(r0+8) * strideN + cc) = make_float2(c[mt][nt][2], c[mt][nt][3]);
        }
    }
}

// ======== generic pipelined TF32 GEMM (used for Wo) ========
__global__ __launch_bounds__(256)
void gemm_tc(const float* __restrict__ X, const float* __restrict__ W0,
             float* __restrict__ C, int N)
{
    __shared__ float As[2][16][136];
    __shared__ float Bs[2][16][72];
    int tid = threadIdx.x;
    int lane = tid & 31, warp = tid >> 5;
    int wm = warp & 3, wn = warp >> 2;
    int gid = lane >> 2, tig = lane & 3;
    int m0 = blockIdx.y * 128, n0 = blockIdx.x * 64;

    float c[2][4][4];
    #pragma unroll
    for (int mt = 0; mt < 2; mt++)
        #pragma unroll
        for (int nt = 0; nt < 4; nt++)
            #pragma unroll
            for (int e = 0; e < 4; e++) c[mt][nt][e] = 0.f;

    int ra = tid >> 2;
    int ka = (tid & 3) * 4;
    int sw = 8 * (tid & 3);
    const float* xp0 = X + (size_t)(m0 + ra) * Kd + ka;
    const float* xp1 = X + (size_t)(m0 + ra + 64) * Kd + ka;
    const float* wp  = W0 + (size_t)(n0 + ra) * Kd + ka;
    int ca = ra ^ sw, ca1 = (ra + 64) ^ sw, cb = ca & 127;

    {
        float4 av0 = *(const float4*)(xp0);
        float4 av1 = *(const float4*)(xp1);
        float4 bv  = *(const float4*)(wp);
        As[0][ka+0][ca]  = f2tf32(av0.x); As[0][ka+1][ca]  = f2tf32(av0.y);
        As[0][ka+2][ca]  = f2tf32(av0.z); As[0][ka+3][ca]  = f2tf32(av0.w);
        As[0][ka+0][ca1] = f2tf32(av1.x); As[0][ka+1][ca1] = f2tf32(av1.y);
        As[0][ka+2][ca1] = f2tf32(av1.z); As[0][ka+3][ca1] = f2tf32(av1.w);
        Bs[0][ka+0][cb] = f2tf32(bv.x); Bs[0][ka+1][cb] = f2tf32(bv.y);
        Bs[0][ka+2][cb] = f2tf32(bv.z); Bs[0][ka+3][cb] = f2tf32(bv.w);
    }
    __syncthreads();

    const int NIT = Kd / 16;
    for (int it = 0; it < NIT; it++) {
        int cur = it & 1;
        float4 nav0, nav1, nbv;
        if (it + 1 < NIT) {
            int k0 = (it + 1) * 16;
            nav0 = *(const float4*)(xp0 + k0);
            nav1 = *(const float4*)(xp1 + k0);
            nbv  = *(const float4*)(wp  + k0);
        }
        #pragma unroll
        for (int ks = 0; ks < 16; ks += 8) {
            int swl = 8 * (ks >> 2), swh = swl + 8;
            int klo = ks + tig, khi = ks + tig + 4;
            unsigned a[2][4], b[4][2];
            #pragma unroll
            for (int mt = 0; mt < 2; mt++) {
                int mr = wm*32 + mt*16 + gid;
                a[mt][0] = __float_as_uint(As[cur][klo][ mr      ^ swl]);
                a[mt][1] = __float_as_uint(As[cur][klo][(mr + 8) ^ swl]);
                a[mt][2] = __float_as_uint(As[cur][khi][ mr      ^ swh]);
                a[mt][3] = __float_as_uint(As[cur][khi][(mr + 8) ^ swh]);
            }
            #pragma unroll
            for (int nt = 0; nt < 4; nt++) {
                int nc = wn*32 + nt*8 + gid;
                b[nt][0] = __float_as_uint(Bs[cur][klo][nc ^ swl]);
                b[nt][1] = __float_as_uint(Bs[cur][khi][nc ^ swh]);
            }
            #pragma unroll
            for (int mt = 0; mt < 2; mt++)
                #pragma unroll
                for (int nt = 0; nt < 4; nt++)
                    mma_tf32(c[mt][nt], a[mt], b[nt]);
        }
        if (it + 1 < NIT) {
            int nx = cur ^ 1;
            As[nx][ka+0][ca]  = f2tf32(nav0.x); As[nx][ka+1][ca]  = f2tf32(nav0.y);
            As[nx][ka+2][ca]  = f2tf32(nav0.z); As[nx][ka+3][ca]  = f2tf32(nav0.w);
            As[nx][ka+0][ca1] = f2tf32(nav1.x); As[nx][ka+1][ca1] = f2tf32(nav1.y);
            As[nx][ka+2][ca1] = f2tf32(nav1.z); As[nx][ka+3][ca1] = f2tf32(nav1.w);
            Bs[nx][ka+0][cb] = f2tf32(nbv.x); Bs[nx][ka+1][cb] = f2tf32(nbv.y);
            Bs[nx][ka+2][cb] = f2tf32(nbv.z); Bs[nx][ka+3][cb] = f2tf32(nbv.w);
        }
        __syncthreads();
    }
    #pragma unroll
    for (int mt = 0; mt < 2; mt++) {
        int r0 = m0 + wm*32 + mt*16 + gid;
        #pragma unroll
        for (int nt = 0; nt < 4; nt++) {
            int cc = n0 + wn*32 + nt*8 + tig*2;
            *(float2*)(C + (size_t)r0 * N + cc)     = make_float2(c[mt][nt][0], c[mt][nt][1]);
            *(float2*)(C + (size_t)(r0+8) * N + cc) = make_float2(c[mt][nt][2], c[mt][nt][3]);
        }
    }
}

// ======== combine v3: BK=32, epilogue scaling, dynamic smem ========
// acc_p = ws/wt @ V/ABR slice ; out = is*acc0 + it*acc1
__global__ __launch_bounds__(256)
void combine_tc3()
{
    extern __shared__ float dynsm[];
    // As: [buf][pass][k 32][col 72] ; Bs same, after As
    float (*As)[2][32][72] = (float (*)[2][32][72])dynsm;
    float (*Bs)[2][32][72] = (float (*)[2][32][72])(dynsm + 2*2*32*72);

    int bz = blockIdx.z;
    int b = bz / 3, t = bz % 3;
    const float* Wt = (t == 0) ? g_wap : (t == 1) ? g_wbd : g_wrs;
    int m0 = (int)(gridDim.y - 1 - blockIdx.y) * 64;   // longest blocks first
    int n0 = blockIdx.x * 64;
    int colbase = t * D3 + n0;

    int tid = threadIdx.x;
    int lane = tid & 31, warp = tid >> 5;
    int wm = warp & 3, wn = warp >> 2;
    int gid = lane >> 2, tig = lane & 3;

    float c[2][4][4];
    #pragma unroll
    for (int p = 0; p < 2; p++)
        #pragma unroll
        for (int nt = 0; nt < 4; nt++)
            #pragma unroll
            for (int e = 0; e < 4; e++) c[p][nt][e] = 0.f;

    int ra = tid >> 2;                  // A row (m) 0..63
    int ka = (tid & 3) * 4;             // A k 0..12
    int cA = ra ^ (8 * (tid & 3));      // A col swizzled (same for k and k+16)
    int kb = tid >> 4;                  // B k 0..15
    int nb = (tid & 15) * 4;            // B col
    int swb = 8 * ((kb >> 2) & 3);      // same for kb and kb+16
    int nbs = nb ^ swb;

    const float* aws = g_ws + (size_t)(b*Ss + m0 + ra) * Ss + ka;
    const float* awt = Wt   + (size_t)(b*Ss + m0 + ra) * Ss + ka;
    const float* bpv = g_V   + (size_t)(b*Ss + kb) * Dd + colbase + nb;
    const float* bpt = g_ABR + (size_t)(b*Ss + kb) * Dd + colbase + nb;

    const int NIT = m0/32 + 2;   // k in [0, m0+64)

    // prologue: fill buffer 0
    {
        float4 a00 = *(const float4*)(aws);
        float4 a01 = *(const float4*)(aws + 16);
        float4 a10 = *(const float4*)(awt);
        float4 a11 = *(const float4*)(awt + 16);
        float4 b00 = *(const float4*)(bpv);
        float4 b01 = *(const float4*)(bpv + (size_t)16 * Dd);
        float4 b10 = *(const float4*)(bpt);
        float4 b11 = *(const float4*)(bpt + (size_t)16 * Dd);
        As[0][0][ka+0][cA] = f2tf32(a00.x); As[0][0][ka+1][cA] = f2tf32(a00.y);
        As[0][0][ka+2][cA] = f2tf32(a00.z); As[0][0][ka+3][cA] = f2tf32(a00.w);
        As[0][0][ka+16][cA] = f2tf32(a01.x); As[0][0][ka+17][cA] = f2tf32(a01.y);
        As[0][0][ka+18][cA] = f2tf32(a01.z); As[0][0][ka+19][cA] = f2tf32(a01.w);
        As[0][1][ka+0][cA] = f2tf32(a10.x); As[0][1][ka+1][cA] = f2tf32(a10.y);
        As[0][1][ka+2][cA] = f2tf32(a10.z); As[0][1][ka+3][cA] = f2tf32(a10.w);
        As[0][1][ka+16][cA] = f2tf32(a11.x); As[0][1][ka+17][cA] = f2tf32(a11.y);
        As[0][1][ka+18][cA] = f2tf32(a11.z); As[0][1][ka+19][cA] = f2tf32(a11.w);
        *(float4*)&Bs[0][0][kb   ][nbs] = make_float4(f2tf32(b00.x), f2tf32(b00.y), f2tf32(b00.z), f2tf32(b00.w));
        *(float4*)&Bs[0][0][kb+16][nbs] = make_float4(f2tf32(b01.x), f2tf32(b01.y), f2tf32(b01.z), f2tf32(b01.w));
        *(float4*)&Bs[0][1][kb   ][nbs] = make_float4(f2tf32(b10.x), f2tf32(b10.y), f2tf32(b10.z), f2tf32(b10.w));
        *(float4*)&Bs[0][1][kb+16][nbs] = make_float4(f2tf32(b11.x), f2tf32(b11.y), f2tf32(b11.z), f2tf32(b11.w));
    }
    __syncthreads();

    for (int it = 0; it < NIT; it++) {
        int cur = it & 1;
        float4 a00, a01, a10, a11, b00, b01, b10, b11;
        if (it + 1 < NIT) {
            int k0 = (it + 1) * 32;
            a00 = *(const float4*)(aws + k0);
            a01 = *(const float4*)(aws + k0 + 16);
            a10 = *(const float4*)(awt + k0);
            a11 = *(const float4*)(awt + k0 + 16);
            b00 = *(const float4*)(bpv + (size_t)k0 * Dd);
            b01 = *(const float4*)(bpv + (size_t)(k0+16) * Dd);
            b10 = *(const float4*)(bpt + (size_t)k0 * Dd);
            b11 = *(const float4*)(bpt + (size_t)(k0+16) * Dd);
        }
        #pragma unroll
        for (int ks = 0; ks < 32; ks += 8) {
            int swl = 8 * ((ks >> 2) & 3);
            int swh = 8 * (((ks + 4) >> 2) & 3);
            int klo = ks + tig, khi = ks + tig + 4;
            int mr = wm*16 + gid;
            #pragma unroll
            for (int p = 0; p < 2; p++) {
                unsigned a[4], bfr[4][2];
                a[0] = __float_as_uint(As[cur][p][klo][ mr      ^ swl]);
                a[1] = __float_as_uint(As[cur][p][klo][(mr + 8) ^ swl]);
                a[2] = __float_as_uint(As[cur][p][khi][ mr      ^ swh]);
                a[3] = __float_as_uint(As[cur][p][khi][(mr + 8) ^ swh]);
                #pragma unroll
                for (int nt = 0; nt < 4; nt++) {
                    int nc = wn*32 + nt*8 + gid;
                    bfr[nt][0] = __float_as_uint(Bs[cur][p][klo][nc ^ swl]);
                    bfr[nt][1] = __float_as_uint(Bs[cur][p][khi][nc ^ swh]);
                }
                #pragma unroll
                for (int nt = 0; nt < 4; nt++)
                    mma_tf32(c[p][nt], a, bfr[nt]);
            }
        }
        if (it + 1 < NIT) {
            int nx = cur ^ 1;
            As[nx][0][ka+0][cA] = f2tf32(a00.x); As[nx][0][ka+1][cA] = f2tf32(a00.y);
            As[nx][0][ka+2][cA] = f2tf32(a00.z); As[nx][0][ka+3][cA] = f2tf32(a00.w);
            As[nx][0][ka+16][cA] = f2tf32(a01.x); As[nx][0][ka+17][cA] = f2tf32(a01.y);
            As[nx][0][ka+18][cA] = f2tf32(a01.z); As[nx][0][ka+19][cA] = f2tf32(a01.w);
            As[nx][1][ka+0][cA] = f2tf32(a10.x); As[nx][1][ka+1][cA] = f2tf32(a10.y);
            As[nx][1][ka+2][cA] = f2tf32(a10.z); As[nx][1][ka+3][cA] = f2tf32(a10.w);
            As[nx][1][ka+16][cA] = f2tf32(a11.x); As[nx][1][ka+17][cA] = f2tf32(a11.y);
            As[nx][1][ka+18][cA] = f2tf32(a11.z); As[nx][1][ka+19][cA] = f2tf32(a11.w);
            *(float4*)&Bs[nx][0][kb   ][nbs] = make_float4(f2tf32(b00.x), f2tf32(b00.y), f2tf32(b00.z), f2tf32(b00.w));
            *(float4*)&Bs[nx][0][kb+16][nbs] = make_float4(f2tf32(b01.x), f2tf32(b01.y), f2tf32(b01.z), f2tf32(b01.w));
            *(float4*)&Bs[nx][1][kb   ][nbs] = make_float4(f2tf32(b10.x), f2tf32(b10.y), f2tf32(b10.z), f2tf32(b10.w));
            *(float4*)&Bs[nx][1][kb+16][nbs] = make_float4(f2tf32(b11.x), f2tf32(b11.y), f2tf32(b11.z), f2tf32(b11.w));
        }
        __syncthreads();
    }

    // epilogue: scale by invden here (moved out of the k-loop)
    int r0 = m0 + wm*16 + gid;
    float is0 = g_invden[b*Ss + r0],     it0 = g_invden[(t+1)*BS + b*Ss + r0];
    float is1 = g_invden[b*Ss + r0 + 8], it1 = g_invden[(t+1)*BS + b*Ss + r0 + 8];
    int rg = b*Ss + r0;
    #pragma unroll
    for (int nt = 0; nt < 4; nt++) {
        int cc = colbase + wn*32 + nt*8 + tig*2;
        *(float2*)(g_comb + (size_t)rg * Dd + cc) =
            make_float2(is0*c[0][nt][0] + it0*c[1][nt][0],
                        is0*c[0][nt][1] + it0*c[1][nt][1]);
        *(float2*)(g_comb + (size_t)(rg+8) * Dd + cc) =
            make_float2(is1*c[0][nt][2] + it1*c[1][nt][2],
                        is1*c[0][nt][3] + it1*c[1][nt][3]);
    }
}

// ---------------- merged setup ----------------
__global__ __launch_bounds__(256)
void setup_kernel(const float* __restrict__ vemb, const float* __restrict__ spec,
                  const float* __restrict__ Wspec, const float* __restrict__ adj,
                  const float* __restrict__ vg)
{
    int tid = threadIdx.x;
    if (blockIdx.x == 0) {
        __shared__ float eb[NV*DV];
        __shared__ float adj_s[NV*NV];
        for (int t = tid; t < NV*DV; t += 256) {
            int u = t / DV, d = t % DV;
            float s = vemb[t];
            #pragma unroll
            for (int h = 0; h < 6; h++) s += 0.1f * spec[u*6+h] * Wspec[d*6+h];
            eb[t] = s;
        }
        for (int t = tid; t < NV*NV; t += 256) adj_s[t] = adj[t];
        __syncthreads();
        for (int t = tid; t < NV*DV; t += 256) {
            int v = t / DV, d = t % DV;
            float s = eb[t];
            #pragma unroll 8
            for (int u = 0; u < NV; u++) s += 0.1f * adj_s[u*NV + v] * eb[u*DV + d];
            g_emb2[t] = s;
        }
    } else {
        int v = blockIdx.x - 1;
        float s = 0.f;
        for (int c = tid; c < Dd; c += 256) {
            float x = vg[(size_t)v*Dd + c];
            s += 1.f / (1.f + __expf(-x));
        }
        __shared__ float red[256];
        red[tid] = s; __syncthreads();
        for (int off = 128; off; off >>= 1) {
            if (tid < off) red[tid] += red[tid + off];
            __syncthreads();
        }
        if (tid == 0) g_gm[v] = red[0] * (1.f / Dd);
    }
}

// ---------------- row-persistent attention ----------------
__global__ __launch_bounds__(256)
void attn_row(float* __restrict__ pi_out)
{
    int i = Ss - 1 - (int)blockIdx.x;     // longest rows launch first
    int b = blockIdx.y;
    int row_g = b*Ss + i;
    size_t rowbase = (size_t)row_g * Ss;
    int tid = threadIdx.x;
    int warp = tid >> 5, lane = tid & 31;
    int gid = lane >> 2, tig = lane & 3;

    __shared__ float Ks[256][36];
    __shared__ float Fs[32][72];
    __shared__ float q_s[DV];
    __shared__ float gm_s[NV];
    __shared__ float wred[8][4];

    if (tid < DV) q_s[tid] = g_QK[(size_t)row_g*64 + tid];
    if (tid >= 64 && tid < 128) gm_s[tid-64] = g_gm[tid-64];
    __syncthreads();
    for (int t = tid; t < 2048; t += 256) {
        int d = t >> 6, v = t & 63;
        Fs[d][v] = f2tf32(q_s[d] * g_emb2[v*DV + d]);
    }

    float gmr[16];
    #pragma unroll
    for (int nt = 0; nt < 8; nt++) {
        gmr[nt*2]   = gm_s[nt*8 + tig*2];
        gmr[nt*2+1] = gm_s[nt*8 + tig*2 + 1];
    }

    float bws = 0.f, bap = 0.f, bbd = 0.f, brs = 0.f;
    int ntiles = (i >> 8) + 1;

    for (int jt = 0; jt < ntiles; jt++) {
        int j0 = jt * 256;
        __syncthreads();
        for (int t = tid; t < 2048; t += 256) {
            int r = t >> 3, q = t & 7;
            float4 kv = *(const float4*)(g_QK + (size_t)(b*Ss + j0 + r)*64 + 32 + q*4);
            Ks[r][q*4+0] = f2tf32(kv.x); Ks[r][q*4+1] = f2tf32(kv.y);
            Ks[r][q*4+2] = f2tf32(kv.z); Ks[r][q*4+3] = f2tf32(kv.w);
        }
        __syncthreads();

        float c[2][8][4];
        #pragma unroll
        for (int mt = 0; mt < 2; mt++)
            #pragma unroll
            for (int nt = 0; nt < 8; nt++)
                #pragma unroll
                for (int e = 0; e < 4; e++) c[mt][nt][e] = 0.f;

        #pragma unroll
        for (int ks = 0; ks < 32; ks += 8) {
            unsigned a[2][4], bf[8][2];
            #pragma unroll
            for (int mt = 0; mt < 2; mt++) {
                int mr = warp*32 + mt*16 + gid;
                a[mt][0] = __float_as_uint(Ks[mr  ][ks+tig]);
                a[mt][1] = __float_as_uint(Ks[mr+8][ks+tig]);
                a[mt][2] = __float_as_uint(Ks[mr  ][ks+tig+4]);
                a[mt][3] = __float_as_uint(Ks[mr+8][ks+tig+4]);
            }
            #pragma unroll
            for (int nt = 0; nt < 8; nt++) {
                int nc = nt*8 + gid;
                bf[nt][0] = __float_as_uint(Fs[ks+tig  ][nc]);
                bf[nt][1] = __float_as_uint(Fs[ks+tig+4][nc]);
            }
            #pragma unroll
            for (int mt = 0; mt < 2; mt++)
                #pragma unroll
                for (int nt = 0; nt < 8; nt++)
                    mma_tf32(c[mt][nt], a[mt], bf[nt]);
        }

        #pragma unroll
        for (int mt = 0; mt < 2; mt++)
        #pragma unroll
        for (int rh = 0; rh < 2; rh++) {
            int j = j0 + warp*32 + mt*16 + rh*8 + gid;
            size_t pair = rowbase + j;
            float e[16];
            float sum = 0.f, sg = 0.f, sap = 0.f;
            #pragma unroll
            for (int q = 0; q < 16; q++) {
                float ev = __expf(c[mt][q>>1][rh*2 + (q&1)]);
                e[q] = ev;
                sum += ev;
                sg = fmaf(ev, gmr[q], sg);
                if (q & 1) sap += ev;
            }
            float sbd = (tig & 1) ? sum : 0.f;
            float srs = (tig & 2) ? sum : 0.f;
            sum += __shfl_xor_sync(0xffffffffu, sum, 1);
            sum += __shfl_xor_sync(0xffffffffu, sum, 2);
            sg  += __shfl_xor_sync(0xffffffffu, sg , 1);
            sg  += __shfl_xor_sync(0xffffffffu, sg , 2);
            sap += __shfl_xor_sync(0xffffffffu, sap, 1);
            sap += __shfl_xor_sync(0xffffffffu, sap, 2);
            sbd += __shfl_xor_sync(0xffffffffu, sbd, 1);
            sbd += __shfl_xor_sync(0xffffffffu, sbd, 2);
            srs += __shfl_xor_sync(0xffffffffu, srs, 1);
            srs += __shfl_xor_sync(0xffffffffu, srs, 2);

            float* po = pi_out + pair*NV + tig*2;
            if (j > i) {
                float2 z = make_float2(0.f, 0.f);
                #pragma unroll
                for (int nt = 0; nt < 8; nt++) __stcs((float2*)(po + nt*8), z);
                if (tig == 0) {
                    g_ws[pair] = 0.f; g_wap[pair] = 0.f;
                    g_wbd[pair] = 0.f; g_wrs[pair] = 0.f;
                }
            } else {
                float inv = 1.f / sum;
                #pragma unroll
                for (int nt = 0; nt < 8; nt++)
                    __stcs((float2*)(po + nt*8), make_float2(e[nt*2]*inv, e[nt*2+1]*inv));
                if (tig == 0) {
                    float ws = sg*inv, ap = sap*inv, bd = sbd*inv, rs = srs*inv;
                    g_ws[pair] = ws; g_wap[pair] = ap; g_wbd[pair] = bd; g_wrs[pair] = rs;
                    bws += ws; bap += ap; bbd += bd; brs += rs;
                }
            }
        }
    }

    {
        int jz0 = ntiles * 256;
        if (jz0 < Ss) {
            float4 z4 = make_float4(0.f,0.f,0.f,0.f);
            float4* base = (float4*)(pi_out + (rowbase + jz0) * NV);
            int n4 = (Ss - jz0) * 16;
            for (int t = tid; t < n4; t += 256) __stcs(base + t, z4);
            for (int j = jz0 + tid; j < Ss; j += 256) {
                size_t p = rowbase + j;
                g_ws[p] = 0.f; g_wap[p] = 0.f; g_wbd[p] = 0.f; g_wrs[p] = 0.f;
            }
        }
    }

    #pragma unroll
    for (int off = 16; off; off >>= 1) {
        bws += __shfl_xor_sync(0xffffffffu, bws, off);
        bap += __shfl_xor_sync(0xffffffffu, bap, off);
        bbd += __shfl_xor_sync(0xffffffffu, bbd, off);
        brs += __shfl_xor_sync(0xffffffffu, brs, off);
    }
    if (lane == 0) {
        wred[warp][0] = bws; wred[warp][1] = bap;
        wred[warp][2] = bbd; wred[warp][3] = brs;
    }
    __syncthreads();
    if (tid < 4) {
        float s = 0.f;
        #pragma unroll
        for (int w = 0; w < 8; w++) s += wred[w][tid];
        if (tid == 0) {
            g_invden[row_g] = 1.f / (s + EPSV);
        } else {
            float d1 = s + EPSV, S2 = s / d1;
            g_invden[tid*BS + row_g] = 1.f / (d1 * (S2 + EPSV));
        }
    }
}

// ---------------- layernorm ----------------
__global__ void ln_kernel(const float* __restrict__ bo, const float* __restrict__ gamma,
                          const float* __restrict__ beta, float* __restrict__ out)
{
    int row = blockIdx.x, tid = threadIdx.x;
    const float* r = g_res + (size_t)row * Dd;
    float v[3];
    float s = 0.f;
    #pragma unroll
    for (int q = 0; q < 3; q++) { int c = tid + q*256; v[q] = r[c] + bo[c]; s += v[q]; }
    __shared__ float red[256];
    __shared__ float mu_s, inv_s;
    red[tid] = s; __syncthreads();
    for (int off = 128; off; off >>= 1) {
        if (tid < off) red[tid] += red[tid + off];
        __syncthreads();
    }
    if (tid == 0) mu_s = red[0] * (1.f / Dd);
    __syncthreads();
    float mu = mu_s;
    float s2 = 0.f;
    #pragma unroll
    for (int q = 0; q < 3; q++) { float d = v[q] - mu; s2 += d*d; }
    __syncthreads();
    red[tid] = s2; __syncthreads();
    for (int off = 128; off; off >>= 1) {
        if (tid < off) red[tid] += red[tid + off];
        __syncthreads();
    }
    if (tid == 0) inv_s = rsqrtf(red[0] * (1.f / Dd) + LNEPS);
    __syncthreads();
    float inv = inv_s;
    #pragma unroll
    for (int q = 0; q < 3; q++) {
        int c = tid + q*256;
        out[(size_t)row*Dd + c] = (v[q] - mu) * inv * gamma[c] + beta[c];
    }
}

// ---------------- launch ----------------
extern "C" void kernel_launch(void* const* d_in, const int* in_sizes, int n_in,
                              void* d_out, int out_size)
{
    const float* x      = (const float*)d_in[0];
    const float* Wq     = (const float*)d_in[2];
    const float* Wk     = (const float*)d_in[3];
    const float* vemb   = (const float*)d_in[4];
    const float* vgates = (const float*)d_in[5];
    const float* Wv     = (const float*)d_in[6];
    const float* Wspec  = (const float*)d_in[7];
    const float* Wa     = (const float*)d_in[8];
    const float* Wb     = (const float*)d_in[9];
    const float* Wr     = (const float*)d_in[10];
    const float* Wo     = (const float*)d_in[11];
    const float* bo     = (const float*)d_in[12];
    const float* gamma  = (const float*)d_in[13];
    const float* beta   = (const float*)d_in[14];
    const float* adj    = (const float*)d_in[15];
    const float* spec   = (const float*)d_in[16];

    float* out    = (float*)d_out;
    float* pi_out = out + NORMED_ELEMS;

    float *pQK, *pV, *pABR, *pComb, *pRes;
    cudaGetSymbolAddress((void**)&pQK,   g_QK);
    cudaGetSymbolAddress((void**)&pV,    g_V);
    cudaGetSymbolAddress((void**)&pABR,  g_ABR);
    cudaGetSymbolAddress((void**)&pComb, g_comb);
    cudaGetSymbolAddress((void**)&pRes,  g_res);

    static int smem_set = 0;
    const int COMBINE_SMEM = 2*2*32*72*4 * 2;   // As + Bs = 73728 bytes
    if (!smem_set) {
        cudaFuncSetAttribute(combine_tc3, cudaFuncAttributeMaxDynamicSharedMemorySize, COMBINE_SMEM);
        smem_set = 1;
    }

    dim3 thr(256);
    setup_kernel<<<65, thr>>>(vemb, spec, Wspec, adj, vgates);
    gemm_fused<<<dim3(25, 16), thr>>>(x, Wq, Wk, Wv, Wa, Wb, Wr, pQK, pV, pABR);

    attn_row<<<dim3(Ss, Bb), thr>>>(pi_out);
    combine_tc3<<<dim3(4, 16, 6), thr, COMBINE_SMEM>>>();

    gemm_tc<<<dim3(12, 16), thr>>>(pComb, Wo, pRes, Dd);
    ln_kernel<<<BS, 256>>>(bo, gamma, beta, out);
}

// round 10
// speedup vs baseline: 4.4415x; 1.0460x over previous
#include <cuda_runtime.h>

#define Bb 2
#define Ss 1024
#define Dd 768
#define DV 32
#define NV 64
#define D3 256
#define BS (Bb*Ss)
#define Kd 768
#define EPSV 1e-8f
#define LNEPS 1e-5f
#define NORMED_ELEMS ((size_t)Bb*Ss*Dd)

// ---------------- scratch ----------------
__device__ float g_QK[BS*64];
__device__ float g_V[BS*Dd];
__device__ float g_ABR[BS*Dd];
__device__ float g_emb2[NV*DV];
__device__ float g_gm[NV];
__device__ float g_ws [(size_t)BS*Ss];
__device__ float g_wap[(size_t)BS*Ss];
__device__ float g_wbd[(size_t)BS*Ss];
__device__ float g_wrs[(size_t)BS*Ss];
__device__ float g_invden[4*BS];
__device__ float g_comb[BS*Dd];
__device__ float g_res[BS*Dd];

// ---------------- helpers ----------------
__device__ __forceinline__ float f2tf32(float f) {
    unsigned r;
    asm("cvt.rna.tf32.f32 %0, %1;" : "=r"(r) : "f"(f));
    return __uint_as_float(r);
}
__device__ __forceinline__ void mma_tf32(float* c, const unsigned* a, const unsigned* b) {
    asm volatile("mma.sync.aligned.m16n8k8.row.col.f32.tf32.tf32.f32 "
                 "{%0,%1,%2,%3}, {%4,%5,%6,%7}, {%8,%9}, {%0,%1,%2,%3};"
                 : "+f"(c[0]), "+f"(c[1]), "+f"(c[2]), "+f"(c[3])
                 : "r"(a[0]), "r"(a[1]), "r"(a[2]), "r"(a[3]), "r"(b[0]), "r"(b[1]));
}
__device__ __forceinline__ unsigned smem_u32(const void* p) {
    return (unsigned)__cvta_generic_to_shared(p);
}
#define CP_ASYNC16(dst, src) \
    asm volatile("cp.async.ca.shared.global [%0], [%1], 16;" :: "r"(dst), "l"(src))
#define CP_COMMIT() asm volatile("cp.async.commit_group;" ::: "memory")
#define CP_WAIT0()  asm volatile("cp.async.wait_group 0;" ::: "memory")

// ======== fused projection GEMM (BK=32, double-buffered) ========
__global__ __launch_bounds__(256)
void gemm_fused(const float* __restrict__ X,
                const float* __restrict__ Wq, const float* __restrict__ Wk,
                const float* __restrict__ Wv, const float* __restrict__ Wa,
                const float* __restrict__ Wb, const float* __restrict__ Wr,
                float* __restrict__ Cqk, float* __restrict__ Cv, float* __restrict__ Cabr)
{
    extern __shared__ float sm[];
    float (*As)[32][136] = (float (*)[32][136])sm;               // [2][32][136]
    float (*Bs)[32][72]  = (float (*)[32][72])(sm + 2*32*136);   // [2][32][72]

    int tid = threadIdx.x;
    int lane = tid & 31, warp = tid >> 5;
    int wm = warp & 3, wn = warp >> 2;
    int gid = lane >> 2, tig = lane & 3;
    int m0 = blockIdx.y * 128, n0 = blockIdx.x * 64;

    float c[2][4][4];
    #pragma unroll
    for (int mt = 0; mt < 2; mt++)
        #pragma unroll
        for (int nt = 0; nt < 4; nt++)
            #pragma unroll
            for (int e = 0; e < 4; e++) c[mt][nt][e] = 0.f;

    int ra = tid >> 2;
    int ka = (tid & 3) * 4;
    int sw = 8 * (tid & 3);
    const float* xp0 = X + (size_t)(m0 + ra) * Kd + ka;
    const float* xp1 = X + (size_t)(m0 + ra + 64) * Kd + ka;
    int rW = n0 + ra;
    const float* wp;
    if      (rW <   32) wp = Wq + (size_t)rW * Kd;
    else if (rW <   64) wp = Wk + (size_t)(rW -   32) * Kd;
    else if (rW <  832) wp = Wv + (size_t)(rW -   64) * Kd;
    else if (rW < 1088) wp = Wa + (size_t)(rW -  832) * Kd;
    else if (rW < 1344) wp = Wb + (size_t)(rW - 1088) * Kd;
    else                wp = Wr + (size_t)(rW - 1344) * Kd;
    wp += ka;

    int ca = ra ^ sw, ca1 = (ra + 64) ^ sw;

    // prologue: buffer 0
    {
        float4 a00 = *(const float4*)(xp0);
        float4 a01 = *(const float4*)(xp0 + 16);
        float4 a10 = *(const float4*)(xp1);
        float4 a11 = *(const float4*)(xp1 + 16);
        float4 b0  = *(const float4*)(wp);
        float4 b1  = *(const float4*)(wp + 16);
        As[0][ka+0][ca]  = f2tf32(a00.x); As[0][ka+1][ca]  = f2tf32(a00.y);
        As[0][ka+2][ca]  = f2tf32(a00.z); As[0][ka+3][ca]  = f2tf32(a00.w);
        As[0][ka+16][ca] = f2tf32(a01.x); As[0][ka+17][ca] = f2tf32(a01.y);
        As[0][ka+18][ca] = f2tf32(a01.z); As[0][ka+19][ca] = f2tf32(a01.w);
        As[0][ka+0][ca1]  = f2tf32(a10.x); As[0][ka+1][ca1]  = f2tf32(a10.y);
        As[0][ka+2][ca1]  = f2tf32(a10.z); As[0][ka+3][ca1]  = f2tf32(a10.w);
        As[0][ka+16][ca1] = f2tf32(a11.x); As[0][ka+17][ca1] = f2tf32(a11.y);
        As[0][ka+18][ca1] = f2tf32(a11.z); As[0][ka+19][ca1] = f2tf32(a11.w);
        Bs[0][ka+0][ca]  = f2tf32(b0.x); Bs[0][ka+1][ca]  = f2tf32(b0.y);
        Bs[0][ka+2][ca]  = f2tf32(b0.z); Bs[0][ka+3][ca]  = f2tf32(b0.w);
        Bs[0][ka+16][ca] = f2tf32(b1.x); Bs[0][ka+17][ca] = f2tf32(b1.y);
        Bs[0][ka+18][ca] = f2tf32(b1.z); Bs[0][ka+19][ca] = f2tf32(b1.w);
    }
    __syncthreads();

    const int NIT = Kd / 32;   // 24
    for (int it = 0; it < NIT; it++) {
        int cur = it & 1;
        float4 a00, a01, a10, a11, b0, b1;
        if (it + 1 < NIT) {
            int k0 = (it + 1) * 32;
            a00 = *(const float4*)(xp0 + k0);
            a01 = *(const float4*)(xp0 + k0 + 16);
            a10 = *(const float4*)(xp1 + k0);
            a11 = *(const float4*)(xp1 + k0 + 16);
            b0  = *(const float4*)(wp  + k0);
            b1  = *(const float4*)(wp  + k0 + 16);
        }
        #pragma unroll
        for (int ks = 0; ks < 32; ks += 8) {
            int swl = 8 * ((ks >> 2) & 3);
            int swh = 8 * (((ks + 4) >> 2) & 3);
            int klo = ks + tig, khi = ks + tig + 4;
            unsigned a[2][4], b[4][2];
            #pragma unroll
            for (int mt = 0; mt < 2; mt++) {
                int mr = wm*32 + mt*16 + gid;
                a[mt][0] = __float_as_uint(As[cur][klo][ mr      ^ swl]);
                a[mt][1] = __float_as_uint(As[cur][klo][(mr + 8) ^ swl]);
                a[mt][2] = __float_as_uint(As[cur][khi][ mr      ^ swh]);
                a[mt][3] = __float_as_uint(As[cur][khi][(mr + 8) ^ swh]);
            }
            #pragma unroll
            for (int nt = 0; nt < 4; nt++) {
                int nc = wn*32 + nt*8 + gid;
                b[nt][0] = __float_as_uint(Bs[cur][klo][nc ^ swl]);
                b[nt][1] = __float_as_uint(Bs[cur][khi][nc ^ swh]);
            }
            #pragma unroll
            for (int mt = 0; mt < 2; mt++)
                #pragma unroll
                for (int nt = 0; nt < 4; nt++)
                    mma_tf32(c[mt][nt], a[mt], b[nt]);
        }
        if (it + 1 < NIT) {
            int nx = cur ^ 1;
            As[nx][ka+0][ca]  = f2tf32(a00.x); As[nx][ka+1][ca]  = f2tf32(a00.y);
            As[nx][ka+2][ca]  = f2tf32(a00.z); As[nx][ka+3][ca]  = f2tf32(a00.w);
            As[nx][ka+16][ca] = f2tf32(a01.x); As[nx][ka+17][ca] = f2tf32(a01.y);
            As[nx][ka+18][ca] = f2tf32(a01.z); As[nx][ka+19][ca] = f2tf32(a01.w);
            As[nx][ka+0][ca1]  = f2tf32(a10.x); As[nx][ka+1][ca1]  = f2tf32(a10.y);
            As[nx][ka+2][ca1]  = f2tf32(a10.z); As[nx][ka+3][ca1]  = f2tf32(a10.w);
            As[nx][ka+16][ca1] = f2tf32(a11.x); As[nx][ka+17][ca1] = f2tf32(a11.y);
            As[nx][ka+18][ca1] = f2tf32(a11.z); As[nx][ka+19][ca1] = f2tf32(a11.w);
            Bs[nx][ka+0][ca]  = f2tf32(b0.x); Bs[nx][ka+1][ca]  = f2tf32(b0.y);
            Bs[nx][ka+2][ca]  = f2tf32(b0.z); Bs[nx][ka+3][ca]  = f2tf32(b0.w);
            Bs[nx][ka+16][ca] = f2tf32(b1.x); Bs[nx][ka+17][ca] = f2tf32(b1.y);
            Bs[nx][ka+18][ca] = f2tf32(b1.z); Bs[nx][ka+19][ca] = f2tf32(b1.w);
        }
        __syncthreads();
    }

    float* Cd; int strideN, cbase;
    if (n0 == 0)       { Cd = Cqk;  strideN = 64;  cbase = 0; }
    else if (n0 < 832) { Cd = Cv;   strideN = Dd;  cbase = n0 - 64; }
    else               { Cd = Cabr; strideN = Dd;  cbase = n0 - 832; }

    #pragma unroll
    for (int mt = 0; mt < 2; mt++) {
        int r0 = m0 + wm*32 + mt*16 + gid;
        #pragma unroll
        for (int nt = 0; nt < 4; nt++) {
            int cc = cbase + wn*32 + nt*8 + tig*2;
            *(float2*)(Cd + (size_t)r0 * strideN + cc)     = make_float2(c[mt][nt][0], c[mt][nt][1]);
            *(float2*)(Cd + (size_t)(r0+8) * strideN + cc) = make_float2(c[mt][nt][2], c[mt][nt][3]);
        }
    }
}

// ======== generic GEMM (BK=32, used for Wo) ========
__global__ __launch_bounds__(256)
void gemm_tc(const float* __restrict__ X, const float* __restrict__ W0,
             float* __restrict__ C, int N)
{
    extern __shared__ float sm[];
    float (*As)[32][136] = (float (*)[32][136])sm;
    float (*Bs)[32][72]  = (float (*)[32][72])(sm + 2*32*136);

    int tid = threadIdx.x;
    int lane = tid & 31, warp = tid >> 5;
    int wm = warp & 3, wn = warp >> 2;
    int gid = lane >> 2, tig = lane & 3;
    int m0 = blockIdx.y * 128, n0 = blockIdx.x * 64;

    float c[2][4][4];
    #pragma unroll
    for (int mt = 0; mt < 2; mt++)
        #pragma unroll
        for (int nt = 0; nt < 4; nt++)
            #pragma unroll
            for (int e = 0; e < 4; e++) c[mt][nt][e] = 0.f;

    int ra = tid >> 2;
    int ka = (tid & 3) * 4;
    int sw = 8 * (tid & 3);
    const float* xp0 = X + (size_t)(m0 + ra) * Kd + ka;
    const float* xp1 = X + (size_t)(m0 + ra + 64) * Kd + ka;
    const float* wp  = W0 + (size_t)(n0 + ra) * Kd + ka;
    int ca = ra ^ sw, ca1 = (ra + 64) ^ sw;

    {
        float4 a00 = *(const float4*)(xp0);
        float4 a01 = *(const float4*)(xp0 + 16);
        float4 a10 = *(const float4*)(xp1);
        float4 a11 = *(const float4*)(xp1 + 16);
        float4 b0  = *(const float4*)(wp);
        float4 b1  = *(const float4*)(wp + 16);
        As[0][ka+0][ca]  = f2tf32(a00.x); As[0][ka+1][ca]  = f2tf32(a00.y);
        As[0][ka+2][ca]  = f2tf32(a00.z); As[0][ka+3][ca]  = f2tf32(a00.w);
        As[0][ka+16][ca] = f2tf32(a01.x); As[0][ka+17][ca] = f2tf32(a01.y);
        As[0][ka+18][ca] = f2tf32(a01.z); As[0][ka+19][ca] = f2tf32(a01.w);
        As[0][ka+0][ca1]  = f2tf32(a10.x); As[0][ka+1][ca1]  = f2tf32(a10.y);
        As[0][ka+2][ca1]  = f2tf32(a10.z); As[0][ka+3][ca1]  = f2tf32(a10.w);
        As[0][ka+16][ca1] = f2tf32(a11.x); As[0][ka+17][ca1] = f2tf32(a11.y);
        As[0][ka+18][ca1] = f2tf32(a11.z); As[0][ka+19][ca1] = f2tf32(a11.w);
        Bs[0][ka+0][ca]  = f2tf32(b0.x); Bs[0][ka+1][ca]  = f2tf32(b0.y);
        Bs[0][ka+2][ca]  = f2tf32(b0.z); Bs[0][ka+3][ca]  = f2tf32(b0.w);
        Bs[0][ka+16][ca] = f2tf32(b1.x); Bs[0][ka+17][ca] = f2tf32(b1.y);
        Bs[0][ka+18][ca] = f2tf32(b1.z); Bs[0][ka+19][ca] = f2tf32(b1.w);
    }
    __syncthreads();

    const int NIT = Kd / 32;
    for (int it = 0; it < NIT; it++) {
        int cur = it & 1;
        float4 a00, a01, a10, a11, b0, b1;
        if (it + 1 < NIT) {
            int k0 = (it + 1) * 32;
            a00 = *(const float4*)(xp0 + k0);
            a01 = *(const float4*)(xp0 + k0 + 16);
            a10 = *(const float4*)(xp1 + k0);
            a11 = *(const float4*)(xp1 + k0 + 16);
            b0  = *(const float4*)(wp  + k0);
            b1  = *(const float4*)(wp  + k0 + 16);
        }
        #pragma unroll
        for (int ks = 0; ks < 32; ks += 8) {
            int swl = 8 * ((ks >> 2) & 3);
            int swh = 8 * (((ks + 4) >> 2) & 3);
            int klo = ks + tig, khi = ks + tig + 4;
            unsigned a[2][4], b[4][2];
            #pragma unroll
            for (int mt = 0; mt < 2; mt++) {
                int mr = wm*32 + mt*16 + gid;
                a[mt][0] = __float_as_uint(As[cur][klo][ mr      ^ swl]);
                a[mt][1] = __float_as_uint(As[cur][klo][(mr + 8) ^ swl]);
                a[mt][2] = __float_as_uint(As[cur][khi][ mr      ^ swh]);
                a[mt][3] = __float_as_uint(As[cur][khi][(mr + 8) ^ swh]);
            }
            #pragma unroll
            for (int nt = 0; nt < 4; nt++) {
                int nc = wn*32 + nt*8 + gid;
                b[nt][0] = __float_as_uint(Bs[cur][klo][nc ^ swl]);
                b[nt][1] = __float_as_uint(Bs[cur][khi][nc ^ swh]);
            }
            #pragma unroll
            for (int mt = 0; mt < 2; mt++)
                #pragma unroll
                for (int nt = 0; nt < 4; nt++)
                    mma_tf32(c[mt][nt], a[mt], b[nt]);
        }
        if (it + 1 < NIT) {
            int nx = cur ^ 1;
            As[nx][ka+0][ca]  = f2tf32(a00.x); As[nx][ka+1][ca]  = f2tf32(a00.y);
            As[nx][ka+2][ca]  = f2tf32(a00.z); As[nx][ka+3][ca]  = f2tf32(a00.w);
            As[nx][ka+16][ca] = f2tf32(a01.x); As[nx][ka+17][ca] = f2tf32(a01.y);
            As[nx][ka+18][ca] = f2tf32(a01.z); As[nx][ka+19][ca] = f2tf32(a01.w);
            As[nx][ka+0][ca1]  = f2tf32(a10.x); As[nx][ka+1][ca1]  = f2tf32(a10.y);
            As[nx][ka+2][ca1]  = f2tf32(a10.z); As[nx][ka+3][ca1]  = f2tf32(a10.w);
            As[nx][ka+16][ca1] = f2tf32(a11.x); As[nx][ka+17][ca1] = f2tf32(a11.y);
            As[nx][ka+18][ca1] = f2tf32(a11.z); As[nx][ka+19][ca1] = f2tf32(a11.w);
            Bs[nx][ka+0][ca]  = f2tf32(b0.x); Bs[nx][ka+1][ca]  = f2tf32(b0.y);
            Bs[nx][ka+2][ca]  = f2tf32(b0.z); Bs[nx][ka+3][ca]  = f2tf32(b0.w);
            Bs[nx][ka+16][ca] = f2tf32(b1.x); Bs[nx][ka+17][ca] = f2tf32(b1.y);
            Bs[nx][ka+18][ca] = f2tf32(b1.z); Bs[nx][ka+19][ca] = f2tf32(b1.w);
        }
        __syncthreads();
    }
    #pragma unroll
    for (int mt = 0; mt < 2; mt++) {
        int r0 = m0 + wm*32 + mt*16 + gid;
        #pragma unroll
        for (int nt = 0; nt < 4; nt++) {
            int cc = n0 + wn*32 + nt*8 + tig*2;
            *(float2*)(C + (size_t)r0 * N + cc)     = make_float2(c[mt][nt][0], c[mt][nt][1]);
            *(float2*)(C + (size_t)(r0+8) * N + cc) = make_float2(c[mt][nt][2], c[mt][nt][3]);
        }
    }
}

// ======== combine v3 (unchanged from round 9) ========
__global__ __launch_bounds__(256)
void combine_tc3()
{
    extern __shared__ float dynsm[];
    float (*As)[2][32][72] = (float (*)[2][32][72])dynsm;
    float (*Bs)[2][32][72] = (float (*)[2][32][72])(dynsm + 2*2*32*72);

    int bz = blockIdx.z;
    int b = bz / 3, t = bz % 3;
    const float* Wt = (t == 0) ? g_wap : (t == 1) ? g_wbd : g_wrs;
    int m0 = (int)(gridDim.y - 1 - blockIdx.y) * 64;
    int n0 = blockIdx.x * 64;
    int colbase = t * D3 + n0;

    int tid = threadIdx.x;
    int lane = tid & 31, warp = tid >> 5;
    int wm = warp & 3, wn = warp >> 2;
    int gid = lane >> 2, tig = lane & 3;

    float c[2][4][4];
    #pragma unroll
    for (int p = 0; p < 2; p++)
        #pragma unroll
        for (int nt = 0; nt < 4; nt++)
            #pragma unroll
            for (int e = 0; e < 4; e++) c[p][nt][e] = 0.f;

    int ra = tid >> 2;
    int ka = (tid & 3) * 4;
    int cA = ra ^ (8 * (tid & 3));
    int kb = tid >> 4;
    int nb = (tid & 15) * 4;
    int swb = 8 * ((kb >> 2) & 3);
    int nbs = nb ^ swb;

    const float* aws = g_ws + (size_t)(b*Ss + m0 + ra) * Ss + ka;
    const float* awt = Wt   + (size_t)(b*Ss + m0 + ra) * Ss + ka;
    const float* bpv = g_V   + (size_t)(b*Ss + kb) * Dd + colbase + nb;
    const float* bpt = g_ABR + (size_t)(b*Ss + kb) * Dd + colbase + nb;

    const int NIT = m0/32 + 2;

    {
        float4 a00 = *(const float4*)(aws);
        float4 a01 = *(const float4*)(aws + 16);
        float4 a10 = *(const float4*)(awt);
        float4 a11 = *(const float4*)(awt + 16);
        float4 b00 = *(const float4*)(bpv);
        float4 b01 = *(const float4*)(bpv + (size_t)16 * Dd);
        float4 b10 = *(const float4*)(bpt);
        float4 b11 = *(const float4*)(bpt + (size_t)16 * Dd);
        As[0][0][ka+0][cA] = f2tf32(a00.x); As[0][0][ka+1][cA] = f2tf32(a00.y);
        As[0][0][ka+2][cA] = f2tf32(a00.z); As[0][0][ka+3][cA] = f2tf32(a00.w);
        As[0][0][ka+16][cA] = f2tf32(a01.x); As[0][0][ka+17][cA] = f2tf32(a01.y);
        As[0][0][ka+18][cA] = f2tf32(a01.z); As[0][0][ka+19][cA] = f2tf32(a01.w);
        As[0][1][ka+0][cA] = f2tf32(a10.x); As[0][1][ka+1][cA] = f2tf32(a10.y);
        As[0][1][ka+2][cA] = f2tf32(a10.z); As[0][1][ka+3][cA] = f2tf32(a10.w);
        As[0][1][ka+16][cA] = f2tf32(a11.x); As[0][1][ka+17][cA] = f2tf32(a11.y);
        As[0][1][ka+18][cA] = f2tf32(a11.z); As[0][1][ka+19][cA] = f2tf32(a11.w);
        *(float4*)&Bs[0][0][kb   ][nbs] = make_float4(f2tf32(b00.x), f2tf32(b00.y), f2tf32(b00.z), f2tf32(b00.w));
        *(float4*)&Bs[0][0][kb+16][nbs] = make_float4(f2tf32(b01.x), f2tf32(b01.y), f2tf32(b01.z), f2tf32(b01.w));
        *(float4*)&Bs[0][1][kb   ][nbs] = make_float4(f2tf32(b10.x), f2tf32(b10.y), f2tf32(b10.z), f2tf32(b10.w));
        *(float4*)&Bs[0][1][kb+16][nbs] = make_float4(f2tf32(b11.x), f2tf32(b11.y), f2tf32(b11.z), f2tf32(b11.w));
    }
    __syncthreads();

    for (int it = 0; it < NIT; it++) {
        int cur = it & 1;
        float4 a00, a01, a10, a11, b00, b01, b10, b11;
        if (it + 1 < NIT) {
            int k0 = (it + 1) * 32;
            a00 = *(const float4*)(aws + k0);
            a01 = *(const float4*)(aws + k0 + 16);
            a10 = *(const float4*)(awt + k0);
            a11 = *(const float4*)(awt + k0 + 16);
            b00 = *(const float4*)(bpv + (size_t)k0 * Dd);
            b01 = *(const float4*)(bpv + (size_t)(k0+16) * Dd);
            b10 = *(const float4*)(bpt + (size_t)k0 * Dd);
            b11 = *(const float4*)(bpt + (size_t)(k0+16) * Dd);
        }
        #pragma unroll
        for (int ks = 0; ks < 32; ks += 8) {
            int swl = 8 * ((ks >> 2) & 3);
            int swh = 8 * (((ks + 4) >> 2) & 3);
            int klo = ks + tig, khi = ks + tig + 4;
            int mr = wm*16 + gid;
            #pragma unroll
            for (int p = 0; p < 2; p++) {
                unsigned a[4], bfr[4][2];
                a[0] = __float_as_uint(As[cur][p][klo][ mr      ^ swl]);
                a[1] = __float_as_uint(As[cur][p][klo][(mr + 8) ^ swl]);
                a[2] = __float_as_uint(As[cur][p][khi][ mr      ^ swh]);
                a[3] = __float_as_uint(As[cur][p][khi][(mr + 8) ^ swh]);
                #pragma unroll
                for (int nt = 0; nt < 4; nt++) {
                    int nc = wn*32 + nt*8 + gid;
                    bfr[nt][0] = __float_as_uint(Bs[cur][p][klo][nc ^ swl]);
                    bfr[nt][1] = __float_as_uint(Bs[cur][p][khi][nc ^ swh]);
                }
                #pragma unroll
                for (int nt = 0; nt < 4; nt++)
                    mma_tf32(c[p][nt], a, bfr[nt]);
            }
        }
        if (it + 1 < NIT) {
            int nx = cur ^ 1;
            As[nx][0][ka+0][cA] = f2tf32(a00.x); As[nx][0][ka+1][cA] = f2tf32(a00.y);
            As[nx][0][ka+2][cA] = f2tf32(a00.z); As[nx][0][ka+3][cA] = f2tf32(a00.w);
            As[nx][0][ka+16][cA] = f2tf32(a01.x); As[nx][0][ka+17][cA] = f2tf32(a01.y);
            As[nx][0][ka+18][cA] = f2tf32(a01.z); As[nx][0][ka+19][cA] = f2tf32(a01.w);
            As[nx][1][ka+0][cA] = f2tf32(a10.x); As[nx][1][ka+1][cA] = f2tf32(a10.y);
            As[nx][1][ka+2][cA] = f2tf32(a10.z); As[nx][1][ka+3][cA] = f2tf32(a10.w);
            As[nx][1][ka+16][cA] = f2tf32(a11.x); As[nx][1][ka+17][cA] = f2tf32(a11.y);
            As[nx][1][ka+18][cA] = f2tf32(a11.z); As[nx][1][ka+19][cA] = f2tf32(a11.w);
            *(float4*)&Bs[nx][0][kb   ][nbs] = make_float4(f2tf32(b00.x), f2tf32(b00.y), f2tf32(b00.z), f2tf32(b00.w));
            *(float4*)&Bs[nx][0][kb+16][nbs] = make_float4(f2tf32(b01.x), f2tf32(b01.y), f2tf32(b01.z), f2tf32(b01.w));
            *(float4*)&Bs[nx][1][kb   ][nbs] = make_float4(f2tf32(b10.x), f2tf32(b10.y), f2tf32(b10.z), f2tf32(b10.w));
            *(float4*)&Bs[nx][1][kb+16][nbs] = make_float4(f2tf32(b11.x), f2tf32(b11.y), f2tf32(b11.z), f2tf32(b11.w));
        }
        __syncthreads();
    }

    int r0 = m0 + wm*16 + gid;
    float is0 = g_invden[b*Ss + r0],     it0 = g_invden[(t+1)*BS + b*Ss + r0];
    float is1 = g_invden[b*Ss + r0 + 8], it1 = g_invden[(t+1)*BS + b*Ss + r0 + 8];
    int rg = b*Ss + r0;
    #pragma unroll
    for (int nt = 0; nt < 4; nt++) {
        int cc = colbase + wn*32 + nt*8 + tig*2;
        *(float2*)(g_comb + (size_t)rg * Dd + cc) =
            make_float2(is0*c[0][nt][0] + it0*c[1][nt][0],
                        is0*c[0][nt][1] + it0*c[1][nt][1]);
        *(float2*)(g_comb + (size_t)(rg+8) * Dd + cc) =
            make_float2(is1*c[0][nt][2] + it1*c[1][nt][2],
                        is1*c[0][nt][3] + it1*c[1][nt][3]);
    }
}

// ---------------- merged setup ----------------
__global__ __launch_bounds__(256)
void setup_kernel(const float* __restrict__ vemb, const float* __restrict__ spec,
                  const float* __restrict__ Wspec, const float* __restrict__ adj,
                  const float* __restrict__ vg)
{
    int tid = threadIdx.x;
    if (blockIdx.x == 0) {
        __shared__ float eb[NV*DV];
        __shared__ float adj_s[NV*NV];
        for (int t = tid; t < NV*DV; t += 256) {
            int u = t / DV, d = t % DV;
            float s = vemb[t];
            #pragma unroll
            for (int h = 0; h < 6; h++) s += 0.1f * spec[u*6+h] * Wspec[d*6+h];
            eb[t] = s;
        }
        for (int t = tid; t < NV*NV; t += 256) adj_s[t] = adj[t];
        __syncthreads();
        for (int t = tid; t < NV*DV; t += 256) {
            int v = t / DV, d = t % DV;
            float s = eb[t];
            #pragma unroll 8
            for (int u = 0; u < NV; u++) s += 0.1f * adj_s[u*NV + v] * eb[u*DV + d];
            g_emb2[t] = s;
        }
    } else {
        int v = blockIdx.x - 1;
        float s = 0.f;
        for (int c = tid; c < Dd; c += 256) {
            float x = vg[(size_t)v*Dd + c];
            s += 1.f / (1.f + __expf(-x));
        }
        __shared__ float red[256];
        red[tid] = s; __syncthreads();
        for (int off = 128; off; off >>= 1) {
            if (tid < off) red[tid] += red[tid + off];
            __syncthreads();
        }
        if (tid == 0) g_gm[v] = red[0] * (1.f / Dd);
    }
}

// ---------------- row-persistent attention with cp.async Ks pipeline ----------------
__global__ __launch_bounds__(256)
void attn_row(float* __restrict__ pi_out)
{
    extern __shared__ float sm[];
    float (*Ks)[256][36] = (float (*)[256][36])sm;     // [2][256][36], raw fp32
    float* Fs = sm + 2*256*36;                          // [32][72], tf32

    int i = Ss - 1 - (int)blockIdx.x;
    int b = blockIdx.y;
    int row_g = b*Ss + i;
    size_t rowbase = (size_t)row_g * Ss;
    int tid = threadIdx.x;
    int warp = tid >> 5, lane = tid & 31;
    int gid = lane >> 2, tig = lane & 3;

    __shared__ float q_s[DV];
    __shared__ float gm_s[NV];
    __shared__ float wred[8][4];

    if (tid < DV) q_s[tid] = g_QK[(size_t)row_g*64 + tid];
    if (tid >= 64 && tid < 128) gm_s[tid-64] = g_gm[tid-64];
    __syncthreads();
    for (int t = tid; t < 2048; t += 256) {
        int d = t >> 6, v = t & 63;
        Fs[d*72 + v] = f2tf32(q_s[d] * g_emb2[v*DV + d]);
    }

    float gmr[16];
    #pragma unroll
    for (int nt = 0; nt < 8; nt++) {
        gmr[nt*2]   = gm_s[nt*8 + tig*2];
        gmr[nt*2+1] = gm_s[nt*8 + tig*2 + 1];
    }

    float bws = 0.f, bap = 0.f, bbd = 0.f, brs = 0.f;
    int ntiles = (i >> 8) + 1;
    int kr = tid >> 3, kq = (tid & 7) * 4;   // K load: 32 rows per pass of 256 thr

    // prologue: async-load tile 0 into buffer 0
    #pragma unroll
    for (int pp = 0; pp < 8; pp++) {
        int r = kr + pp*32;
        unsigned dst = smem_u32(&Ks[0][r][kq]);
        CP_ASYNC16(dst, g_QK + (size_t)(b*Ss + r)*64 + 32 + kq);
    }
    CP_COMMIT();

    for (int jt = 0; jt < ntiles; jt++) {
        int j0 = jt * 256;
        int cur = jt & 1;
        CP_WAIT0();
        __syncthreads();

        float c[2][8][4];
        #pragma unroll
        for (int mt = 0; mt < 2; mt++)
            #pragma unroll
            for (int nt = 0; nt < 8; nt++)
                #pragma unroll
                for (int e = 0; e < 4; e++) c[mt][nt][e] = 0.f;

        #pragma unroll
        for (int ks = 0; ks < 32; ks += 8) {
            unsigned a[2][4], bf[8][2];
            #pragma unroll
            for (int mt = 0; mt < 2; mt++) {
                int mr = warp*32 + mt*16 + gid;
                a[mt][0] = __float_as_uint(f2tf32(Ks[cur][mr  ][ks+tig]));
                a[mt][1] = __float_as_uint(f2tf32(Ks[cur][mr+8][ks+tig]));
                a[mt][2] = __float_as_uint(f2tf32(Ks[cur][mr  ][ks+tig+4]));
                a[mt][3] = __float_as_uint(f2tf32(Ks[cur][mr+8][ks+tig+4]));
            }
            #pragma unroll
            for (int nt = 0; nt < 8; nt++) {
                int nc = nt*8 + gid;
                bf[nt][0] = __float_as_uint(Fs[(ks+tig  )*72 + nc]);
                bf[nt][1] = __float_as_uint(Fs[(ks+tig+4)*72 + nc]);
            }
            #pragma unroll
            for (int mt = 0; mt < 2; mt++)
                #pragma unroll
                for (int nt = 0; nt < 8; nt++)
                    mma_tf32(c[mt][nt], a[mt], bf[nt]);
        }

        // issue next tile's loads before the epilogue (overlap)
        if (jt + 1 < ntiles) {
            int j0n = (jt + 1) * 256;
            int nx = cur ^ 1;
            #pragma unroll
            for (int pp = 0; pp < 8; pp++) {
                int r = kr + pp*32;
                unsigned dst = smem_u32(&Ks[nx][r][kq]);
                CP_ASYNC16(dst, g_QK + (size_t)(b*Ss + j0n + r)*64 + 32 + kq);
            }
            CP_COMMIT();
        }

        #pragma unroll
        for (int mt = 0; mt < 2; mt++)
        #pragma unroll
        for (int rh = 0; rh < 2; rh++) {
            int j = j0 + warp*32 + mt*16 + rh*8 + gid;
            size_t pair = rowbase + j;
            float e[16];
            float sum = 0.f, sg = 0.f, sap = 0.f;
            #pragma unroll
            for (int q = 0; q < 16; q++) {
                float ev = __expf(c[mt][q>>1][rh*2 + (q&1)]);
                e[q] = ev;
                sum += ev;
                sg = fmaf(ev, gmr[q], sg);
                if (q & 1) sap += ev;
            }
            float sbd = (tig & 1) ? sum : 0.f;
            float srs = (tig & 2) ? sum : 0.f;
            sum += __shfl_xor_sync(0xffffffffu, sum, 1);
            sum += __shfl_xor_sync(0xffffffffu, sum, 2);
            sg  += __shfl_xor_sync(0xffffffffu, sg , 1);
            sg  += __shfl_xor_sync(0xffffffffu, sg , 2);
            sap += __shfl_xor_sync(0xffffffffu, sap, 1);
            sap += __shfl_xor_sync(0xffffffffu, sap, 2);
            sbd += __shfl_xor_sync(0xffffffffu, sbd, 1);
            sbd += __shfl_xor_sync(0xffffffffu, sbd, 2);
            srs += __shfl_xor_sync(0xffffffffu, srs, 1);
            srs += __shfl_xor_sync(0xffffffffu, srs, 2);

            float* po = pi_out + pair*NV + tig*2;
            if (j > i) {
                float2 z = make_float2(0.f, 0.f);
                #pragma unroll
                for (int nt = 0; nt < 8; nt++) __stcs((float2*)(po + nt*8), z);
                if (tig == 0) {
                    g_ws[pair] = 0.f; g_wap[pair] = 0.f;
                    g_wbd[pair] = 0.f; g_wrs[pair] = 0.f;
                }
            } else {
                float inv = 1.f / sum;
                #pragma unroll
                for (int nt = 0; nt < 8; nt++)
                    __stcs((float2*)(po + nt*8), make_float2(e[nt*2]*inv, e[nt*2+1]*inv));
                if (tig == 0) {
                    float ws = sg*inv, ap = sap*inv, bd = sbd*inv, rs = srs*inv;
                    g_ws[pair] = ws; g_wap[pair] = ap; g_wbd[pair] = bd; g_wrs[pair] = rs;
                    bws += ws; bap += ap; bbd += bd; brs += rs;
                }
            }
        }
    }

    {
        int jz0 = ntiles * 256;
        if (jz0 < Ss) {
            float4 z4 = make_float4(0.f,0.f,0.f,0.f);
            float4* base = (float4*)(pi_out + (rowbase + jz0) * NV);
            int n4 = (Ss - jz0) * 16;
            for (int t = tid; t < n4; t += 256) __stcs(base + t, z4);
            for (int j = jz0 + tid; j < Ss; j += 256) {
                size_t p = rowbase + j;
                g_ws[p] = 0.f; g_wap[p] = 0.f; g_wbd[p] = 0.f; g_wrs[p] = 0.f;
            }
        }
    }

    #pragma unroll
    for (int off = 16; off; off >>= 1) {
        bws += __shfl_xor_sync(0xffffffffu, bws, off);
        bap += __shfl_xor_sync(0xffffffffu, bap, off);
        bbd += __shfl_xor_sync(0xffffffffu, bbd, off);
        brs += __shfl_xor_sync(0xffffffffu, brs, off);
    }
    if (lane == 0) {
        wred[warp][0] = bws; wred[warp][1] = bap;
        wred[warp][2] = bbd; wred[warp][3] = brs;
    }
    __syncthreads();
    if (tid < 4) {
        float s = 0.f;
        #pragma unroll
        for (int w = 0; w < 8; w++) s += wred[w][tid];
        if (tid == 0) {
            g_invden[row_g] = 1.f / (s + EPSV);
        } else {
            float d1 = s + EPSV, S2 = s / d1;
            g_invden[tid*BS + row_g] = 1.f / (d1 * (S2 + EPSV));
        }
    }
}

// ---------------- layernorm ----------------
__global__ void ln_kernel(const float* __restrict__ bo, const float* __restrict__ gamma,
                          const float* __restrict__ beta, float* __restrict__ out)
{
    int row = blockIdx.x, tid = threadIdx.x;
    const float* r = g_res + (size_t)row * Dd;
    float v[3];
    float s = 0.f;
    #pragma unroll
    for (int q = 0; q < 3; q++) { int c = tid + q*256; v[q] = r[c] + bo[c]; s += v[q]; }
    __shared__ float red[256];
    __shared__ float mu_s, inv_s;
    red[tid] = s; __syncthreads();
    for (int off = 128; off; off >>= 1) {
        if (tid < off) red[tid] += red[tid + off];
        __syncthreads();
    }
    if (tid == 0) mu_s = red[0] * (1.f / Dd);
    __syncthreads();
    float mu = mu_s;
    float s2 = 0.f;
    #pragma unroll
    for (int q = 0; q < 3; q++) { float d = v[q] - mu; s2 += d*d; }
    __syncthreads();
    red[tid] = s2; __syncthreads();
    for (int off = 128; off; off >>= 1) {
        if (tid < off) red[tid] += red[tid + off];
        __syncthreads();
    }
    if (tid == 0) inv_s = rsqrtf(red[0] * (1.f / Dd) + LNEPS);
    __syncthreads();
    float inv = inv_s;
    #pragma unroll
    for (int q = 0; q < 3; q++) {
        int c = tid + q*256;
        out[(size_t)row*Dd + c] = (v[q] - mu) * inv * gamma[c] + beta[c];
    }
}

// ---------------- launch ----------------
extern "C" void kernel_launch(void* const* d_in, const int* in_sizes, int n_in,
                              void* d_out, int out_size)
{
    const float* x      = (const float*)d_in[0];
    const float* Wq     = (const float*)d_in[2];
    const float* Wk     = (const float*)d_in[3];
    const float* vemb   = (const float*)d_in[4];
    const float* vgates = (const float*)d_in[5];
    const float* Wv     = (const float*)d_in[6];
    const float* Wspec  = (const float*)d_in[7];
    const float* Wa     = (const float*)d_in[8];
    const float* Wb     = (const float*)d_in[9];
    const float* Wr     = (const float*)d_in[10];
    const float* Wo     = (const float*)d_in[11];
    const float* bo     = (const float*)d_in[12];
    const float* gamma  = (const float*)d_in[13];
    const float* beta   = (const float*)d_in[14];
    const float* adj    = (const float*)d_in[15];
    const float* spec   = (const float*)d_in[16];

    float* out    = (float*)d_out;
    float* pi_out = out + NORMED_ELEMS;

    float *pQK, *pV, *pABR, *pComb, *pRes;
    cudaGetSymbolAddress((void**)&pQK,   g_QK);
    cudaGetSymbolAddress((void**)&pV,    g_V);
    cudaGetSymbolAddress((void**)&pABR,  g_ABR);
    cudaGetSymbolAddress((void**)&pComb, g_comb);
    cudaGetSymbolAddress((void**)&pRes,  g_res);

    const int COMBINE_SMEM = 2*2*32*72*4 * 2;          // 73728
    const int GEMM_SMEM    = (2*32*136 + 2*32*72) * 4; // 53248
    const int ATTN_SMEM    = (2*256*36 + 32*72) * 4;   // 82944
    static int smem_set = 0;
    if (!smem_set) {
        cudaFuncSetAttribute(combine_tc3, cudaFuncAttributeMaxDynamicSharedMemorySize, COMBINE_SMEM);
        cudaFuncSetAttribute(gemm_fused,  cudaFuncAttributeMaxDynamicSharedMemorySize, GEMM_SMEM);
        cudaFuncSetAttribute(gemm_tc,     cudaFuncAttributeMaxDynamicSharedMemorySize, GEMM_SMEM);
        cudaFuncSetAttribute(attn_row,    cudaFuncAttributeMaxDynamicSharedMemorySize, ATTN_SMEM);
        smem_set = 1;
    }

    dim3 thr(256);
    setup_kernel<<<65, thr>>>(vemb, spec, Wspec, adj, vgates);
    gemm_fused<<<dim3(25, 16), thr, GEMM_SMEM>>>(x, Wq, Wk, Wv, Wa, Wb, Wr, pQK, pV, pABR);

    attn_row<<<dim3(Ss, Bb), thr, ATTN_SMEM>>>(pi_out);
    combine_tc3<<<dim3(4, 16, 6), thr, COMBINE_SMEM>>>();

    gemm_tc<<<dim3(12, 16), thr, GEMM_SMEM>>>(pComb, Wo, pRes, Dd);
    ln_kernel<<<BS, 256>>>(bo, gamma, beta, out);
}

// round 11
// speedup vs baseline: 4.4424x; 1.0002x over previous
#include <cuda_runtime.h>

#define Bb 2
#define Ss 1024
#define Dd 768
#define DV 32
#define NV 64
#define D3 256
#define BS (Bb*Ss)
#define Kd 768
#define EPSV 1e-8f
#define LNEPS 1e-5f
#define NORMED_ELEMS ((size_t)Bb*Ss*Dd)

// ---------------- scratch ----------------
__device__ float g_QK[BS*64];
__device__ float g_V[BS*Dd];
__device__ float g_ABR[BS*Dd];
__device__ float g_emb2[NV*DV];
__device__ float g_gm[NV];
__device__ float g_ws [(size_t)BS*Ss];
__device__ float g_wap[(size_t)BS*Ss];
__device__ float g_wbd[(size_t)BS*Ss];
__device__ float g_wrs[(size_t)BS*Ss];
__device__ float g_invden[4*BS];
__device__ float g_comb[BS*Dd];
__device__ float g_res[BS*Dd];

// ---------------- helpers ----------------
__device__ __forceinline__ float f2tf32(float f) {
    unsigned r;
    asm("cvt.rna.tf32.f32 %0, %1;" : "=r"(r) : "f"(f));
    return __uint_as_float(r);
}
__device__ __forceinline__ void mma_tf32(float* c, const unsigned* a, const unsigned* b) {
    asm volatile("mma.sync.aligned.m16n8k8.row.col.f32.tf32.tf32.f32 "
                 "{%0,%1,%2,%3}, {%4,%5,%6,%7}, {%8,%9}, {%0,%1,%2,%3};"
                 : "+f"(c[0]), "+f"(c[1]), "+f"(c[2]), "+f"(c[3])
                 : "r"(a[0]), "r"(a[1]), "r"(a[2]), "r"(a[3]), "r"(b[0]), "r"(b[1]));
}
__device__ __forceinline__ unsigned smem_u32(const void* p) {
    return (unsigned)__cvta_generic_to_shared(p);
}
#define CP_ASYNC16(dst, src) \
    asm volatile("cp.async.ca.shared.global [%0], [%1], 16;" :: "r"(dst), "l"(src))
#define CP_COMMIT() asm volatile("cp.async.commit_group;" ::: "memory")
#define CP_WAIT0()  asm volatile("cp.async.wait_group 0;" ::: "memory")

// ======== fused projection GEMM (BK=32, double-buffered, n-offset selectable) ========
__global__ __launch_bounds__(256)
void gemm_fused(const float* __restrict__ X,
                const float* __restrict__ Wq, const float* __restrict__ Wk,
                const float* __restrict__ Wv, const float* __restrict__ Wa,
                const float* __restrict__ Wb, const float* __restrict__ Wr,
                float* __restrict__ Cqk, float* __restrict__ Cv, float* __restrict__ Cabr,
                int n_off)
{
    extern __shared__ float sm[];
    float (*As)[32][136] = (float (*)[32][136])sm;
    float (*Bs)[32][72]  = (float (*)[32][72])(sm + 2*32*136);

    int tid = threadIdx.x;
    int lane = tid & 31, warp = tid >> 5;
    int wm = warp & 3, wn = warp >> 2;
    int gid = lane >> 2, tig = lane & 3;
    int m0 = blockIdx.y * 128, n0 = (blockIdx.x + n_off) * 64;

    float c[2][4][4];
    #pragma unroll
    for (int mt = 0; mt < 2; mt++)
        #pragma unroll
        for (int nt = 0; nt < 4; nt++)
            #pragma unroll
            for (int e = 0; e < 4; e++) c[mt][nt][e] = 0.f;

    int ra = tid >> 2;
    int ka = (tid & 3) * 4;
    int sw = 8 * (tid & 3);
    const float* xp0 = X + (size_t)(m0 + ra) * Kd + ka;
    const float* xp1 = X + (size_t)(m0 + ra + 64) * Kd + ka;
    int rW = n0 + ra;
    const float* wp;
    if      (rW <   32) wp = Wq + (size_t)rW * Kd;
    else if (rW <   64) wp = Wk + (size_t)(rW -   32) * Kd;
    else if (rW <  832) wp = Wv + (size_t)(rW -   64) * Kd;
    else if (rW < 1088) wp = Wa + (size_t)(rW -  832) * Kd;
    else if (rW < 1344) wp = Wb + (size_t)(rW - 1088) * Kd;
    else                wp = Wr + (size_t)(rW - 1344) * Kd;
    wp += ka;

    int ca = ra ^ sw, ca1 = (ra + 64) ^ sw;

    {
        float4 a00 = *(const float4*)(xp0);
        float4 a01 = *(const float4*)(xp0 + 16);
        float4 a10 = *(const float4*)(xp1);
        float4 a11 = *(const float4*)(xp1 + 16);
        float4 b0  = *(const float4*)(wp);
        float4 b1  = *(const float4*)(wp + 16);
        As[0][ka+0][ca]  = f2tf32(a00.x); As[0][ka+1][ca]  = f2tf32(a00.y);
        As[0][ka+2][ca]  = f2tf32(a00.z); As[0][ka+3][ca]  = f2tf32(a00.w);
        As[0][ka+16][ca] = f2tf32(a01.x); As[0][ka+17][ca] = f2tf32(a01.y);
        As[0][ka+18][ca] = f2tf32(a01.z); As[0][ka+19][ca] = f2tf32(a01.w);
        As[0][ka+0][ca1]  = f2tf32(a10.x); As[0][ka+1][ca1]  = f2tf32(a10.y);
        As[0][ka+2][ca1]  = f2tf32(a10.z); As[0][ka+3][ca1]  = f2tf32(a10.w);
        As[0][ka+16][ca1] = f2tf32(a11.x); As[0][ka+17][ca1] = f2tf32(a11.y);
        As[0][ka+18][ca1] = f2tf32(a11.z); As[0][ka+19][ca1] = f2tf32(a11.w);
        Bs[0][ka+0][ca]  = f2tf32(b0.x); Bs[0][ka+1][ca]  = f2tf32(b0.y);
        Bs[0][ka+2][ca]  = f2tf32(b0.z); Bs[0][ka+3][ca]  = f2tf32(b0.w);
        Bs[0][ka+16][ca] = f2tf32(b1.x); Bs[0][ka+17][ca] = f2tf32(b1.y);
        Bs[0][ka+18][ca] = f2tf32(b1.z); Bs[0][ka+19][ca] = f2tf32(b1.w);
    }
    __syncthreads();

    const int NIT = Kd / 32;
    for (int it = 0; it < NIT; it++) {
        int cur = it & 1;
        float4 a00, a01, a10, a11, b0, b1;
        if (it + 1 < NIT) {
            int k0 = (it + 1) * 32;
            a00 = *(const float4*)(xp0 + k0);
            a01 = *(const float4*)(xp0 + k0 + 16);
            a10 = *(const float4*)(xp1 + k0);
            a11 = *(const float4*)(xp1 + k0 + 16);
            b0  = *(const float4*)(wp  + k0);
            b1  = *(const float4*)(wp  + k0 + 16);
        }
        #pragma unroll
        for (int ks = 0; ks < 32; ks += 8) {
            int swl = 8 * ((ks >> 2) & 3);
            int swh = 8 * (((ks + 4) >> 2) & 3);
            int klo = ks + tig, khi = ks + tig + 4;
            unsigned a[2][4], b[4][2];
            #pragma unroll
            for (int mt = 0; mt < 2; mt++) {
                int mr = wm*32 + mt*16 + gid;
                a[mt][0] = __float_as_uint(As[cur][klo][ mr      ^ swl]);
                a[mt][1] = __float_as_uint(As[cur][klo][(mr + 8) ^ swl]);
                a[mt][2] = __float_as_uint(As[cur][khi][ mr      ^ swh]);
                a[mt][3] = __float_as_uint(As[cur][khi][(mr + 8) ^ swh]);
            }
            #pragma unroll
            for (int nt = 0; nt < 4; nt++) {
                int nc = wn*32 + nt*8 + gid;
                b[nt][0] = __float_as_uint(Bs[cur][klo][nc ^ swl]);
                b[nt][1] = __float_as_uint(Bs[cur][khi][nc ^ swh]);
            }
            #pragma unroll
            for (int mt = 0; mt < 2; mt++)
                #pragma unroll
                for (int nt = 0; nt < 4; nt++)
                    mma_tf32(c[mt][nt], a[mt], b[nt]);
        }
        if (it + 1 < NIT) {
            int nx = cur ^ 1;
            As[nx][ka+0][ca]  = f2tf32(a00.x); As[nx][ka+1][ca]  = f2tf32(a00.y);
            As[nx][ka+2][ca]  = f2tf32(a00.z); As[nx][ka+3][ca]  = f2tf32(a00.w);
            As[nx][ka+16][ca] = f2tf32(a01.x); As[nx][ka+17][ca] = f2tf32(a01.y);
            As[nx][ka+18][ca] = f2tf32(a01.z); As[nx][ka+19][ca] = f2tf32(a01.w);
            As[nx][ka+0][ca1]  = f2tf32(a10.x); As[nx][ka+1][ca1]  = f2tf32(a10.y);
            As[nx][ka+2][ca1]  = f2tf32(a10.z); As[nx][ka+3][ca1]  = f2tf32(a10.w);
            As[nx][ka+16][ca1] = f2tf32(a11.x); As[nx][ka+17][ca1] = f2tf32(a11.y);
            As[nx][ka+18][ca1] = f2tf32(a11.z); As[nx][ka+19][ca1] = f2tf32(a11.w);
            Bs[nx][ka+0][ca]  = f2tf32(b0.x); Bs[nx][ka+1][ca]  = f2tf32(b0.y);
            Bs[nx][ka+2][ca]  = f2tf32(b0.z); Bs[nx][ka+3][ca]  = f2tf32(b0.w);
            Bs[nx][ka+16][ca] = f2tf32(b1.x); Bs[nx][ka+17][ca] = f2tf32(b1.y);
            Bs[nx][ka+18][ca] = f2tf32(b1.z); Bs[nx][ka+19][ca] = f2tf32(b1.w);
        }
        __syncthreads();
    }

    float* Cd; int strideN, cbase;
    if (n0 == 0)       { Cd = Cqk;  strideN = 64;  cbase = 0; }
    else if (n0 < 832) { Cd = Cv;   strideN = Dd;  cbase = n0 - 64; }
    else               { Cd = Cabr; strideN = Dd;  cbase = n0 - 832; }

    #pragma unroll
    for (int mt = 0; mt < 2; mt++) {
        int r0 = m0 + wm*32 + mt*16 + gid;
        #pragma unroll
        for (int nt = 0; nt < 4; nt++) {
            int cc = cbase + wn*32 + nt*8 + tig*2;
            *(float2*)(Cd + (size_t)r0 * strideN + cc)     = make_float2(c[mt][nt][0], c[mt][nt][1]);
            *(float2*)(Cd + (size_t)(r0+8) * strideN + cc) = make_float2(c[mt][nt][2], c[mt][nt][3]);
        }
    }
}

// ======== generic GEMM (BK=32, used for Wo) ========
__global__ __launch_bounds__(256)
void gemm_tc(const float* __restrict__ X, const float* __restrict__ W0,
             float* __restrict__ C, int N)
{
    extern __shared__ float sm[];
    float (*As)[32][136] = (float (*)[32][136])sm;
    float (*Bs)[32][72]  = (float (*)[32][72])(sm + 2*32*136);

    int tid = threadIdx.x;
    int lane = tid & 31, warp = tid >> 5;
    int wm = warp & 3, wn = warp >> 2;
    int gid = lane >> 2, tig = lane & 3;
    int m0 = blockIdx.y * 128, n0 = blockIdx.x * 64;

    float c[2][4][4];
    #pragma unroll
    for (int mt = 0; mt < 2; mt++)
        #pragma unroll
        for (int nt = 0; nt < 4; nt++)
            #pragma unroll
            for (int e = 0; e < 4; e++) c[mt][nt][e] = 0.f;

    int ra = tid >> 2;
    int ka = (tid & 3) * 4;
    int sw = 8 * (tid & 3);
    const float* xp0 = X + (size_t)(m0 + ra) * Kd + ka;
    const float* xp1 = X + (size_t)(m0 + ra + 64) * Kd + ka;
    const float* wp  = W0 + (size_t)(n0 + ra) * Kd + ka;
    int ca = ra ^ sw, ca1 = (ra + 64) ^ sw;

    {
        float4 a00 = *(const float4*)(xp0);
        float4 a01 = *(const float4*)(xp0 + 16);
        float4 a10 = *(const float4*)(xp1);
        float4 a11 = *(const float4*)(xp1 + 16);
        float4 b0  = *(const float4*)(wp);
        float4 b1  = *(const float4*)(wp + 16);
        As[0][ka+0][ca]  = f2tf32(a00.x); As[0][ka+1][ca]  = f2tf32(a00.y);
        As[0][ka+2][ca]  = f2tf32(a00.z); As[0][ka+3][ca]  = f2tf32(a00.w);
        As[0][ka+16][ca] = f2tf32(a01.x); As[0][ka+17][ca] = f2tf32(a01.y);
        As[0][ka+18][ca] = f2tf32(a01.z); As[0][ka+19][ca] = f2tf32(a01.w);
        As[0][ka+0][ca1]  = f2tf32(a10.x); As[0][ka+1][ca1]  = f2tf32(a10.y);
        As[0][ka+2][ca1]  = f2tf32(a10.z); As[0][ka+3][ca1]  = f2tf32(a10.w);
        As[0][ka+16][ca1] = f2tf32(a11.x); As[0][ka+17][ca1] = f2tf32(a11.y);
        As[0][ka+18][ca1] = f2tf32(a11.z); As[0][ka+19][ca1] = f2tf32(a11.w);
        Bs[0][ka+0][ca]  = f2tf32(b0.x); Bs[0][ka+1][ca]  = f2tf32(b0.y);
        Bs[0][ka+2][ca]  = f2tf32(b0.z); Bs[0][ka+3][ca]  = f2tf32(b0.w);
        Bs[0][ka+16][ca] = f2tf32(b1.x); Bs[0][ka+17][ca] = f2tf32(b1.y);
        Bs[0][ka+18][ca] = f2tf32(b1.z); Bs[0][ka+19][ca] = f2tf32(b1.w);
    }
    __syncthreads();

    const int NIT = Kd / 32;
    for (int it = 0; it < NIT; it++) {
        int cur = it & 1;
        float4 a00, a01, a10, a11, b0, b1;
        if (it + 1 < NIT) {
            int k0 = (it + 1) * 32;
            a00 = *(const float4*)(xp0 + k0);
            a01 = *(const float4*)(xp0 + k0 + 16);
            a10 = *(const float4*)(xp1 + k0);
            a11 = *(const float4*)(xp1 + k0 + 16);
            b0  = *(const float4*)(wp  + k0);
            b1  = *(const float4*)(wp  + k0 + 16);
        }
        #pragma unroll
        for (int ks = 0; ks < 32; ks += 8) {
            int swl = 8 * ((ks >> 2) & 3);
            int swh = 8 * (((ks + 4) >> 2) & 3);
            int klo = ks + tig, khi = ks + tig + 4;
            unsigned a[2][4], b[4][2];
            #pragma unroll
            for (int mt = 0; mt < 2; mt++) {
                int mr = wm*32 + mt*16 + gid;
                a[mt][0] = __float_as_uint(As[cur][klo][ mr      ^ swl]);
                a[mt][1] = __float_as_uint(As[cur][klo][(mr + 8) ^ swl]);
                a[mt][2] = __float_as_uint(As[cur][khi][ mr      ^ swh]);
                a[mt][3] = __float_as_uint(As[cur][khi][(mr + 8) ^ swh]);
            }
            #pragma unroll
            for (int nt = 0; nt < 4; nt++) {
                int nc = wn*32 + nt*8 + gid;
                b[nt][0] = __float_as_uint(Bs[cur][klo][nc ^ swl]);
                b[nt][1] = __float_as_uint(Bs[cur][khi][nc ^ swh]);
            }
            #pragma unroll
            for (int mt = 0; mt < 2; mt++)
                #pragma unroll
                for (int nt = 0; nt < 4; nt++)
                    mma_tf32(c[mt][nt], a[mt], b[nt]);
        }
        if (it + 1 < NIT) {
            int nx = cur ^ 1;
            As[nx][ka+0][ca]  = f2tf32(a00.x); As[nx][ka+1][ca]  = f2tf32(a00.y);
            As[nx][ka+2][ca]  = f2tf32(a00.z); As[nx][ka+3][ca]  = f2tf32(a00.w);
            As[nx][ka+16][ca] = f2tf32(a01.x); As[nx][ka+17][ca] = f2tf32(a01.y);
            As[nx][ka+18][ca] = f2tf32(a01.z); As[nx][ka+19][ca] = f2tf32(a01.w);
            As[nx][ka+0][ca1]  = f2tf32(a10.x); As[nx][ka+1][ca1]  = f2tf32(a10.y);
            As[nx][ka+2][ca1]  = f2tf32(a10.z); As[nx][ka+3][ca1]  = f2tf32(a10.w);
            As[nx][ka+16][ca1] = f2tf32(a11.x); As[nx][ka+17][ca1] = f2tf32(a11.y);
            As[nx][ka+18][ca1] = f2tf32(a11.z); As[nx][ka+19][ca1] = f2tf32(a11.w);
            Bs[nx][ka+0][ca]  = f2tf32(b0.x); Bs[nx][ka+1][ca]  = f2tf32(b0.y);
            Bs[nx][ka+2][ca]  = f2tf32(b0.z); Bs[nx][ka+3][ca]  = f2tf32(b0.w);
            Bs[nx][ka+16][ca] = f2tf32(b1.x); Bs[nx][ka+17][ca] = f2tf32(b1.y);
            Bs[nx][ka+18][ca] = f2tf32(b1.z); Bs[nx][ka+19][ca] = f2tf32(b1.w);
        }
        __syncthreads();
    }
    #pragma unroll
    for (int mt = 0; mt < 2; mt++) {
        int r0 = m0 + wm*32 + mt*16 + gid;
        #pragma unroll
        for (int nt = 0; nt < 4; nt++) {
            int cc = n0 + wn*32 + nt*8 + tig*2;
            *(float2*)(C + (size_t)r0 * N + cc)     = make_float2(c[mt][nt][0], c[mt][nt][1]);
            *(float2*)(C + (size_t)(r0+8) * N + cc) = make_float2(c[mt][nt][2], c[mt][nt][3]);
        }
    }
}

// ======== combine v3 (unchanged) ========
__global__ __launch_bounds__(256)
void combine_tc3()
{
    extern __shared__ float dynsm[];
    float (*As)[2][32][72] = (float (*)[2][32][72])dynsm;
    float (*Bs)[2][32][72] = (float (*)[2][32][72])(dynsm + 2*2*32*72);

    int bz = blockIdx.z;
    int b = bz / 3, t = bz % 3;
    const float* Wt = (t == 0) ? g_wap : (t == 1) ? g_wbd : g_wrs;
    int m0 = (int)(gridDim.y - 1 - blockIdx.y) * 64;
    int n0 = blockIdx.x * 64;
    int colbase = t * D3 + n0;

    int tid = threadIdx.x;
    int lane = tid & 31, warp = tid >> 5;
    int wm = warp & 3, wn = warp >> 2;
    int gid = lane >> 2, tig = lane & 3;

    float c[2][4][4];
    #pragma unroll
    for (int p = 0; p < 2; p++)
        #pragma unroll
        for (int nt = 0; nt < 4; nt++)
            #pragma unroll
            for (int e = 0; e < 4; e++) c[p][nt][e] = 0.f;

    int ra = tid >> 2;
    int ka = (tid & 3) * 4;
    int cA = ra ^ (8 * (tid & 3));
    int kb = tid >> 4;
    int nb = (tid & 15) * 4;
    int swb = 8 * ((kb >> 2) & 3);
    int nbs = nb ^ swb;

    const float* aws = g_ws + (size_t)(b*Ss + m0 + ra) * Ss + ka;
    const float* awt = Wt   + (size_t)(b*Ss + m0 + ra) * Ss + ka;
    const float* bpv = g_V   + (size_t)(b*Ss + kb) * Dd + colbase + nb;
    const float* bpt = g_ABR + (size_t)(b*Ss + kb) * Dd + colbase + nb;

    const int NIT = m0/32 + 2;

    {
        float4 a00 = *(const float4*)(aws);
        float4 a01 = *(const float4*)(aws + 16);
        float4 a10 = *(const float4*)(awt);
        float4 a11 = *(const float4*)(awt + 16);
        float4 b00 = *(const float4*)(bpv);
        float4 b01 = *(const float4*)(bpv + (size_t)16 * Dd);
        float4 b10 = *(const float4*)(bpt);
        float4 b11 = *(const float4*)(bpt + (size_t)16 * Dd);
        As[0][0][ka+0][cA] = f2tf32(a00.x); As[0][0][ka+1][cA] = f2tf32(a00.y);
        As[0][0][ka+2][cA] = f2tf32(a00.z); As[0][0][ka+3][cA] = f2tf32(a00.w);
        As[0][0][ka+16][cA] = f2tf32(a01.x); As[0][0][ka+17][cA] = f2tf32(a01.y);
        As[0][0][ka+18][cA] = f2tf32(a01.z); As[0][0][ka+19][cA] = f2tf32(a01.w);
        As[0][1][ka+0][cA] = f2tf32(a10.x); As[0][1][ka+1][cA] = f2tf32(a10.y);
        As[0][1][ka+2][cA] = f2tf32(a10.z); As[0][1][ka+3][cA] = f2tf32(a10.w);
        As[0][1][ka+16][cA] = f2tf32(a11.x); As[0][1][ka+17][cA] = f2tf32(a11.y);
        As[0][1][ka+18][cA] = f2tf32(a11.z); As[0][1][ka+19][cA] = f2tf32(a11.w);
        *(float4*)&Bs[0][0][kb   ][nbs] = make_float4(f2tf32(b00.x), f2tf32(b00.y), f2tf32(b00.z), f2tf32(b00.w));
        *(float4*)&Bs[0][0][kb+16][nbs] = make_float4(f2tf32(b01.x), f2tf32(b01.y), f2tf32(b01.z), f2tf32(b01.w));
        *(float4*)&Bs[0][1][kb   ][nbs] = make_float4(f2tf32(b10.x), f2tf32(b10.y), f2tf32(b10.z), f2tf32(b10.w));
        *(float4*)&Bs[0][1][kb+16][nbs] = make_float4(f2tf32(b11.x), f2tf32(b11.y), f2tf32(b11.z), f2tf32(b11.w));
    }
    __syncthreads();

    for (int it = 0; it < NIT; it++) {
        int cur = it & 1;
        float4 a00, a01, a10, a11, b00, b01, b10, b11;
        if (it + 1 < NIT) {
            int k0 = (it + 1) * 32;
            a00 = *(const float4*)(aws + k0);
            a01 = *(const float4*)(aws + k0 + 16);
            a10 = *(const float4*)(awt + k0);
            a11 = *(const float4*)(awt + k0 + 16);
            b00 = *(const float4*)(bpv + (size_t)k0 * Dd);
            b01 = *(const float4*)(bpv + (size_t)(k0+16) * Dd);
            b10 = *(const float4*)(bpt + (size_t)k0 * Dd);
            b11 = *(const float4*)(bpt + (size_t)(k0+16) * Dd);
        }
        #pragma unroll
        for (int ks = 0; ks < 32; ks += 8) {
            int swl = 8 * ((ks >> 2) & 3);
            int swh = 8 * (((ks + 4) >> 2) & 3);
            int klo = ks + tig, khi = ks + tig + 4;
            int mr = wm*16 + gid;
            #pragma unroll
            for (int p = 0; p < 2; p++) {
                unsigned a[4], bfr[4][2];
                a[0] = __float_as_uint(As[cur][p][klo][ mr      ^ swl]);
                a[1] = __float_as_uint(As[cur][p][klo][(mr + 8) ^ swl]);
                a[2] = __float_as_uint(As[cur][p][khi][ mr      ^ swh]);
                a[3] = __float_as_uint(As[cur][p][khi][(mr + 8) ^ swh]);
                #pragma unroll
                for (int nt = 0; nt < 4; nt++) {
                    int nc = wn*32 + nt*8 + gid;
                    bfr[nt][0] = __float_as_uint(Bs[cur][p][klo][nc ^ swl]);
                    bfr[nt][1] = __float_as_uint(Bs[cur][p][khi][nc ^ swh]);
                }
                #pragma unroll
                for (int nt = 0; nt < 4; nt++)
                    mma_tf32(c[p][nt], a, bfr[nt]);
            }
        }
        if (it + 1 < NIT) {
            int nx = cur ^ 1;
            As[nx][0][ka+0][cA] = f2tf32(a00.x); As[nx][0][ka+1][cA] = f2tf32(a00.y);
            As[nx][0][ka+2][cA] = f2tf32(a00.z); As[nx][0][ka+3][cA] = f2tf32(a00.w);
            As[nx][0][ka+16][cA] = f2tf32(a01.x); As[nx][0][ka+17][cA] = f2tf32(a01.y);
            As[nx][0][ka+18][cA] = f2tf32(a01.z); As[nx][0][ka+19][cA] = f2tf32(a01.w);
            As[nx][1][ka+0][cA] = f2tf32(a10.x); As[nx][1][ka+1][cA] = f2tf32(a10.y);
            As[nx][1][ka+2][cA] = f2tf32(a10.z); As[nx][1][ka+3][cA] = f2tf32(a10.w);
            As[nx][1][ka+16][cA] = f2tf32(a11.x); As[nx][1][ka+17][cA] = f2tf32(a11.y);
            As[nx][1][ka+18][cA] = f2tf32(a11.z); As[nx][1][ka+19][cA] = f2tf32(a11.w);
            *(float4*)&Bs[nx][0][kb   ][nbs] = make_float4(f2tf32(b00.x), f2tf32(b00.y), f2tf32(b00.z), f2tf32(b00.w));
            *(float4*)&Bs[nx][0][kb+16][nbs] = make_float4(f2tf32(b01.x), f2tf32(b01.y), f2tf32(b01.z), f2tf32(b01.w));
            *(float4*)&Bs[nx][1][kb   ][nbs] = make_float4(f2tf32(b10.x), f2tf32(b10.y), f2tf32(b10.z), f2tf32(b10.w));
            *(float4*)&Bs[nx][1][kb+16][nbs] = make_float4(f2tf32(b11.x), f2tf32(b11.y), f2tf32(b11.z), f2tf32(b11.w));
        }
        __syncthreads();
    }

    int r0 = m0 + wm*16 + gid;
    float is0 = g_invden[b*Ss + r0],     it0 = g_invden[(t+1)*BS + b*Ss + r0];
    float is1 = g_invden[b*Ss + r0 + 8], it1 = g_invden[(t+1)*BS + b*Ss + r0 + 8];
    int rg = b*Ss + r0;
    #pragma unroll
    for (int nt = 0; nt < 4; nt++) {
        int cc = colbase + wn*32 + nt*8 + tig*2;
        *(float2*)(g_comb + (size_t)rg * Dd + cc) =
            make_float2(is0*c[0][nt][0] + it0*c[1][nt][0],
                        is0*c[0][nt][1] + it0*c[1][nt][1]);
        *(float2*)(g_comb + (size_t)(rg+8) * Dd + cc) =
            make_float2(is1*c[0][nt][2] + it1*c[1][nt][2],
                        is1*c[0][nt][3] + it1*c[1][nt][3]);
    }
}

// ---------------- merged setup ----------------
__global__ __launch_bounds__(256)
void setup_kernel(const float* __restrict__ vemb, const float* __restrict__ spec,
                  const float* __restrict__ Wspec, const float* __restrict__ adj,
                  const float* __restrict__ vg)
{
    int tid = threadIdx.x;
    if (blockIdx.x == 0) {
        __shared__ float eb[NV*DV];
        __shared__ float adj_s[NV*NV];
        for (int t = tid; t < NV*DV; t += 256) {
            int u = t / DV, d = t % DV;
            float s = vemb[t];
            #pragma unroll
            for (int h = 0; h < 6; h++) s += 0.1f * spec[u*6+h] * Wspec[d*6+h];
            eb[t] = s;
        }
        for (int t = tid; t < NV*NV; t += 256) adj_s[t] = adj[t];
        __syncthreads();
        for (int t = tid; t < NV*DV; t += 256) {
            int v = t / DV, d = t % DV;
            float s = eb[t];
            #pragma unroll 8
            for (int u = 0; u < NV; u++) s += 0.1f * adj_s[u*NV + v] * eb[u*DV + d];
            g_emb2[t] = s;
        }
    } else {
        int v = blockIdx.x - 1;
        float s = 0.f;
        for (int c = tid; c < Dd; c += 256) {
            float x = vg[(size_t)v*Dd + c];
            s += 1.f / (1.f + __expf(-x));
        }
        __shared__ float red[256];
        red[tid] = s; __syncthreads();
        for (int off = 128; off; off >>= 1) {
            if (tid < off) red[tid] += red[tid + off];
            __syncthreads();
        }
        if (tid == 0) g_gm[v] = red[0] * (1.f / Dd);
    }
}

// ---------------- row-persistent attention (cp.async pipeline, exp2) ----------------
__global__ __launch_bounds__(256)
void attn_row(float* __restrict__ pi_out)
{
    extern __shared__ float sm[];
    float (*Ks)[256][36] = (float (*)[256][36])sm;
    float* Fs = sm + 2*256*36;

    int i = Ss - 1 - (int)blockIdx.x;
    int b = blockIdx.y;
    int row_g = b*Ss + i;
    size_t rowbase = (size_t)row_g * Ss;
    int tid = threadIdx.x;
    int warp = tid >> 5, lane = tid & 31;
    int gid = lane >> 2, tig = lane & 3;

    __shared__ float q_s[DV];
    __shared__ float gm_s[NV];
    __shared__ float wred[8][4];

    if (tid < DV) q_s[tid] = g_QK[(size_t)row_g*64 + tid];
    if (tid >= 64 && tid < 128) gm_s[tid-64] = g_gm[tid-64];
    __syncthreads();
    // fold log2(e) into F so softmax exp becomes a bare exp2
    const float LOG2E = 1.4426950408889634f;
    for (int t = tid; t < 2048; t += 256) {
        int d = t >> 6, v = t & 63;
        Fs[d*72 + v] = f2tf32(q_s[d] * LOG2E * g_emb2[v*DV + d]);
    }

    float gmr[16];
    #pragma unroll
    for (int nt = 0; nt < 8; nt++) {
        gmr[nt*2]   = gm_s[nt*8 + tig*2];
        gmr[nt*2+1] = gm_s[nt*8 + tig*2 + 1];
    }

    float bws = 0.f, bap = 0.f, bbd = 0.f, brs = 0.f;
    int ntiles = (i >> 8) + 1;
    int kr = tid >> 3, kq = (tid & 7) * 4;

    #pragma unroll
    for (int pp = 0; pp < 8; pp++) {
        int r = kr + pp*32;
        unsigned dst = smem_u32(&Ks[0][r][kq]);
        CP_ASYNC16(dst, g_QK + (size_t)(b*Ss + r)*64 + 32 + kq);
    }
    CP_COMMIT();

    for (int jt = 0; jt < ntiles; jt++) {
        int j0 = jt * 256;
        int cur = jt & 1;
        CP_WAIT0();
        __syncthreads();

        float c[2][8][4];
        #pragma unroll
        for (int mt = 0; mt < 2; mt++)
            #pragma unroll
            for (int nt = 0; nt < 8; nt++)
                #pragma unroll
                for (int e = 0; e < 4; e++) c[mt][nt][e] = 0.f;

        #pragma unroll
        for (int ks = 0; ks < 32; ks += 8) {
            unsigned a[2][4], bf[8][2];
            #pragma unroll
            for (int mt = 0; mt < 2; mt++) {
                int mr = warp*32 + mt*16 + gid;
                a[mt][0] = __float_as_uint(f2tf32(Ks[cur][mr  ][ks+tig]));
                a[mt][1] = __float_as_uint(f2tf32(Ks[cur][mr+8][ks+tig]));
                a[mt][2] = __float_as_uint(f2tf32(Ks[cur][mr  ][ks+tig+4]));
                a[mt][3] = __float_as_uint(f2tf32(Ks[cur][mr+8][ks+tig+4]));
            }
            #pragma unroll
            for (int nt = 0; nt < 8; nt++) {
                int nc = nt*8 + gid;
                bf[nt][0] = __float_as_uint(Fs[(ks+tig  )*72 + nc]);
                bf[nt][1] = __float_as_uint(Fs[(ks+tig+4)*72 + nc]);
            }
            #pragma unroll
            for (int mt = 0; mt < 2; mt++)
                #pragma unroll
                for (int nt = 0; nt < 8; nt++)
                    mma_tf32(c[mt][nt], a[mt], bf[nt]);
        }

        if (jt + 1 < ntiles) {
            int j0n = (jt + 1) * 256;
            int nx = cur ^ 1;
            #pragma unroll
            for (int pp = 0; pp < 8; pp++) {
                int r = kr + pp*32;
                unsigned dst = smem_u32(&Ks[nx][r][kq]);
                CP_ASYNC16(dst, g_QK + (size_t)(b*Ss + j0n + r)*64 + 32 + kq);
            }
            CP_COMMIT();
        }

        #pragma unroll
        for (int mt = 0; mt < 2; mt++)
        #pragma unroll
        for (int rh = 0; rh < 2; rh++) {
            int j = j0 + warp*32 + mt*16 + rh*8 + gid;
            size_t pair = rowbase + j;
            float e[16];
            float sum = 0.f, sg = 0.f, sap = 0.f;
            #pragma unroll
            for (int q = 0; q < 16; q++) {
                float ev = exp2f(c[mt][q>>1][rh*2 + (q&1)]);
                e[q] = ev;
                sum += ev;
                sg = fmaf(ev, gmr[q], sg);
                if (q & 1) sap += ev;
            }
            float sbd = (tig & 1) ? sum : 0.f;
            float srs = (tig & 2) ? sum : 0.f;
            sum += __shfl_xor_sync(0xffffffffu, sum, 1);
            sum += __shfl_xor_sync(0xffffffffu, sum, 2);
            sg  += __shfl_xor_sync(0xffffffffu, sg , 1);
            sg  += __shfl_xor_sync(0xffffffffu, sg , 2);
            sap += __shfl_xor_sync(0xffffffffu, sap, 1);
            sap += __shfl_xor_sync(0xffffffffu, sap, 2);
            sbd += __shfl_xor_sync(0xffffffffu, sbd, 1);
            sbd += __shfl_xor_sync(0xffffffffu, sbd, 2);
            srs += __shfl_xor_sync(0xffffffffu, srs, 1);
            srs += __shfl_xor_sync(0xffffffffu, srs, 2);

            float* po = pi_out + pair*NV + tig*2;
            if (j > i) {
                float2 z = make_float2(0.f, 0.f);
                #pragma unroll
                for (int nt = 0; nt < 8; nt++) __stcs((float2*)(po + nt*8), z);
                if (tig == 0) {
                    g_ws[pair] = 0.f; g_wap[pair] = 0.f;
                    g_wbd[pair] = 0.f; g_wrs[pair] = 0.f;
                }
            } else {
                float inv = 1.f / sum;
                #pragma unroll
                for (int nt = 0; nt < 8; nt++)
                    __stcs((float2*)(po + nt*8), make_float2(e[nt*2]*inv, e[nt*2+1]*inv));
                if (tig == 0) {
                    float ws = sg*inv, ap = sap*inv, bd = sbd*inv, rs = srs*inv;
                    g_ws[pair] = ws; g_wap[pair] = ap; g_wbd[pair] = bd; g_wrs[pair] = rs;
                    bws += ws; bap += ap; bbd += bd; brs += rs;
                }
            }
        }
    }

    {
        int jz0 = ntiles * 256;
        if (jz0 < Ss) {
            float4 z4 = make_float4(0.f,0.f,0.f,0.f);
            float4* base = (float4*)(pi_out + (rowbase + jz0) * NV);
            int n4 = (Ss - jz0) * 16;
            for (int t = tid; t < n4; t += 256) __stcs(base + t, z4);
            for (int j = jz0 + tid; j < Ss; j += 256) {
                size_t p = rowbase + j;
                g_ws[p] = 0.f; g_wap[p] = 0.f; g_wbd[p] = 0.f; g_wrs[p] = 0.f;
            }
        }
    }

    #pragma unroll
    for (int off = 16; off; off >>= 1) {
        bws += __shfl_xor_sync(0xffffffffu, bws, off);
        bap += __shfl_xor_sync(0xffffffffu, bap, off);
        bbd += __shfl_xor_sync(0xffffffffu, bbd, off);
        brs += __shfl_xor_sync(0xffffffffu, brs, off);
    }
    if (lane == 0) {
        wred[warp][0] = bws; wred[warp][1] = bap;
        wred[warp][2] = bbd; wred[warp][3] = brs;
    }
    __syncthreads();
    if (tid < 4) {
        float s = 0.f;
        #pragma unroll
        for (int w = 0; w < 8; w++) s += wred[w][tid];
        if (tid == 0) {
            g_invden[row_g] = 1.f / (s + EPSV);
        } else {
            float d1 = s + EPSV, S2 = s / d1;
            g_invden[tid*BS + row_g] = 1.f / (d1 * (S2 + EPSV));
        }
    }
}

// ---------------- layernorm ----------------
__global__ void ln_kernel(const float* __restrict__ bo, const float* __restrict__ gamma,
                          const float* __restrict__ beta, float* __restrict__ out)
{
    int row = blockIdx.x, tid = threadIdx.x;
    const float* r = g_res + (size_t)row * Dd;
    float v[3];
    float s = 0.f;
    #pragma unroll
    for (int q = 0; q < 3; q++) { int c = tid + q*256; v[q] = r[c] + bo[c]; s += v[q]; }
    __shared__ float red[256];
    __shared__ float mu_s, inv_s;
    red[tid] = s; __syncthreads();
    for (int off = 128; off; off >>= 1) {
        if (tid < off) red[tid] += red[tid + off];
        __syncthreads();
    }
    if (tid == 0) mu_s = red[0] * (1.f / Dd);
    __syncthreads();
    float mu = mu_s;
    float s2 = 0.f;
    #pragma unroll
    for (int q = 0; q < 3; q++) { float d = v[q] - mu; s2 += d*d; }
    __syncthreads();
    red[tid] = s2; __syncthreads();
    for (int off = 128; off; off >>= 1) {
        if (tid < off) red[tid] += red[tid + off];
        __syncthreads();
    }
    if (tid == 0) inv_s = rsqrtf(red[0] * (1.f / Dd) + LNEPS);
    __syncthreads();
    float inv = inv_s;
    #pragma unroll
    for (int q = 0; q < 3; q++) {
        int c = tid + q*256;
        out[(size_t)row*Dd + c] = (v[q] - mu) * inv * gamma[c] + beta[c];
    }
}

// ---------------- launch ----------------
extern "C" void kernel_launch(void* const* d_in, const int* in_sizes, int n_in,
                              void* d_out, int out_size)
{
    const float* x      = (const float*)d_in[0];
    const float* Wq     = (const float*)d_in[2];
    const float* Wk     = (const float*)d_in[3];
    const float* vemb   = (const float*)d_in[4];
    const float* vgates = (const float*)d_in[5];
    const float* Wv     = (const float*)d_in[6];
    const float* Wspec  = (const float*)d_in[7];
    const float* Wa     = (const float*)d_in[8];
    const float* Wb     = (const float*)d_in[9];
    const float* Wr     = (const float*)d_in[10];
    const float* Wo     = (const float*)d_in[11];
    const float* bo     = (const float*)d_in[12];
    const float* gamma  = (const float*)d_in[13];
    const float* beta   = (const float*)d_in[14];
    const float* adj    = (const float*)d_in[15];
    const float* spec   = (const float*)d_in[16];

    float* out    = (float*)d_out;
    float* pi_out = out + NORMED_ELEMS;

    float *pQK, *pV, *pABR, *pComb, *pRes;
    cudaGetSymbolAddress((void**)&pQK,   g_QK);
    cudaGetSymbolAddress((void**)&pV,    g_V);
    cudaGetSymbolAddress((void**)&pABR,  g_ABR);
    cudaGetSymbolAddress((void**)&pComb, g_comb);
    cudaGetSymbolAddress((void**)&pRes,  g_res);

    const int COMBINE_SMEM = 2*2*32*72*4 * 2;          // 73728
    const int GEMM_SMEM    = (2*32*136 + 2*32*72) * 4; // 53248
    const int ATTN_SMEM    = (2*256*36 + 32*72) * 4;   // 82944

    static cudaStream_t s1 = nullptr;
    static cudaEvent_t ev_fork = nullptr, ev_join = nullptr;
    if (!s1) {
        cudaFuncSetAttribute(combine_tc3, cudaFuncAttributeMaxDynamicSharedMemorySize, COMBINE_SMEM);
        cudaFuncSetAttribute(gemm_fused,  cudaFuncAttributeMaxDynamicSharedMemorySize, GEMM_SMEM);
        cudaFuncSetAttribute(gemm_tc,     cudaFuncAttributeMaxDynamicSharedMemorySize, GEMM_SMEM);
        cudaFuncSetAttribute(attn_row,    cudaFuncAttributeMaxDynamicSharedMemorySize, ATTN_SMEM);
        cudaStreamCreateWithFlags(&s1, cudaStreamNonBlocking);
        cudaEventCreateWithFlags(&ev_fork, cudaEventDisableTiming);
        cudaEventCreateWithFlags(&ev_join, cudaEventDisableTiming);
    }

    dim3 thr(256);

    // fork: V/ABR projection on s1 (only needed by combine)
    cudaEventRecord(ev_fork, 0);
    cudaStreamWaitEvent(s1, ev_fork, 0);
    gemm_fused<<<dim3(24, 16), thr, GEMM_SMEM, s1>>>(x, Wq, Wk, Wv, Wa, Wb, Wr,
                                                     pQK, pV, pABR, /*n_off=*/1);
    cudaEventRecord(ev_join, s1);

    // main stream: setup + QK projection + attention
    setup_kernel<<<65, thr>>>(vemb, spec, Wspec, adj, vgates);
    gemm_fused<<<dim3(1, 16), thr, GEMM_SMEM>>>(x, Wq, Wk, Wv, Wa, Wb, Wr,
                                                pQK, pV, pABR, /*n_off=*/0);
    attn_row<<<dim3(Ss, Bb), thr, ATTN_SMEM>>>(pi_out);

    // join: combine needs V/ABR + attn outputs
    cudaStreamWaitEvent(0, ev_join, 0);
    combine_tc3<<<dim3(4, 16, 6), thr, COMBINE_SMEM>>>();

    gemm_tc<<<dim3(12, 16), thr, GEMM_SMEM>>>(pComb, Wo, pRes, Dd);
    ln_kernel<<<BS, 256>>>(bo, gamma, beta, out);
}